// round 2
// baseline (speedup 1.0000x reference)
#include <cuda_runtime.h>
#include <cuda_bf16.h>
#include <math.h>

// Problem dims (fixed by setup_inputs)
constexpr int B = 8;
constexpr int T = 128;
constexpr int E = 30522;
constexpr int H = 1000;
constexpr int S = 64;
constexpr int NZ = 10000;
constexpr int G4 = 4 * H;          // 4000
constexpr int EMB_LD = E + NZ;     // 40522
constexpr int ATTN_LD = 3 * H;     // 3000
constexpr int COMB_LD = 2 * H;     // 2000

// ---------------- scratch (static device arrays; no allocation) ----------------
__device__ float g_pre_enc[T * B * G4];   // 16.4 MB  precomputed x@Wih^T + biases
__device__ float g_enc_out[T * B * H];    // 4.1 MB   encoder hidden states [t][b][j]
__device__ float g_Mmat[H * H];           // 4 MB     M = emb_W[:, :E] @ out_W
__device__ float g_n1pre[S * B * H];      // 2 MB     noise1 @ emb_W[:, E:]^T + emb_b
__device__ float g_n2pre[S * B * T];      // 0.26 MB  noise2 @ attn_W[:, 2H:]^T + attn_b
__device__ float g_Hs[S * B * H];         // 2 MB     decoder hidden states
__device__ float g_h[B * H];
__device__ float g_c[B * H];
__device__ float g_emb[B * H];
__device__ float g_attn[B * T];
__device__ float g_applied[B * H];
__device__ float g_comb[B * H];
__device__ float g_gates[B * G4];
__device__ float g_encbias[G4];
__device__ float g_decbias[G4];
__device__ float g_v[H];                  // out_b @ emb_W[:, :E]^T  (bias for emb at s>=1)

// ---------------- big tiled fp32 GEMM: C[M,N] = A @ B (+bias[n]) ----------------
// NT when B_K_CONTIG (B stored [N,K] row-major), NN otherwise (B stored [K,N]).
// SWIZ_A remaps logical row m -> memory row (m%8)*swizT + (m/8)  (the [B,T]->[T,B] transpose).
template <bool SWIZ_A, bool B_K_CONTIG>
__global__ void gemm_big(const float* __restrict__ A, int ldA, int swizT,
                         const float* __restrict__ Bm, int ldB,
                         const float* __restrict__ bias,
                         float* __restrict__ C, int ldC,
                         int M, int N, int K) {
    constexpr int BM = 128, BN = 128, BK = 16;
    __shared__ float As[BK][BM];
    __shared__ float Bs[BK][BN];
    int tid = threadIdx.x;          // 256 threads
    int tx = tid & 15, ty = tid >> 4;
    int n0 = blockIdx.x * BN, m0 = blockIdx.y * BM;
    float acc[8][8];
#pragma unroll
    for (int i = 0; i < 8; i++)
#pragma unroll
        for (int j = 0; j < 8; j++) acc[i][j] = 0.f;

    for (int k0 = 0; k0 < K; k0 += BK) {
        // A tile
#pragma unroll
        for (int i = 0; i < 8; i++) {
            int lin = tid + i * 256;   // 0..2047
            int m = lin >> 4, k = lin & 15;
            int gm = m0 + m, gk = k0 + k;
            float v = 0.f;
            if (gm < M && gk < K) {
                int idx;
                if (SWIZ_A) idx = ((gm & 7) * swizT + (gm >> 3)) * ldA + gk;
                else        idx = gm * ldA + gk;
                v = A[idx];
            }
            As[k][m] = v;
        }
        // B tile
#pragma unroll
        for (int i = 0; i < 8; i++) {
            int lin = tid + i * 256;
            int n, k;
            if (B_K_CONTIG) { n = lin >> 4; k = lin & 15; }
            else            { k = lin >> 7; n = lin & 127; }
            int gn = n0 + n, gk = k0 + k;
            float v = 0.f;
            if (gn < N && gk < K)
                v = B_K_CONTIG ? Bm[gn * ldB + gk] : Bm[gk * ldB + gn];
            Bs[k][n] = v;
        }
        __syncthreads();
#pragma unroll
        for (int k = 0; k < BK; k++) {
            float a[8], b[8];
#pragma unroll
            for (int i = 0; i < 8; i++) a[i] = As[k][ty * 8 + i];
#pragma unroll
            for (int j = 0; j < 8; j++) b[j] = Bs[k][tx * 8 + j];
#pragma unroll
            for (int i = 0; i < 8; i++)
#pragma unroll
                for (int j = 0; j < 8; j++) acc[i][j] += a[i] * b[j];
        }
        __syncthreads();
    }
#pragma unroll
    for (int i = 0; i < 8; i++) {
        int gm = m0 + ty * 8 + i;
        if (gm >= M) continue;
#pragma unroll
        for (int j = 0; j < 8; j++) {
            int gn = n0 + tx * 8 + j;
            if (gn >= N) continue;
            float v = acc[i][j];
            if (bias) v += bias[gn];
            C[gm * ldC + gn] = v;
        }
    }
}

// ---------------- small batch-8 GEMM: C[8,N] = sum_seg A_seg[8,K]@W_seg[N,K]^T ----------------
// + optional addend[8,N], bias[N], relu. A segments are contiguous [8,K] arrays.
struct Seg {
    const float* A;
    const float* W;
    int ldW;
    int K;   // 0 => segment disabled
};

__global__ void gemm8(Seg s0, Seg s1,
                      const float* __restrict__ addend,
                      const float* __restrict__ bias,
                      float* __restrict__ C, int N, int act) {
    __shared__ float As[8][1024];
    int tid = threadIdx.x;            // 256
    int lane = tid & 31, w = tid >> 5;
    int rbase = blockIdx.x * 32 + w * 4;
    float acc[4][8];
#pragma unroll
    for (int r = 0; r < 4; r++)
#pragma unroll
        for (int b = 0; b < 8; b++) acc[r][b] = 0.f;

    for (int si = 0; si < 2; si++) {
        Seg s = si ? s1 : s0;
        if (s.K == 0) continue;   // uniform across block
        for (int kb = 0; kb < s.K; kb += 1024) {
            int kc = min(1024, s.K - kb);
            __syncthreads();
            for (int i = tid; i < 8 * kc; i += 256) {
                int b = i / kc, k = i - b * kc;
                As[b][k] = s.A[b * s.K + kb + k];
            }
            __syncthreads();
            for (int k0 = 0; k0 < kc; k0 += 32) {
                int kk = k0 + lane;
                bool kin = kk < kc;
                float a[8];
#pragma unroll
                for (int b = 0; b < 8; b++) a[b] = kin ? As[b][kk] : 0.f;
#pragma unroll
                for (int r = 0; r < 4; r++) {
                    int row = rbase + r;
                    float wv = (kin && row < N) ? s.W[row * s.ldW + kb + kk] : 0.f;
#pragma unroll
                    for (int b = 0; b < 8; b++) acc[r][b] += wv * a[b];
                }
            }
        }
    }
    // warp butterfly reduce -> full sum in all lanes
#pragma unroll
    for (int r = 0; r < 4; r++)
#pragma unroll
        for (int b = 0; b < 8; b++) {
            float v = acc[r][b];
#pragma unroll
            for (int off = 16; off; off >>= 1) v += __shfl_xor_sync(0xFFFFFFFFu, v, off);
            acc[r][b] = v;
        }
    if (lane < 8) {
        int b = lane;
#pragma unroll
        for (int r = 0; r < 4; r++) {
            int row = rbase + r;
            if (row < N) {
                float v = acc[r][b];
                if (bias) v += bias[row];
                if (addend) v += addend[b * N + row];
                if (act) v = fmaxf(v, 0.f);
                C[b * N + row] = v;
            }
        }
    }
}

// ---------------- LSTM pointwise ----------------
__global__ void lstm_point(const float* __restrict__ gates,
                           float* __restrict__ h, float* __restrict__ c,
                           float* __restrict__ hcopy) {
    int idx = blockIdx.x * blockDim.x + threadIdx.x;
    if (idx >= B * H) return;
    int b = idx / H, j = idx - b * H;
    const float* g = gates + b * G4;
    float i = 1.f / (1.f + expf(-g[j]));
    float f = 1.f / (1.f + expf(-g[H + j]));
    float gg = tanhf(g[2 * H + j]);
    float o = 1.f / (1.f + expf(-g[3 * H + j]));
    float cn = f * c[idx] + i * gg;
    c[idx] = cn;
    float hn = o * tanhf(cn);
    h[idx] = hn;
    if (hcopy) hcopy[idx] = hn;
}

// ---------------- softmax over T + attention apply ----------------
__global__ void softmax_applied(const float* __restrict__ logits,
                                const float* __restrict__ enc_out,
                                float* __restrict__ applied) {
    __shared__ float aw[T];
    __shared__ float s_inv;
    int b = blockIdx.x, tid = threadIdx.x;
    if (tid < T) aw[tid] = logits[b * T + tid];
    __syncthreads();
    if (tid == 0) {
        float m = -1e30f;
        for (int t = 0; t < T; t++) m = fmaxf(m, aw[t]);
        float s = 0.f;
        for (int t = 0; t < T; t++) { float e = expf(aw[t] - m); aw[t] = e; s += e; }
        s_inv = 1.f / s;
    }
    __syncthreads();
    float inv = s_inv;
    float acc[4] = {0.f, 0.f, 0.f, 0.f};
    for (int t = 0; t < T; t++) {
        float wgt = aw[t] * inv;
        const float* row = enc_out + t * (B * H) + b * H;
#pragma unroll
        for (int q = 0; q < 4; q++) {
            int j = tid + q * 256;
            if (j < H) acc[q] += wgt * row[j];
        }
    }
#pragma unroll
    for (int q = 0; q < 4; q++) {
        int j = tid + q * 256;
        if (j < H) applied[b * H + j] = acc[q];
    }
}

// ---------------- tiny precompute kernels ----------------
__global__ void bias_sum(const float* __restrict__ a, const float* __restrict__ b,
                         float* __restrict__ o, int n) {
    int i = blockIdx.x * blockDim.x + threadIdx.x;
    if (i < n) o[i] = a[i] + b[i];
}

// v[j] = sum_e out_b[e] * emb_W[j, e]
__global__ void calc_v(const float* __restrict__ out_b, const float* __restrict__ emb_W,
                       float* __restrict__ v) {
    int j = blockIdx.x;
    const float* row = emb_W + j * EMB_LD;
    float acc = 0.f;
    for (int e = threadIdx.x; e < E; e += 256) acc += out_b[e] * row[e];
    __shared__ float s[256];
    s[threadIdx.x] = acc;
    __syncthreads();
    for (int off = 128; off; off >>= 1) {
        if (threadIdx.x < off) s[threadIdx.x] += s[threadIdx.x + off];
        __syncthreads();
    }
    if (threadIdx.x == 0) v[j] = s[0];
}

// ---------------- host orchestration ----------------
static inline float* sym(void* p) { return (float*)p; }

extern "C" void kernel_launch(void* const* d_in, const int* in_sizes, int n_in,
                              void* d_out, int out_size) {
    const float* in_input  = (const float*)d_in[0];   // [B,T,E]
    // d_in[1] = target_size (unused, S fixed)
    const float* noise1    = (const float*)d_in[2];   // [S,B,NZ]
    const float* noise2    = (const float*)d_in[3];   // [S,B,H]
    const float* init_dec  = (const float*)d_in[4];   // [B,E]
    const float* enc_Wih   = (const float*)d_in[5];   // [4H,E]
    const float* enc_Whh   = (const float*)d_in[6];   // [4H,H]
    const float* enc_bih   = (const float*)d_in[7];
    const float* enc_bhh   = (const float*)d_in[8];
    const float* dec_Wih   = (const float*)d_in[9];   // [4H,H]
    const float* dec_Whh   = (const float*)d_in[10];  // [4H,H]
    const float* dec_bih   = (const float*)d_in[11];
    const float* dec_bhh   = (const float*)d_in[12];
    const float* emb_W     = (const float*)d_in[13];  // [H, E+NZ]
    const float* emb_b     = (const float*)d_in[14];
    const float* attn_W    = (const float*)d_in[15];  // [T, 3H]
    const float* attn_b    = (const float*)d_in[16];
    const float* comb_W    = (const float*)d_in[17];  // [H, 2H]
    const float* comb_b    = (const float*)d_in[18];
    const float* out_W     = (const float*)d_in[19];  // [E, H]
    const float* out_b     = (const float*)d_in[20];
    float* out = (float*)d_out;                       // [S,B,E]

    void *p_pre, *p_enc, *p_M, *p_n1, *p_n2, *p_Hs, *p_h, *p_c, *p_emb, *p_attn,
         *p_app, *p_comb, *p_g, *p_eb, *p_db, *p_v;
    cudaGetSymbolAddress(&p_pre, g_pre_enc);
    cudaGetSymbolAddress(&p_enc, g_enc_out);
    cudaGetSymbolAddress(&p_M, g_Mmat);
    cudaGetSymbolAddress(&p_n1, g_n1pre);
    cudaGetSymbolAddress(&p_n2, g_n2pre);
    cudaGetSymbolAddress(&p_Hs, g_Hs);
    cudaGetSymbolAddress(&p_h, g_h);
    cudaGetSymbolAddress(&p_c, g_c);
    cudaGetSymbolAddress(&p_emb, g_emb);
    cudaGetSymbolAddress(&p_attn, g_attn);
    cudaGetSymbolAddress(&p_app, g_applied);
    cudaGetSymbolAddress(&p_comb, g_comb);
    cudaGetSymbolAddress(&p_g, g_gates);
    cudaGetSymbolAddress(&p_eb, g_encbias);
    cudaGetSymbolAddress(&p_db, g_decbias);
    cudaGetSymbolAddress(&p_v, g_v);
    float *pre = sym(p_pre), *enc = sym(p_enc), *Mm = sym(p_M), *n1p = sym(p_n1),
          *n2p = sym(p_n2), *Hs = sym(p_Hs), *h = sym(p_h), *c = sym(p_c),
          *emb = sym(p_emb), *att = sym(p_attn), *app = sym(p_app),
          *comb = sym(p_comb), *gates = sym(p_g), *encb = sym(p_eb),
          *decb = sym(p_db), *v = sym(p_v);

    // init
    cudaMemsetAsync(h, 0, B * H * sizeof(float));
    cudaMemsetAsync(c, 0, B * H * sizeof(float));
    bias_sum<<<(G4 + 255) / 256, 256>>>(enc_bih, enc_bhh, encb, G4);
    bias_sum<<<(G4 + 255) / 256, 256>>>(dec_bih, dec_bhh, decb, G4);
    calc_v<<<H, 256>>>(out_b, emb_W, v);

    // ---- big batched precomputes ----
    // pre_enc[t*8+b, :] = input[b,t,:] @ enc_Wih^T + (bih+bhh)
    {
        dim3 grid((G4 + 127) / 128, (T * B + 127) / 128);
        gemm_big<true, true><<<grid, 256>>>(in_input, E, T, enc_Wih, E, encb,
                                            pre, G4, T * B, G4, E);
    }
    // Mmat = emb_W[:, :E] @ out_W   (NN)
    {
        dim3 grid((H + 127) / 128, (H + 127) / 128);
        gemm_big<false, false><<<grid, 256>>>(emb_W, EMB_LD, 0, out_W, H, nullptr,
                                              Mm, H, H, H, E);
    }
    // n1pre = noise1 @ emb_W[:, E:]^T + emb_b
    {
        dim3 grid((H + 127) / 128, (S * B + 127) / 128);
        gemm_big<false, true><<<grid, 256>>>(noise1, NZ, 0, emb_W + E, EMB_LD, emb_b,
                                             n1p, H, S * B, H, NZ);
    }
    // n2pre = noise2 @ attn_W[:, 2H:]^T + attn_b
    {
        dim3 grid((T + 127) / 128, (S * B + 127) / 128);
        gemm_big<false, true><<<grid, 256>>>(noise2, H, 0, attn_W + 2 * H, ATTN_LD, attn_b,
                                             n2p, T, S * B, T, H);
    }

    Seg none = {nullptr, nullptr, 0, 0};

    // ---- encoder recurrence ----
    for (int t = 0; t < T; t++) {
        Seg s0 = {h, enc_Whh, H, H};
        gemm8<<<(G4 + 31) / 32, 256>>>(s0, none, pre + t * B * G4, nullptr,
                                       gates, G4, 0);
        lstm_point<<<(B * H + 255) / 256, 256>>>(gates, h, c, enc + t * B * H);
    }

    // ---- decoder recurrence ----
    for (int s = 0; s < S; s++) {
        // emb
        if (s == 0) {
            Seg s0 = {init_dec, emb_W, EMB_LD, E};
            gemm8<<<(H + 31) / 32, 256>>>(s0, none, n1p, nullptr, emb, H, 0);
        } else {
            Seg s0 = {h, Mm, H, H};
            gemm8<<<(H + 31) / 32, 256>>>(s0, none, n1p + s * B * H, v, emb, H, 0);
        }
        // attention logits = emb@Wa1^T + h@Wa2^T + n2pre
        {
            Seg s0 = {emb, attn_W, ATTN_LD, H};
            Seg s1 = {h, attn_W + H, ATTN_LD, H};
            gemm8<<<(T + 31) / 32, 256>>>(s0, s1, n2p + s * B * T, nullptr, att, T, 0);
        }
        softmax_applied<<<B, 256>>>(att, enc, app);
        // combined = relu(emb@Wc1^T + applied@Wc2^T + comb_b)
        {
            Seg s0 = {emb, comb_W, COMB_LD, H};
            Seg s1 = {app, comb_W + H, COMB_LD, H};
            gemm8<<<(H + 31) / 32, 256>>>(s0, s1, nullptr, comb_b, comb, H, 1);
        }
        // gates = combined@dec_Wih^T + h@dec_Whh^T + (bih+bhh)
        {
            Seg s0 = {comb, dec_Wih, H, H};
            Seg s1 = {h, dec_Whh, H, H};
            gemm8<<<(G4 + 31) / 32, 256>>>(s0, s1, nullptr, decb, gates, G4, 0);
        }
        lstm_point<<<(B * H + 255) / 256, 256>>>(gates, h, c, Hs + s * B * H);
    }

    // ---- final output GEMM: out = Hs @ out_W^T + out_b ----
    {
        dim3 grid((E + 127) / 128, (S * B + 127) / 128);
        gemm_big<false, true><<<grid, 256>>>(Hs, H, 0, out_W, H, out_b,
                                             out, E, S * B, E, H);
    }
}

// round 3
// speedup vs baseline: 1.3122x; 1.3122x over previous
#include <cuda_runtime.h>
#include <cuda_bf16.h>
#include <math.h>

// Problem dims (fixed by setup_inputs)
constexpr int B = 8;
constexpr int T = 128;
constexpr int E = 30522;
constexpr int H = 1000;
constexpr int S = 64;
constexpr int NZ = 10000;
constexpr int G4 = 4 * H;          // 4000
constexpr int EMB_LD = E + NZ;     // 40522
constexpr int ATTN_LD = 3 * H;     // 3000
constexpr int COMB_LD = 2 * H;     // 2000

// ---------------- scratch (static device arrays; no allocation) ----------------
__device__ float g_pre_enc[T * B * G4];
__device__ float g_enc_out[T * B * H];
__device__ float g_Mmat[H * H];
__device__ float g_n1pre[S * B * H];
__device__ float g_n2pre[S * B * T];
__device__ float g_Hs[S * B * H];
__device__ float g_h[B * H];
__device__ float g_c[B * H];
__device__ float g_emb[B * H];
__device__ float g_attn[B * T];
__device__ float g_applied[B * H];
__device__ float g_comb[B * H];
__device__ float g_gates[B * G4];
__device__ float g_encbias[G4];
__device__ float g_decbias[G4];
__device__ float g_v[H];

// ---------------- tf32 helpers ----------------
__device__ __forceinline__ unsigned f2tf(float x) {
    unsigned u;
    asm("cvt.rna.tf32.f32 %0, %1;" : "=r"(u) : "f"(x));
    return u;
}

__device__ __forceinline__ void mma_tf32(float* c, const unsigned* a, const unsigned* b) {
    asm volatile(
        "mma.sync.aligned.m16n8k8.row.col.f32.tf32.tf32.f32 "
        "{%0,%1,%2,%3}, {%4,%5,%6,%7}, {%8,%9}, {%0,%1,%2,%3};"
        : "+f"(c[0]), "+f"(c[1]), "+f"(c[2]), "+f"(c[3])
        : "r"(a[0]), "r"(a[1]), "r"(a[2]), "r"(a[3]), "r"(b[0]), "r"(b[1]));
}

// ---------------- big GEMM via mma.sync tf32x2: C[M,N] = A@B (+bias[n]) ----------------
// B_K_CONTIG: B stored [N,K] row-major (NT). Else B stored [K,N] (NN).
// SWIZ_A: logical row m -> memory row (m%8)*swizT + (m/8).
template <bool SWIZ_A, bool B_K_CONTIG>
__global__ void __launch_bounds__(256, 1)
gemm_mma(const float* __restrict__ A, int ldA, int swizT,
         const float* __restrict__ Bm, int ldB,
         const float* __restrict__ bias,
         float* __restrict__ C, int ldC,
         int M, int N, int K) {
    __shared__ float As[128][20];
    __shared__ float Bs[128][20];

    const int tid = threadIdx.x;
    const int wid = tid >> 5, lane = tid & 31;
    const int g = lane >> 2, tq = lane & 3;
    const int wm = wid & 1, wn = wid >> 1;          // warp grid 2 (m) x 4 (n)
    const int m0 = blockIdx.y * 128, n0 = blockIdx.x * 128;

    float acc[4][4][4];                              // [mfrag][nfrag][4]
#pragma unroll
    for (int i = 0; i < 4; i++)
#pragma unroll
        for (int j = 0; j < 4; j++)
#pragma unroll
            for (int q = 0; q < 4; q++) acc[i][j][q] = 0.f;

    // loader mapping
    const int la_m = tid >> 1, la_k = (tid & 1) * 8;
    int lb_n, lb_k;
    if (B_K_CONTIG) { lb_n = tid >> 1; lb_k = (tid & 1) * 8; }
    else            { lb_n = tid & 127; lb_k = (tid >> 7) * 8; }

    const int gm_a = m0 + la_m;
    long a_row_off = -1;
    if (gm_a < M) {
        int mr = SWIZ_A ? ((gm_a & 7) * swizT + (gm_a >> 3)) : gm_a;
        a_row_off = (long)mr * ldA;
    }
    const int gn_b = n0 + lb_n;

    float ra[8], rb[8];

    // prologue fetch (tile k0 = 0)
#pragma unroll
    for (int i = 0; i < 8; i++) {
        int gk = la_k + i;
        ra[i] = (a_row_off >= 0 && gk < K) ? A[a_row_off + gk] : 0.f;
    }
#pragma unroll
    for (int i = 0; i < 8; i++) {
        int gk = lb_k + i;
        float v = 0.f;
        if (gn_b < N && gk < K)
            v = B_K_CONTIG ? Bm[(long)gn_b * ldB + gk] : Bm[(long)gk * ldB + gn_b];
        rb[i] = v;
    }

    for (int k0 = 0; k0 < K; k0 += 16) {
        // commit staged regs to smem
#pragma unroll
        for (int i = 0; i < 8; i++) As[la_m][la_k + i] = ra[i];
#pragma unroll
        for (int i = 0; i < 8; i++) Bs[lb_n][lb_k + i] = rb[i];
        __syncthreads();

        // prefetch next tile into regs (in flight during compute)
        if (k0 + 16 < K) {
#pragma unroll
            for (int i = 0; i < 8; i++) {
                int gk = k0 + 16 + la_k + i;
                ra[i] = (a_row_off >= 0 && gk < K) ? A[a_row_off + gk] : 0.f;
            }
#pragma unroll
            for (int i = 0; i < 8; i++) {
                int gk = k0 + 16 + lb_k + i;
                float v = 0.f;
                if (gn_b < N && gk < K)
                    v = B_K_CONTIG ? Bm[(long)gn_b * ldB + gk] : Bm[(long)gk * ldB + gn_b];
                rb[i] = v;
            }
        }

        // compute 2 k8 steps
#pragma unroll
        for (int ks = 0; ks < 16; ks += 8) {
            unsigned bh[4][2], bl[4][2];
#pragma unroll
            for (int j = 0; j < 4; j++) {
                int bn = wn * 32 + j * 8 + g;
                float b0 = Bs[bn][ks + tq];
                float b1 = Bs[bn][ks + tq + 4];
                bh[j][0] = f2tf(b0);
                bh[j][1] = f2tf(b1);
                bl[j][0] = f2tf(b0 - __uint_as_float(bh[j][0]));
                bl[j][1] = f2tf(b1 - __uint_as_float(bh[j][1]));
            }
#pragma unroll
            for (int i = 0; i < 4; i++) {
                int am = wm * 64 + i * 16 + g;
                float a0 = As[am][ks + tq];
                float a1 = As[am + 8][ks + tq];
                float a2 = As[am][ks + tq + 4];
                float a3 = As[am + 8][ks + tq + 4];
                unsigned ah[4], al[4];
                ah[0] = f2tf(a0); ah[1] = f2tf(a1); ah[2] = f2tf(a2); ah[3] = f2tf(a3);
                al[0] = f2tf(a0 - __uint_as_float(ah[0]));
                al[1] = f2tf(a1 - __uint_as_float(ah[1]));
                al[2] = f2tf(a2 - __uint_as_float(ah[2]));
                al[3] = f2tf(a3 - __uint_as_float(ah[3]));
                // hi*hi for all j, then lo*hi, then hi*lo: dependents spaced by 4
#pragma unroll
                for (int j = 0; j < 4; j++) mma_tf32(acc[i][j], ah, bh[j]);
#pragma unroll
                for (int j = 0; j < 4; j++) mma_tf32(acc[i][j], al, bh[j]);
#pragma unroll
                for (int j = 0; j < 4; j++) mma_tf32(acc[i][j], ah, bl[j]);
            }
        }
        __syncthreads();
    }

    // epilogue
#pragma unroll
    for (int i = 0; i < 4; i++) {
        int r0 = m0 + wm * 64 + i * 16 + g;
#pragma unroll
        for (int j = 0; j < 4; j++) {
            int cb = n0 + wn * 32 + j * 8 + tq * 2;
#pragma unroll
            for (int q = 0; q < 4; q++) {
                int rr = r0 + (q >> 1) * 8;          // q=0,1 -> row g; q=2,3 -> row g+8
                int cc = cb + (q & 1);
                if (rr < M && cc < N) {
                    float v = acc[i][j][q];
                    if (bias) v += bias[cc];
                    C[(long)rr * ldC + cc] = v;
                }
            }
        }
    }
}

// ---------------- small batch-8 GEMM (sequential path) ----------------
struct Seg {
    const float* A;
    const float* W;
    int ldW;
    int K;   // 0 => segment disabled
};

__global__ void gemm8(Seg s0, Seg s1,
                      const float* __restrict__ addend,
                      const float* __restrict__ bias,
                      float* __restrict__ C, int N, int act) {
    __shared__ float As[8][1024];
    int tid = threadIdx.x;            // 256
    int lane = tid & 31, w = tid >> 5;
    int rbase = blockIdx.x * 32 + w * 4;
    float acc[4][8];
#pragma unroll
    for (int r = 0; r < 4; r++)
#pragma unroll
        for (int b = 0; b < 8; b++) acc[r][b] = 0.f;

    for (int si = 0; si < 2; si++) {
        Seg s = si ? s1 : s0;
        if (s.K == 0) continue;
        for (int kb = 0; kb < s.K; kb += 1024) {
            int kc = min(1024, s.K - kb);
            __syncthreads();
            for (int i = tid; i < 8 * kc; i += 256) {
                int b = i / kc, k = i - b * kc;
                As[b][k] = s.A[b * s.K + kb + k];
            }
            __syncthreads();
            for (int k0 = 0; k0 < kc; k0 += 32) {
                int kk = k0 + lane;
                bool kin = kk < kc;
                float a[8];
#pragma unroll
                for (int b = 0; b < 8; b++) a[b] = kin ? As[b][kk] : 0.f;
#pragma unroll
                for (int r = 0; r < 4; r++) {
                    int row = rbase + r;
                    float wv = (kin && row < N) ? s.W[row * s.ldW + kb + kk] : 0.f;
#pragma unroll
                    for (int b = 0; b < 8; b++) acc[r][b] += wv * a[b];
                }
            }
        }
    }
#pragma unroll
    for (int r = 0; r < 4; r++)
#pragma unroll
        for (int b = 0; b < 8; b++) {
            float v = acc[r][b];
#pragma unroll
            for (int off = 16; off; off >>= 1) v += __shfl_xor_sync(0xFFFFFFFFu, v, off);
            acc[r][b] = v;
        }
    if (lane < 8) {
        int b = lane;
#pragma unroll
        for (int r = 0; r < 4; r++) {
            int row = rbase + r;
            if (row < N) {
                float v = acc[r][b];
                if (bias) v += bias[row];
                if (addend) v += addend[b * N + row];
                if (act) v = fmaxf(v, 0.f);
                C[b * N + row] = v;
            }
        }
    }
}

// ---------------- LSTM pointwise ----------------
__global__ void lstm_point(const float* __restrict__ gates,
                           float* __restrict__ h, float* __restrict__ c,
                           float* __restrict__ hcopy) {
    int idx = blockIdx.x * blockDim.x + threadIdx.x;
    if (idx >= B * H) return;
    int b = idx / H, j = idx - b * H;
    const float* g = gates + b * G4;
    float i = 1.f / (1.f + expf(-g[j]));
    float f = 1.f / (1.f + expf(-g[H + j]));
    float gg = tanhf(g[2 * H + j]);
    float o = 1.f / (1.f + expf(-g[3 * H + j]));
    float cn = f * c[idx] + i * gg;
    c[idx] = cn;
    float hn = o * tanhf(cn);
    h[idx] = hn;
    if (hcopy) hcopy[idx] = hn;
}

// ---------------- softmax over T + attention apply ----------------
__global__ void softmax_applied(const float* __restrict__ logits,
                                const float* __restrict__ enc_out,
                                float* __restrict__ applied) {
    __shared__ float aw[T];
    __shared__ float s_inv;
    int b = blockIdx.x, tid = threadIdx.x;
    if (tid < T) aw[tid] = logits[b * T + tid];
    __syncthreads();
    if (tid == 0) {
        float m = -1e30f;
        for (int t = 0; t < T; t++) m = fmaxf(m, aw[t]);
        float s = 0.f;
        for (int t = 0; t < T; t++) { float e = expf(aw[t] - m); aw[t] = e; s += e; }
        s_inv = 1.f / s;
    }
    __syncthreads();
    float inv = s_inv;
    float acc[4] = {0.f, 0.f, 0.f, 0.f};
    for (int t = 0; t < T; t++) {
        float wgt = aw[t] * inv;
        const float* row = enc_out + t * (B * H) + b * H;
#pragma unroll
        for (int q = 0; q < 4; q++) {
            int j = tid + q * 256;
            if (j < H) acc[q] += wgt * row[j];
        }
    }
#pragma unroll
    for (int q = 0; q < 4; q++) {
        int j = tid + q * 256;
        if (j < H) applied[b * H + j] = acc[q];
    }
}

// ---------------- tiny precompute kernels ----------------
__global__ void bias_sum(const float* __restrict__ a, const float* __restrict__ b,
                         float* __restrict__ o, int n) {
    int i = blockIdx.x * blockDim.x + threadIdx.x;
    if (i < n) o[i] = a[i] + b[i];
}

__global__ void calc_v(const float* __restrict__ out_b, const float* __restrict__ emb_W,
                       float* __restrict__ v) {
    int j = blockIdx.x;
    const float* row = emb_W + j * EMB_LD;
    float acc = 0.f;
    for (int e = threadIdx.x; e < E; e += 256) acc += out_b[e] * row[e];
    __shared__ float s[256];
    s[threadIdx.x] = acc;
    __syncthreads();
    for (int off = 128; off; off >>= 1) {
        if (threadIdx.x < off) s[threadIdx.x] += s[threadIdx.x + off];
        __syncthreads();
    }
    if (threadIdx.x == 0) v[j] = s[0];
}

// ---------------- host orchestration ----------------
static inline float* sym(void* p) { return (float*)p; }

extern "C" void kernel_launch(void* const* d_in, const int* in_sizes, int n_in,
                              void* d_out, int out_size) {
    const float* in_input  = (const float*)d_in[0];   // [B,T,E]
    const float* noise1    = (const float*)d_in[2];   // [S,B,NZ]
    const float* noise2    = (const float*)d_in[3];   // [S,B,H]
    const float* init_dec  = (const float*)d_in[4];   // [B,E]
    const float* enc_Wih   = (const float*)d_in[5];   // [4H,E]
    const float* enc_Whh   = (const float*)d_in[6];   // [4H,H]
    const float* enc_bih   = (const float*)d_in[7];
    const float* enc_bhh   = (const float*)d_in[8];
    const float* dec_Wih   = (const float*)d_in[9];   // [4H,H]
    const float* dec_Whh   = (const float*)d_in[10];  // [4H,H]
    const float* dec_bih   = (const float*)d_in[11];
    const float* dec_bhh   = (const float*)d_in[12];
    const float* emb_W     = (const float*)d_in[13];  // [H, E+NZ]
    const float* emb_b     = (const float*)d_in[14];
    const float* attn_W    = (const float*)d_in[15];  // [T, 3H]
    const float* attn_b    = (const float*)d_in[16];
    const float* comb_W    = (const float*)d_in[17];  // [H, 2H]
    const float* comb_b    = (const float*)d_in[18];
    const float* out_W     = (const float*)d_in[19];  // [E, H]
    const float* out_b     = (const float*)d_in[20];
    float* out = (float*)d_out;                       // [S,B,E]

    void *p_pre, *p_enc, *p_M, *p_n1, *p_n2, *p_Hs, *p_h, *p_c, *p_emb, *p_attn,
         *p_app, *p_comb, *p_g, *p_eb, *p_db, *p_v;
    cudaGetSymbolAddress(&p_pre, g_pre_enc);
    cudaGetSymbolAddress(&p_enc, g_enc_out);
    cudaGetSymbolAddress(&p_M, g_Mmat);
    cudaGetSymbolAddress(&p_n1, g_n1pre);
    cudaGetSymbolAddress(&p_n2, g_n2pre);
    cudaGetSymbolAddress(&p_Hs, g_Hs);
    cudaGetSymbolAddress(&p_h, g_h);
    cudaGetSymbolAddress(&p_c, g_c);
    cudaGetSymbolAddress(&p_emb, g_emb);
    cudaGetSymbolAddress(&p_attn, g_attn);
    cudaGetSymbolAddress(&p_app, g_applied);
    cudaGetSymbolAddress(&p_comb, g_comb);
    cudaGetSymbolAddress(&p_g, g_gates);
    cudaGetSymbolAddress(&p_eb, g_encbias);
    cudaGetSymbolAddress(&p_db, g_decbias);
    cudaGetSymbolAddress(&p_v, g_v);
    float *pre = sym(p_pre), *enc = sym(p_enc), *Mm = sym(p_M), *n1p = sym(p_n1),
          *n2p = sym(p_n2), *Hs = sym(p_Hs), *h = sym(p_h), *c = sym(p_c),
          *emb = sym(p_emb), *att = sym(p_attn), *app = sym(p_app),
          *comb = sym(p_comb), *gates = sym(p_g), *encb = sym(p_eb),
          *decb = sym(p_db), *v = sym(p_v);

    // init
    cudaMemsetAsync(h, 0, B * H * sizeof(float));
    cudaMemsetAsync(c, 0, B * H * sizeof(float));
    bias_sum<<<(G4 + 255) / 256, 256>>>(enc_bih, enc_bhh, encb, G4);
    bias_sum<<<(G4 + 255) / 256, 256>>>(dec_bih, dec_bhh, decb, G4);
    calc_v<<<H, 256>>>(out_b, emb_W, v);

    // ---- big batched precomputes (tensor-core tf32x2) ----
    // pre_enc[t*8+b, :] = input[b,t,:] @ enc_Wih^T + (bih+bhh)
    {
        dim3 grid((G4 + 127) / 128, (T * B + 127) / 128);
        gemm_mma<true, true><<<grid, 256>>>(in_input, E, T, enc_Wih, E, encb,
                                            pre, G4, T * B, G4, E);
    }
    // Mmat = emb_W[:, :E] @ out_W   (NN)
    {
        dim3 grid((H + 127) / 128, (H + 127) / 128);
        gemm_mma<false, false><<<grid, 256>>>(emb_W, EMB_LD, 0, out_W, H, nullptr,
                                              Mm, H, H, H, E);
    }
    // n1pre = noise1 @ emb_W[:, E:]^T + emb_b
    {
        dim3 grid((H + 127) / 128, (S * B + 127) / 128);
        gemm_mma<false, true><<<grid, 256>>>(noise1, NZ, 0, emb_W + E, EMB_LD, emb_b,
                                             n1p, H, S * B, H, NZ);
    }
    // n2pre = noise2 @ attn_W[:, 2H:]^T + attn_b
    {
        dim3 grid((T + 127) / 128, (S * B + 127) / 128);
        gemm_mma<false, true><<<grid, 256>>>(noise2, H, 0, attn_W + 2 * H, ATTN_LD, attn_b,
                                             n2p, T, S * B, T, H);
    }

    Seg none = {nullptr, nullptr, 0, 0};

    // ---- encoder recurrence ----
    for (int t = 0; t < T; t++) {
        Seg s0 = {h, enc_Whh, H, H};
        gemm8<<<(G4 + 31) / 32, 256>>>(s0, none, pre + t * B * G4, nullptr,
                                       gates, G4, 0);
        lstm_point<<<(B * H + 255) / 256, 256>>>(gates, h, c, enc + t * B * H);
    }

    // ---- decoder recurrence ----
    for (int s = 0; s < S; s++) {
        if (s == 0) {
            Seg s0 = {init_dec, emb_W, EMB_LD, E};
            gemm8<<<(H + 31) / 32, 256>>>(s0, none, n1p, nullptr, emb, H, 0);
        } else {
            Seg s0 = {h, Mm, H, H};
            gemm8<<<(H + 31) / 32, 256>>>(s0, none, n1p + s * B * H, v, emb, H, 0);
        }
        {
            Seg s0 = {emb, attn_W, ATTN_LD, H};
            Seg s1 = {h, attn_W + H, ATTN_LD, H};
            gemm8<<<(T + 31) / 32, 256>>>(s0, s1, n2p + s * B * T, nullptr, att, T, 0);
        }
        softmax_applied<<<B, 256>>>(att, enc, app);
        {
            Seg s0 = {emb, comb_W, COMB_LD, H};
            Seg s1 = {app, comb_W + H, COMB_LD, H};
            gemm8<<<(H + 31) / 32, 256>>>(s0, s1, nullptr, comb_b, comb, H, 1);
        }
        {
            Seg s0 = {comb, dec_Wih, H, H};
            Seg s1 = {h, dec_Whh, H, H};
            gemm8<<<(G4 + 31) / 32, 256>>>(s0, s1, nullptr, decb, gates, G4, 0);
        }
        lstm_point<<<(B * H + 255) / 256, 256>>>(gates, h, c, Hs + s * B * H);
    }

    // ---- final output GEMM: out = Hs @ out_W^T + out_b ----
    {
        dim3 grid((E + 127) / 128, (S * B + 127) / 128);
        gemm_mma<false, true><<<grid, 256>>>(Hs, H, 0, out_W, H, out_b,
                                             out, E, S * B, E, H);
    }
}

// round 4
// speedup vs baseline: 1.3149x; 1.0021x over previous
#include <cuda_runtime.h>
#include <cuda_bf16.h>
#include <math.h>

// Problem dims (fixed by setup_inputs)
constexpr int B = 8;
constexpr int T = 128;
constexpr int E = 30522;
constexpr int H = 1000;
constexpr int S = 64;
constexpr int NZ = 10000;
constexpr int G4 = 4 * H;          // 4000
constexpr int EMB_LD = E + NZ;     // 40522
constexpr int ATTN_LD = 3 * H;     // 3000
constexpr int COMB_LD = 2 * H;     // 2000
constexpr int NCTA = 148;          // persistent grid (<= SM count -> co-resident)

// ---------------- scratch (static device arrays; no allocation) ----------------
__device__ float g_pre_enc[T * B * G4];   // x@Wih^T + biases, rows t*8+b
__device__ float g_enc_out[T * B * H];    // [t][b][j]
__device__ float g_Mmat[H * H];           // M = emb_W[:, :E] @ out_W
__device__ float g_n1pre[S * B * H];      // noise1 @ emb_W[:, E:]^T + emb_b
__device__ float g_n2pre[S * B * T];      // noise2 @ attn_W[:, 2H:]^T + attn_b
__device__ float g_Hs[S * B * H];         // decoder hidden states
__device__ float g_hbuf[2][B * H];        // double-buffered h
__device__ float g_c[B * H];
__device__ float g_emb[B * H];
__device__ float g_attn[B * T];
__device__ float g_applied[B * H];
__device__ float g_comb[B * H];
__device__ float g_encbias[G4];
__device__ float g_decbias[G4];
__device__ float g_v[H];                  // out_b @ emb_W[:, :E]^T
__device__ unsigned g_bar_arrive;
__device__ unsigned g_bar_gen;

// ---------------- bf16 split helpers ----------------
__device__ __forceinline__ unsigned short f2bf_bits(float x) {
    __nv_bfloat16 b = __float2bfloat16_rn(x);
    return *reinterpret_cast<unsigned short*>(&b);
}
__device__ __forceinline__ float bf_bits2f(unsigned short u) {
    return __uint_as_float(((unsigned)u) << 16);
}
// pack (x0,x1) into hi/lo bf16x2 words
__device__ __forceinline__ void cvt_pair(float x0, float x1, unsigned& hi, unsigned& lo) {
    unsigned short h0 = f2bf_bits(x0), h1 = f2bf_bits(x1);
    unsigned short l0 = f2bf_bits(x0 - bf_bits2f(h0));
    unsigned short l1 = f2bf_bits(x1 - bf_bits2f(h1));
    hi = (unsigned)h0 | ((unsigned)h1 << 16);
    lo = (unsigned)l0 | ((unsigned)l1 << 16);
}
__device__ __forceinline__ void mma_bf16(float* c, const unsigned* a, const unsigned* b) {
    asm volatile(
        "mma.sync.aligned.m16n8k16.row.col.f32.bf16.bf16.f32 "
        "{%0,%1,%2,%3}, {%4,%5,%6,%7}, {%8,%9}, {%0,%1,%2,%3};"
        : "+f"(c[0]), "+f"(c[1]), "+f"(c[2]), "+f"(c[3])
        : "r"(a[0]), "r"(a[1]), "r"(a[2]), "r"(a[3]), "r"(b[0]), "r"(b[1]));
}

// ---------------- big GEMM via mma bf16x2: C[M,N] = A@B (+bias[n]) ----------------
template <bool SWIZ_A, bool B_K_CONTIG>
__global__ void __launch_bounds__(256, 1)
gemm_mma(const float* __restrict__ A, int ldA, int swizT,
         const float* __restrict__ Bm, int ldB,
         const float* __restrict__ bias,
         float* __restrict__ C, int ldC,
         int M, int N, int K) {
    constexpr int SH = 12;   // padded stride in 32-bit words (conflict-free)
    __shared__ unsigned AsH[128 * SH], AsL[128 * SH];
    __shared__ unsigned BsH[128 * SH], BsL[128 * SH];

    const int tid = threadIdx.x;
    const int wid = tid >> 5, lane = tid & 31;
    const int g = lane >> 2, tq = lane & 3;
    const int wm = wid & 1, wn = wid >> 1;          // 2 (m) x 4 (n) warps
    const int m0 = blockIdx.y * 128, n0 = blockIdx.x * 128;

    float acc[4][4][4];
#pragma unroll
    for (int i = 0; i < 4; i++)
#pragma unroll
        for (int j = 0; j < 4; j++)
#pragma unroll
            for (int q = 0; q < 4; q++) acc[i][j][q] = 0.f;

    const int la_m = tid >> 1, la_kb = (tid & 1) * 8;   // 8 floats each
    int lb_n, lb_kb;
    if (B_K_CONTIG) { lb_n = tid >> 1; lb_kb = (tid & 1) * 8; }
    else            { lb_n = tid & 127; lb_kb = (tid >> 7) * 8; }

    const int gm_a = m0 + la_m;
    long a_row_off = -1;
    if (gm_a < M) {
        int mr = SWIZ_A ? ((gm_a & 7) * swizT + (gm_a >> 3)) : gm_a;
        a_row_off = (long)mr * ldA;
    }
    const int gn_b = n0 + lb_n;

    float ra[8], rb[8];
#pragma unroll
    for (int i = 0; i < 8; i++) {
        int gk = la_kb + i;
        ra[i] = (a_row_off >= 0 && gk < K) ? A[a_row_off + gk] : 0.f;
    }
#pragma unroll
    for (int i = 0; i < 8; i++) {
        int gk = lb_kb + i;
        float v = 0.f;
        if (gn_b < N && gk < K)
            v = B_K_CONTIG ? Bm[(long)gn_b * ldB + gk] : Bm[(long)gk * ldB + gn_b];
        rb[i] = v;
    }

    for (int k0 = 0; k0 < K; k0 += 16) {
        // convert + commit staged regs
#pragma unroll
        for (int p = 0; p < 4; p++) {
            unsigned hi, lo;
            cvt_pair(ra[2 * p], ra[2 * p + 1], hi, lo);
            AsH[la_m * SH + (la_kb >> 1) + p] = hi;
            AsL[la_m * SH + (la_kb >> 1) + p] = lo;
        }
#pragma unroll
        for (int p = 0; p < 4; p++) {
            unsigned hi, lo;
            cvt_pair(rb[2 * p], rb[2 * p + 1], hi, lo);
            BsH[lb_n * SH + (lb_kb >> 1) + p] = hi;
            BsL[lb_n * SH + (lb_kb >> 1) + p] = lo;
        }
        __syncthreads();

        if (k0 + 16 < K) {
#pragma unroll
            for (int i = 0; i < 8; i++) {
                int gk = k0 + 16 + la_kb + i;
                ra[i] = (a_row_off >= 0 && gk < K) ? A[a_row_off + gk] : 0.f;
            }
#pragma unroll
            for (int i = 0; i < 8; i++) {
                int gk = k0 + 16 + lb_kb + i;
                float v = 0.f;
                if (gn_b < N && gk < K)
                    v = B_K_CONTIG ? Bm[(long)gn_b * ldB + gk] : Bm[(long)gk * ldB + gn_b];
                rb[i] = v;
            }
        }

        unsigned bh[4][2], bl[4][2];
#pragma unroll
        for (int j = 0; j < 4; j++) {
            int bn = wn * 32 + j * 8 + g;
            bh[j][0] = BsH[bn * SH + tq];
            bh[j][1] = BsH[bn * SH + tq + 4];
            bl[j][0] = BsL[bn * SH + tq];
            bl[j][1] = BsL[bn * SH + tq + 4];
        }
#pragma unroll
        for (int i = 0; i < 4; i++) {
            int am = wm * 64 + i * 16 + g;
            unsigned ah[4], al[4];
            ah[0] = AsH[am * SH + tq];
            ah[1] = AsH[(am + 8) * SH + tq];
            ah[2] = AsH[am * SH + tq + 4];
            ah[3] = AsH[(am + 8) * SH + tq + 4];
            al[0] = AsL[am * SH + tq];
            al[1] = AsL[(am + 8) * SH + tq];
            al[2] = AsL[am * SH + tq + 4];
            al[3] = AsL[(am + 8) * SH + tq + 4];
#pragma unroll
            for (int j = 0; j < 4; j++) mma_bf16(acc[i][j], ah, bh[j]);
#pragma unroll
            for (int j = 0; j < 4; j++) mma_bf16(acc[i][j], al, bh[j]);
#pragma unroll
            for (int j = 0; j < 4; j++) mma_bf16(acc[i][j], ah, bl[j]);
        }
        __syncthreads();
    }

    // epilogue
#pragma unroll
    for (int i = 0; i < 4; i++) {
        int r0 = m0 + wm * 64 + i * 16 + g;
#pragma unroll
        for (int j = 0; j < 4; j++) {
            int cb = n0 + wn * 32 + j * 8 + tq * 2;
#pragma unroll
            for (int q = 0; q < 4; q++) {
                int rr = r0 + (q >> 1) * 8;
                int cc = cb + (q & 1);
                if (rr < M && cc < N) {
                    float v = acc[i][j][q];
                    if (bias) v += bias[cc];
                    C[(long)rr * ldC + cc] = v;
                }
            }
        }
    }
}

// ---------------- persistent sequential kernel ----------------
__device__ __forceinline__ void grid_barrier() {
    __threadfence();
    __syncthreads();
    if (threadIdx.x == 0) {
        unsigned gen = atomicAdd(&g_bar_gen, 0u);
        if (atomicAdd(&g_bar_arrive, 1u) == gridDim.x - 1) {
            g_bar_arrive = 0;
            __threadfence();
            atomicAdd(&g_bar_gen, 1u);
        } else {
            volatile unsigned* vg = &g_bar_gen;
            while (*vg == gen) { }
        }
    }
    __syncthreads();
}

__device__ __forceinline__ float wsum(float v) {
#pragma unroll
    for (int off = 16; off; off >>= 1) v += __shfl_xor_sync(0xFFFFFFFFu, v, off);
    return v;
}
__device__ __forceinline__ float sigm(float x) { return 1.f / (1.f + expf(-x)); }

// copy B*H floats global -> smem (all 256 threads)
__device__ __forceinline__ void stage8k(float* xs, const float* src) {
    const float4* s4 = reinterpret_cast<const float4*>(src);
    float4* d4 = reinterpret_cast<float4*>(xs);
    for (int i = threadIdx.x; i < B * H / 4; i += 256) d4[i] = s4[i];
}

__global__ void __launch_bounds__(256, 1)
seq_kernel(const float* __restrict__ enc_Whh,
           const float* __restrict__ dec_Wih,
           const float* __restrict__ dec_Whh,
           const float* __restrict__ emb_W,
           const float* __restrict__ attn_W,
           const float* __restrict__ comb_W,
           const float* __restrict__ comb_b,
           const float* __restrict__ init_dec) {
    __shared__ __align__(16) float xs[B][H];
    __shared__ float aw[B][T];
    __shared__ float part[4][64];

    const int ct = blockIdx.x, tid = threadIdx.x;
    const int w = tid >> 5, lane = tid & 31;
    const int j = ct + NCTA * w;                 // row owned by this warp (w<7)
    const bool own = (w < 7) && (j < H);

    // ================= encoder =================
    for (int t = 0; t < T; t++) {
        stage8k(xs[0], g_hbuf[t & 1]);
        __syncthreads();
        float acc[4][8];
#pragma unroll
        for (int ga = 0; ga < 4; ga++)
#pragma unroll
            for (int b = 0; b < 8; b++) acc[ga][b] = 0.f;
        if (own) {
            for (int kb = 0; kb < 32; kb++) {
                int kk = kb * 32 + lane;
                bool in = kk < H;
                float xv[8];
#pragma unroll
                for (int b = 0; b < 8; b++) xv[b] = in ? xs[b][kk] : 0.f;
#pragma unroll
                for (int ga = 0; ga < 4; ga++) {
                    float wv = in ? enc_Whh[(ga * H + j) * H + kk] : 0.f;
#pragma unroll
                    for (int b = 0; b < 8; b++) acc[ga][b] += wv * xv[b];
                }
            }
        }
#pragma unroll
        for (int ga = 0; ga < 4; ga++)
#pragma unroll
            for (int b = 0; b < 8; b++) acc[ga][b] = wsum(acc[ga][b]);
        if (own && lane < 8) {
            int b = lane;
            const float* pre = g_pre_enc + (t * 8 + b) * G4;
            float gi = sigm(acc[0][b] + pre[j]);
            float gf = sigm(acc[1][b] + pre[H + j]);
            float gg = tanhf(acc[2][b] + pre[2 * H + j]);
            float go = sigm(acc[3][b] + pre[3 * H + j]);
            float cn = gf * g_c[b * H + j] + gi * gg;
            g_c[b * H + j] = cn;
            float hn = go * tanhf(cn);
            g_hbuf[(t + 1) & 1][b * H + j] = hn;
            g_enc_out[t * (B * H) + b * H + j] = hn;
        }
        grid_barrier();
    }

    // ================= decoder =================
    for (int s = 0; s < S; s++) {
        const float* hold = g_hbuf[s & 1];

        // ---- P1: emb ----
        {
            float acc[8];
#pragma unroll
            for (int b = 0; b < 8; b++) acc[b] = 0.f;
            if (s > 0) stage8k(xs[0], hold);
            __syncthreads();
            if (s == 0) {
                if (own) {
                    for (int kb = 0; kb < (E + 31) / 32; kb++) {
                        int kk = kb * 32 + lane;
                        bool in = kk < E;
                        float wv = in ? emb_W[(long)j * EMB_LD + kk] : 0.f;
#pragma unroll
                        for (int b = 0; b < 8; b++)
                            acc[b] += wv * (in ? init_dec[b * E + kk] : 0.f);
                    }
                }
            } else {
                if (own) {
                    for (int kb = 0; kb < 32; kb++) {
                        int kk = kb * 32 + lane;
                        bool in = kk < H;
                        float wv = in ? g_Mmat[j * H + kk] : 0.f;
#pragma unroll
                        for (int b = 0; b < 8; b++)
                            acc[b] += wv * (in ? xs[b][kk] : 0.f);
                    }
                }
            }
#pragma unroll
            for (int b = 0; b < 8; b++) acc[b] = wsum(acc[b]);
            if (own && lane < 8) {
                int b = lane;
                float e = acc[b] + g_n1pre[(s * 8 + b) * H + j];
                if (s > 0) e += g_v[j];
                g_emb[b * H + j] = e;
            }
        }
        grid_barrier();

        // ---- P2: attention logits (CTA = t') ----
        if (ct < T) {
            int tp = ct, b = w;   // all 8 warps
            float acc = 0.f;
            for (int kb = 0; kb < 32; kb++) {
                int kk = kb * 32 + lane;
                if (kk < H)
                    acc += g_emb[b * H + kk] * attn_W[tp * ATTN_LD + kk];
            }
            for (int kb = 0; kb < 32; kb++) {
                int kk = kb * 32 + lane;
                if (kk < H)
                    acc += hold[b * H + kk] * attn_W[tp * ATTN_LD + H + kk];
            }
            acc = wsum(acc);
            if (lane == 0)
                g_attn[b * T + tp] = acc + g_n2pre[(s * 8 + b) * T + tp];
        }
        grid_barrier();

        // ---- P3: softmax + applied ----
        {
            float vx[4];
#pragma unroll
            for (int q = 0; q < 4; q++) vx[q] = g_attn[w * T + lane + 32 * q];
            float m = fmaxf(fmaxf(vx[0], vx[1]), fmaxf(vx[2], vx[3]));
#pragma unroll
            for (int off = 16; off; off >>= 1)
                m = fmaxf(m, __shfl_xor_sync(0xFFFFFFFFu, m, off));
            float e[4], ssum = 0.f;
#pragma unroll
            for (int q = 0; q < 4; q++) { e[q] = expf(vx[q] - m); ssum += e[q]; }
            ssum = wsum(ssum);
            float inv = 1.f / ssum;
#pragma unroll
            for (int q = 0; q < 4; q++) aw[w][lane + 32 * q] = e[q] * inv;
            __syncthreads();

            int q = tid >> 6, il = tid & 63;
            int item = ct * 55 + il;
            if (il < 55 && item < B * H) {
                int b = item / H, jj = item - b * H;
                const float* eo = g_enc_out + b * H + jj;
                float a = 0.f;
                int t0 = q * 32;
#pragma unroll 8
                for (int tt = 0; tt < 32; tt++)
                    a += aw[b][t0 + tt] * eo[(t0 + tt) * (B * H)];
                part[q][il] = a;
            }
            __syncthreads();
            if (tid < 55) {
                int it2 = ct * 55 + tid;
                if (it2 < B * H) {
                    int b = it2 / H, jj = it2 - b * H;
                    g_applied[b * H + jj] =
                        part[0][tid] + part[1][tid] + part[2][tid] + part[3][tid];
                }
            }
        }
        grid_barrier();

        // ---- P4: comb = relu(emb@Wc1^T + applied@Wc2^T + comb_b) ----
        {
            float acc[8];
#pragma unroll
            for (int b = 0; b < 8; b++) acc[b] = 0.f;
            stage8k(xs[0], g_emb);
            __syncthreads();
            if (own) {
                for (int kb = 0; kb < 32; kb++) {
                    int kk = kb * 32 + lane;
                    bool in = kk < H;
                    float wv = in ? comb_W[j * COMB_LD + kk] : 0.f;
#pragma unroll
                    for (int b = 0; b < 8; b++) acc[b] += wv * (in ? xs[b][kk] : 0.f);
                }
            }
            __syncthreads();
            stage8k(xs[0], g_applied);
            __syncthreads();
            if (own) {
                for (int kb = 0; kb < 32; kb++) {
                    int kk = kb * 32 + lane;
                    bool in = kk < H;
                    float wv = in ? comb_W[j * COMB_LD + H + kk] : 0.f;
#pragma unroll
                    for (int b = 0; b < 8; b++) acc[b] += wv * (in ? xs[b][kk] : 0.f);
                }
            }
#pragma unroll
            for (int b = 0; b < 8; b++) acc[b] = wsum(acc[b]);
            if (own && lane < 8) {
                int b = lane;
                g_comb[b * H + j] = fmaxf(acc[b] + comb_b[j], 0.f);
            }
        }
        grid_barrier();

        // ---- P5: gates + LSTM pointwise ----
        {
            float acc[4][8];
#pragma unroll
            for (int ga = 0; ga < 4; ga++)
#pragma unroll
                for (int b = 0; b < 8; b++) acc[ga][b] = 0.f;
            stage8k(xs[0], g_comb);
            __syncthreads();
            if (own) {
                for (int kb = 0; kb < 32; kb++) {
                    int kk = kb * 32 + lane;
                    bool in = kk < H;
                    float xv[8];
#pragma unroll
                    for (int b = 0; b < 8; b++) xv[b] = in ? xs[b][kk] : 0.f;
#pragma unroll
                    for (int ga = 0; ga < 4; ga++) {
                        float wv = in ? dec_Wih[(ga * H + j) * H + kk] : 0.f;
#pragma unroll
                        for (int b = 0; b < 8; b++) acc[ga][b] += wv * xv[b];
                    }
                }
            }
            __syncthreads();
            stage8k(xs[0], hold);
            __syncthreads();
            if (own) {
                for (int kb = 0; kb < 32; kb++) {
                    int kk = kb * 32 + lane;
                    bool in = kk < H;
                    float xv[8];
#pragma unroll
                    for (int b = 0; b < 8; b++) xv[b] = in ? xs[b][kk] : 0.f;
#pragma unroll
                    for (int ga = 0; ga < 4; ga++) {
                        float wv = in ? dec_Whh[(ga * H + j) * H + kk] : 0.f;
#pragma unroll
                        for (int b = 0; b < 8; b++) acc[ga][b] += wv * xv[b];
                    }
                }
            }
#pragma unroll
            for (int ga = 0; ga < 4; ga++)
#pragma unroll
                for (int b = 0; b < 8; b++) acc[ga][b] = wsum(acc[ga][b]);
            if (own && lane < 8) {
                int b = lane;
                float gi = sigm(acc[0][b] + g_decbias[j]);
                float gf = sigm(acc[1][b] + g_decbias[H + j]);
                float gg = tanhf(acc[2][b] + g_decbias[2 * H + j]);
                float go = sigm(acc[3][b] + g_decbias[3 * H + j]);
                float cn = gf * g_c[b * H + j] + gi * gg;
                g_c[b * H + j] = cn;
                float hn = go * tanhf(cn);
                g_hbuf[(s + 1) & 1][b * H + j] = hn;
                g_Hs[s * (B * H) + b * H + j] = hn;
            }
        }
        grid_barrier();
    }
}

// ---------------- tiny precompute kernels ----------------
__global__ void bias_sum(const float* __restrict__ a, const float* __restrict__ b,
                         float* __restrict__ o, int n) {
    int i = blockIdx.x * blockDim.x + threadIdx.x;
    if (i < n) o[i] = a[i] + b[i];
}

__global__ void calc_v(const float* __restrict__ out_b, const float* __restrict__ emb_W,
                       float* __restrict__ v) {
    int j = blockIdx.x;
    const float* row = emb_W + (long)j * EMB_LD;
    float acc = 0.f;
    for (int e = threadIdx.x; e < E; e += 256) acc += out_b[e] * row[e];
    __shared__ float s[256];
    s[threadIdx.x] = acc;
    __syncthreads();
    for (int off = 128; off; off >>= 1) {
        if (threadIdx.x < off) s[threadIdx.x] += s[threadIdx.x + off];
        __syncthreads();
    }
    if (threadIdx.x == 0) v[j] = s[0];
}

// ---------------- host orchestration ----------------
static inline float* sym(const void* p) { return (float*)p; }

extern "C" void kernel_launch(void* const* d_in, const int* in_sizes, int n_in,
                              void* d_out, int out_size) {
    const float* in_input  = (const float*)d_in[0];   // [B,T,E]
    const float* noise1    = (const float*)d_in[2];   // [S,B,NZ]
    const float* noise2    = (const float*)d_in[3];   // [S,B,H]
    const float* init_dec  = (const float*)d_in[4];   // [B,E]
    const float* enc_Wih   = (const float*)d_in[5];   // [4H,E]
    const float* enc_Whh   = (const float*)d_in[6];   // [4H,H]
    const float* enc_bih   = (const float*)d_in[7];
    const float* enc_bhh   = (const float*)d_in[8];
    const float* dec_Wih   = (const float*)d_in[9];   // [4H,H]
    const float* dec_Whh   = (const float*)d_in[10];  // [4H,H]
    const float* dec_bih   = (const float*)d_in[11];
    const float* dec_bhh   = (const float*)d_in[12];
    const float* emb_W     = (const float*)d_in[13];  // [H, E+NZ]
    const float* attn_W    = (const float*)d_in[15];  // [T, 3H]
    const float* comb_W    = (const float*)d_in[17];  // [H, 2H]
    const float* comb_b    = (const float*)d_in[18];
    const float* out_W     = (const float*)d_in[19];  // [E, H]
    const float* out_b     = (const float*)d_in[20];
    const float* emb_b     = (const float*)d_in[14];
    const float* attn_b    = (const float*)d_in[16];
    float* out = (float*)d_out;                       // [S,B,E]

    void *p_pre, *p_M, *p_n1, *p_n2, *p_Hs, *p_hb, *p_c, *p_eb, *p_db, *p_v;
    cudaGetSymbolAddress(&p_pre, g_pre_enc);
    cudaGetSymbolAddress(&p_M, g_Mmat);
    cudaGetSymbolAddress(&p_n1, g_n1pre);
    cudaGetSymbolAddress(&p_n2, g_n2pre);
    cudaGetSymbolAddress(&p_Hs, g_Hs);
    cudaGetSymbolAddress(&p_hb, g_hbuf);
    cudaGetSymbolAddress(&p_c, g_c);
    cudaGetSymbolAddress(&p_eb, g_encbias);
    cudaGetSymbolAddress(&p_db, g_decbias);
    cudaGetSymbolAddress(&p_v, g_v);
    float *pre = sym(p_pre), *Mm = sym(p_M), *n1p = sym(p_n1), *n2p = sym(p_n2),
          *Hs = sym(p_Hs), *hb = sym(p_hb), *c = sym(p_c),
          *encb = sym(p_eb), *decb = sym(p_db), *v = sym(p_v);

    // init h (buffer 0) and c to zero
    cudaMemsetAsync(hb, 0, B * H * sizeof(float));
    cudaMemsetAsync(c, 0, B * H * sizeof(float));
    bias_sum<<<(G4 + 255) / 256, 256>>>(enc_bih, enc_bhh, encb, G4);
    bias_sum<<<(G4 + 255) / 256, 256>>>(dec_bih, dec_bhh, decb, G4);
    calc_v<<<H, 256>>>(out_b, emb_W, v);

    // ---- big batched precomputes (tensor cores, bf16x2) ----
    {   // pre_enc[t*8+b, :] = input[b,t,:] @ enc_Wih^T + (bih+bhh)
        dim3 grid((G4 + 127) / 128, (T * B + 127) / 128);
        gemm_mma<true, true><<<grid, 256>>>(in_input, E, T, enc_Wih, E, encb,
                                            pre, G4, T * B, G4, E);
    }
    {   // Mmat = emb_W[:, :E] @ out_W   (NN)
        dim3 grid((H + 127) / 128, (H + 127) / 128);
        gemm_mma<false, false><<<grid, 256>>>(emb_W, EMB_LD, 0, out_W, H, nullptr,
                                              Mm, H, H, H, E);
    }
    {   // n1pre = noise1 @ emb_W[:, E:]^T + emb_b
        dim3 grid((H + 127) / 128, (S * B + 127) / 128);
        gemm_mma<false, true><<<grid, 256>>>(noise1, NZ, 0, emb_W + E, EMB_LD, emb_b,
                                             n1p, H, S * B, H, NZ);
    }
    {   // n2pre = noise2 @ attn_W[:, 2H:]^T + attn_b
        dim3 grid((T + 127) / 128, (S * B + 127) / 128);
        gemm_mma<false, true><<<grid, 256>>>(noise2, H, 0, attn_W + 2 * H, ATTN_LD, attn_b,
                                             n2p, T, S * B, T, H);
    }

    // ---- whole recurrent network in ONE persistent kernel ----
    seq_kernel<<<NCTA, 256>>>(enc_Whh, dec_Wih, dec_Whh, emb_W, attn_W,
                              comb_W, comb_b, init_dec);

    // ---- final output GEMM: out = Hs @ out_W^T + out_b ----
    {
        dim3 grid((E + 127) / 128, (S * B + 127) / 128);
        gemm_mma<false, true><<<grid, 256>>>(Hs, H, 0, out_W, H, out_b,
                                             out, E, S * B, E, H);
    }
}

// round 6
// speedup vs baseline: 2.5448x; 1.9353x over previous
#include <cuda_runtime.h>
#include <cuda_bf16.h>
#include <math.h>

// Problem dims (fixed by setup_inputs)
constexpr int B = 8;
constexpr int T = 128;
constexpr int E = 30522;
constexpr int H = 1000;
constexpr int S = 64;
constexpr int NZ = 10000;
constexpr int G4 = 4 * H;          // 4000
constexpr int EMB_LD = E + NZ;     // 40522
constexpr int ATTN_LD = 3 * H;     // 3000
constexpr int COMB_LD = 2 * H;     // 2000
constexpr int NCTA = 148;

constexpr int KP_E  = 30528;       // E padded to 64
constexpr int KP_NZ = 10048;       // NZ padded to 64
constexpr int KP_H  = 1024;        // H padded to 64

// ---------------- fp32 scratch ----------------
__device__ float g_pre_enc[T * B * G4];
__device__ float g_enc_out[T * B * H];
__device__ float g_Mmat[H * H];
__device__ float g_n1pre[S * B * H];
__device__ float g_n2pre[S * B * T];
__device__ float g_Hs[S * B * H];
__device__ float g_hbuf[2][B * H];
__device__ float g_c[B * H];
__device__ float g_emb[B * H];
__device__ float g_attn[B * T];
__device__ float g_applied[B * H];
__device__ float g_comb[B * H];
__device__ float g_encbias[G4];
__device__ float g_decbias[G4];
__device__ float g_v[H];
__device__ unsigned g_bar_arrive;
__device__ unsigned g_bar_gen;

// ---------------- bf16 hi/lo operand buffers (padded) ----------------
__device__ __nv_bfloat16 g_Ain_h[1024 * KP_E],  g_Ain_l[1024 * KP_E];    // pre_enc A
__device__ __nv_bfloat16 g_Wih_h[4096 * KP_E],  g_Wih_l[4096 * KP_E];    // pre_enc B
__device__ __nv_bfloat16 g_eWE_h[1024 * KP_E],  g_eWE_l[1024 * KP_E];    // Mmat A
__device__ __nv_bfloat16 g_oWt_h[1024 * KP_E],  g_oWt_l[1024 * KP_E];    // Mmat B (out_W^T)
__device__ __nv_bfloat16 g_n1A_h[512 * KP_NZ],  g_n1A_l[512 * KP_NZ];    // n1pre A
__device__ __nv_bfloat16 g_eWN_h[1024 * KP_NZ], g_eWN_l[1024 * KP_NZ];   // n1pre B
__device__ __nv_bfloat16 g_n2A_h[512 * KP_H],   g_n2A_l[512 * KP_H];     // n2pre A
__device__ __nv_bfloat16 g_aW2_h[256 * KP_H],   g_aW2_l[256 * KP_H];     // n2pre B
__device__ __nv_bfloat16 g_oW_h[30720 * KP_H],  g_oW_l[30720 * KP_H];    // final B
__device__ __nv_bfloat16 g_HsA_h[512 * KP_H],   g_HsA_l[512 * KP_H];     // final A

// ---------------- helpers ----------------
__device__ __forceinline__ unsigned s2u(const void* p) {
    unsigned a;
    asm("{ .reg .u64 t; cvta.to.shared.u64 t, %1; cvt.u32.u64 %0, t; }"
        : "=r"(a) : "l"(p));
    return a;
}
__device__ __forceinline__ void cp16(unsigned dst, const void* src) {
    asm volatile("cp.async.cg.shared.global [%0], [%1], 16;" :: "r"(dst), "l"(src)
                 : "memory");
}
__device__ __forceinline__ void cp_commit() {
    asm volatile("cp.async.commit_group;" ::: "memory");
}
template <int N>
__device__ __forceinline__ void cp_wait() {
    asm volatile("cp.async.wait_group %0;" :: "n"(N) : "memory");
}
__device__ __forceinline__ void mma_bf16(float* c, const unsigned* a, const unsigned* b) {
    asm volatile(
        "mma.sync.aligned.m16n8k16.row.col.f32.bf16.bf16.f32 "
        "{%0,%1,%2,%3}, {%4,%5,%6,%7}, {%8,%9}, {%0,%1,%2,%3};"
        : "+f"(c[0]), "+f"(c[1]), "+f"(c[2]), "+f"(c[3])
        : "r"(a[0]), "r"(a[1]), "r"(a[2]), "r"(a[3]), "r"(b[0]), "r"(b[1]));
}

// ---------------- converters: fp32 -> bf16 hi/lo (padded, zero-filled) ------
template <bool SWIZ>
__global__ void conv_plain(const float* __restrict__ src, int ldS, int swizT,
                           __nv_bfloat16* __restrict__ dh,
                           __nv_bfloat16* __restrict__ dl,
                           int Mr, int Kr, int Kpad) {
    int row = blockIdx.x;
    int col = blockIdx.y * 256 + threadIdx.x;
    if (col >= Kpad) return;
    float x = 0.f;
    if (row < Mr && col < Kr) {
        int r = SWIZ ? ((row & 7) * swizT + (row >> 3)) : row;
        x = src[(size_t)r * ldS + col];
    }
    __nv_bfloat16 h = __float2bfloat16_rn(x);
    dh[(size_t)row * Kpad + col] = h;
    dl[(size_t)row * Kpad + col] = __float2bfloat16_rn(x - __bfloat162float(h));
}

// dst[n][k] = src[k][n]
__global__ void conv_trans(const float* __restrict__ src, int ldS,
                           __nv_bfloat16* __restrict__ dh,
                           __nv_bfloat16* __restrict__ dl,
                           int Kr, int Nr, int Kpad, int Npad) {
    __shared__ float tile[32][33];
    int kb = blockIdx.x * 32, nb = blockIdx.y * 32;
    int tx = threadIdx.x, ty = threadIdx.y;   // 32 x 8
    for (int i = ty; i < 32; i += 8) {
        int k = kb + i, n = nb + tx;
        tile[i][tx] = (k < Kr && n < Nr) ? src[(size_t)k * ldS + n] : 0.f;
    }
    __syncthreads();
    for (int i = ty; i < 32; i += 8) {
        int n = nb + i, k = kb + tx;
        if (n < Npad && k < Kpad) {
            float x = tile[tx][i];
            __nv_bfloat16 h = __float2bfloat16_rn(x);
            dh[(size_t)n * Kpad + k] = h;
            dl[(size_t)n * Kpad + k] = __float2bfloat16_rn(x - __bfloat162float(h));
        }
    }
}

// ---------------- mma.sync GEMM, bf16 hi/lo, 3-stage cp.async pipeline ------
// C[M,N] = A@B^T (+bias).  A: [gridDim.y*128, Kpad] bf16 hi/lo.
// B: [gridDim.x*256, Kpad] bf16 hi/lo.  C fp32 [M, ldC].  Kpad % 32 == 0.
// Stage layout (32-bit words): Ah 128*20 | Al 128*20 | Bh 256*20 | Bl 256*20.
constexpr int ST_W = 20 * (128 + 128 + 256 + 256);   // 15360 words
constexpr int ST_BYTES = ST_W * 4;                   // 61440
constexpr int GEMM_SMEM = 3 * ST_BYTES;              // 184320

__global__ void __launch_bounds__(256, 1)
gemm_tc(const __nv_bfloat16* __restrict__ Ah, const __nv_bfloat16* __restrict__ Al,
        const __nv_bfloat16* __restrict__ Bh, const __nv_bfloat16* __restrict__ Bl,
        int Kpad, const float* __restrict__ bias,
        float* __restrict__ C, int ldC, int M, int N) {
    extern __shared__ unsigned sm[];
    const unsigned sbase = s2u(sm);
    const int tid = threadIdx.x;
    const int wid = tid >> 5, lane = tid & 31;
    const int g = lane >> 2, tq = lane & 3;
    const int wm = wid & 1, wn = wid >> 1;           // 2 (m) x 4 (n) warps
    const int m0 = blockIdx.y * 128, n0 = blockIdx.x * 256;
    const int nch = Kpad / 32;

    float acc[4][8][4];
#pragma unroll
    for (int i = 0; i < 4; i++)
#pragma unroll
        for (int j = 0; j < 8; j++)
#pragma unroll
            for (int q = 0; q < 4; q++) acc[i][j][q] = 0.f;

    // stage loader: 3072 16B chunks / 256 threads = 12 per thread
    auto load_stage = [&](int st, int ci) {
        unsigned sb = sbase + st * ST_BYTES;
        int k0 = ci * 32;
#pragma unroll
        for (int q = 0; q < 12; q++) {
            int it = tid + q * 256;
            const __nv_bfloat16* gp;
            unsigned dw;
            if (it < 1024) {
                int idx = it & 511, r = idx >> 2, c = idx & 3;
                gp = (it < 512 ? Ah : Al) + (size_t)(m0 + r) * Kpad + k0 + c * 8;
                dw = (it < 512 ? 0u : 2560u) + r * 20 + c * 4;
            } else {
                int idx = (it - 1024) & 1023, r = idx >> 2, c = idx & 3;
                gp = (it < 2048 ? Bh : Bl) + (size_t)(n0 + r) * Kpad + k0 + c * 8;
                dw = (it < 2048 ? 5120u : 10240u) + r * 20 + c * 4;
            }
            cp16(sb + dw * 4, gp);
        }
        cp_commit();
    };

    load_stage(0, 0);
    load_stage(1, 1);

    for (int ci = 0; ci < nch; ci++) {
        int st = ci % 3;
        if (ci == nch - 1) cp_wait<0>(); else cp_wait<1>();
        __syncthreads();
        if (ci + 2 < nch) load_stage((ci + 2) % 3, ci + 2);

        const unsigned b0 = st * ST_W;
#pragma unroll
        for (int ks = 0; ks < 2; ks++) {
            int ws = ks * 8 + tq;
            unsigned ahf[4][4], alf[4][4];
#pragma unroll
            for (int i = 0; i < 4; i++) {
                int am = wm * 64 + i * 16 + g;
                ahf[i][0] = sm[b0 + am * 20 + ws];
                ahf[i][1] = sm[b0 + (am + 8) * 20 + ws];
                ahf[i][2] = sm[b0 + am * 20 + ws + 4];
                ahf[i][3] = sm[b0 + (am + 8) * 20 + ws + 4];
                alf[i][0] = sm[b0 + 2560 + am * 20 + ws];
                alf[i][1] = sm[b0 + 2560 + (am + 8) * 20 + ws];
                alf[i][2] = sm[b0 + 2560 + am * 20 + ws + 4];
                alf[i][3] = sm[b0 + 2560 + (am + 8) * 20 + ws + 4];
            }
#pragma unroll
            for (int jh = 0; jh < 2; jh++) {
                unsigned bhf[4][2], blf[4][2];
#pragma unroll
                for (int j = 0; j < 4; j++) {
                    int bn = wn * 64 + jh * 32 + j * 8 + g;
                    bhf[j][0] = sm[b0 + 5120 + bn * 20 + ws];
                    bhf[j][1] = sm[b0 + 5120 + bn * 20 + ws + 4];
                    blf[j][0] = sm[b0 + 10240 + bn * 20 + ws];
                    blf[j][1] = sm[b0 + 10240 + bn * 20 + ws + 4];
                }
#pragma unroll
                for (int i = 0; i < 4; i++)
#pragma unroll
                    for (int j = 0; j < 4; j++)
                        mma_bf16(acc[i][jh * 4 + j], ahf[i], bhf[j]);
#pragma unroll
                for (int i = 0; i < 4; i++)
#pragma unroll
                    for (int j = 0; j < 4; j++)
                        mma_bf16(acc[i][jh * 4 + j], alf[i], bhf[j]);
#pragma unroll
                for (int i = 0; i < 4; i++)
#pragma unroll
                    for (int j = 0; j < 4; j++)
                        mma_bf16(acc[i][jh * 4 + j], ahf[i], blf[j]);
            }
        }
        __syncthreads();
    }

    // epilogue
#pragma unroll
    for (int i = 0; i < 4; i++) {
        int rr0 = m0 + wm * 64 + i * 16 + g;
#pragma unroll
        for (int j = 0; j < 8; j++) {
            int cc = n0 + wn * 64 + j * 8 + tq * 2;
#pragma unroll
            for (int q = 0; q < 4; q++) {
                int rr = rr0 + (q >> 1) * 8;
                int cn = cc + (q & 1);
                if (rr < M && cn < N) {
                    float v = acc[i][j][q];
                    if (bias) v += bias[cn];
                    C[(size_t)rr * ldC + cn] = v;
                }
            }
        }
    }
}

// ---------------- persistent sequential kernel ----------------
__device__ __forceinline__ void grid_barrier() {
    __threadfence();
    __syncthreads();
    if (threadIdx.x == 0) {
        unsigned gen = atomicAdd(&g_bar_gen, 0u);
        if (atomicAdd(&g_bar_arrive, 1u) == gridDim.x - 1) {
            g_bar_arrive = 0;
            __threadfence();
            atomicAdd(&g_bar_gen, 1u);
        } else {
            volatile unsigned* vg = &g_bar_gen;
            while (*vg == gen) { }
        }
    }
    __syncthreads();
}
__device__ __forceinline__ float wsum(float v) {
#pragma unroll
    for (int off = 16; off; off >>= 1) v += __shfl_xor_sync(0xFFFFFFFFu, v, off);
    return v;
}
__device__ __forceinline__ float sigm(float x) { return 1.f / (1.f + expf(-x)); }
__device__ __forceinline__ void stage8k(float* xs, const float* src) {
    const float4* s4 = reinterpret_cast<const float4*>(src);
    float4* d4 = reinterpret_cast<float4*>(xs);
    for (int i = threadIdx.x; i < B * H / 4; i += 256) d4[i] = s4[i];
}

__global__ void __launch_bounds__(256, 1)
seq_kernel(const float* __restrict__ enc_Whh,
           const float* __restrict__ dec_Wih,
           const float* __restrict__ dec_Whh,
           const float* __restrict__ emb_W,
           const float* __restrict__ attn_W,
           const float* __restrict__ comb_W,
           const float* __restrict__ comb_b,
           const float* __restrict__ init_dec) {
    __shared__ __align__(16) float xs[B][H];
    __shared__ float aw[B][T];
    __shared__ float part[4][64];

    const int ct = blockIdx.x, tid = threadIdx.x;
    const int w = tid >> 5, lane = tid & 31;
    const int j = ct + NCTA * w;
    const bool own = (w < 7) && (j < H);

    // encoder
    for (int t = 0; t < T; t++) {
        stage8k(xs[0], g_hbuf[t & 1]);
        __syncthreads();
        float acc[4][8];
#pragma unroll
        for (int ga = 0; ga < 4; ga++)
#pragma unroll
            for (int b = 0; b < 8; b++) acc[ga][b] = 0.f;
        if (own) {
            for (int kb = 0; kb < 32; kb++) {
                int kk = kb * 32 + lane;
                bool in = kk < H;
                float xv[8];
#pragma unroll
                for (int b = 0; b < 8; b++) xv[b] = in ? xs[b][kk] : 0.f;
#pragma unroll
                for (int ga = 0; ga < 4; ga++) {
                    float wv = in ? enc_Whh[(ga * H + j) * H + kk] : 0.f;
#pragma unroll
                    for (int b = 0; b < 8; b++) acc[ga][b] += wv * xv[b];
                }
            }
        }
#pragma unroll
        for (int ga = 0; ga < 4; ga++)
#pragma unroll
            for (int b = 0; b < 8; b++) acc[ga][b] = wsum(acc[ga][b]);
        if (own && lane < 8) {
            int b = lane;
            const float* pre = g_pre_enc + (t * 8 + b) * G4;
            float gi = sigm(acc[0][b] + pre[j]);
            float gf = sigm(acc[1][b] + pre[H + j]);
            float gg = tanhf(acc[2][b] + pre[2 * H + j]);
            float go = sigm(acc[3][b] + pre[3 * H + j]);
            float cn = gf * g_c[b * H + j] + gi * gg;
            g_c[b * H + j] = cn;
            float hn = go * tanhf(cn);
            g_hbuf[(t + 1) & 1][b * H + j] = hn;
            g_enc_out[t * (B * H) + b * H + j] = hn;
        }
        grid_barrier();
    }

    // decoder
    for (int s = 0; s < S; s++) {
        const float* hold = g_hbuf[s & 1];

        // P1: emb
        {
            float acc[8];
#pragma unroll
            for (int b = 0; b < 8; b++) acc[b] = 0.f;
            if (s > 0) stage8k(xs[0], hold);
            __syncthreads();
            if (s == 0) {
                if (own) {
                    for (int kb = 0; kb < (E + 31) / 32; kb++) {
                        int kk = kb * 32 + lane;
                        bool in = kk < E;
                        float wv = in ? emb_W[(size_t)j * EMB_LD + kk] : 0.f;
#pragma unroll
                        for (int b = 0; b < 8; b++)
                            acc[b] += wv * (in ? init_dec[b * E + kk] : 0.f);
                    }
                }
            } else {
                if (own) {
                    for (int kb = 0; kb < 32; kb++) {
                        int kk = kb * 32 + lane;
                        bool in = kk < H;
                        float wv = in ? g_Mmat[j * H + kk] : 0.f;
#pragma unroll
                        for (int b = 0; b < 8; b++)
                            acc[b] += wv * (in ? xs[b][kk] : 0.f);
                    }
                }
            }
#pragma unroll
            for (int b = 0; b < 8; b++) acc[b] = wsum(acc[b]);
            if (own && lane < 8) {
                int b = lane;
                float e = acc[b] + g_n1pre[(s * 8 + b) * H + j];
                if (s > 0) e += g_v[j];
                g_emb[b * H + j] = e;
            }
        }
        grid_barrier();

        // P2: attention logits
        if (ct < T) {
            int tp = ct, b = w;
            float acc = 0.f;
            for (int kb = 0; kb < 32; kb++) {
                int kk = kb * 32 + lane;
                if (kk < H) acc += g_emb[b * H + kk] * attn_W[tp * ATTN_LD + kk];
            }
            for (int kb = 0; kb < 32; kb++) {
                int kk = kb * 32 + lane;
                if (kk < H) acc += hold[b * H + kk] * attn_W[tp * ATTN_LD + H + kk];
            }
            acc = wsum(acc);
            if (lane == 0)
                g_attn[b * T + tp] = acc + g_n2pre[(s * 8 + b) * T + tp];
        }
        grid_barrier();

        // P3: softmax + applied
        {
            float vx[4];
#pragma unroll
            for (int q = 0; q < 4; q++) vx[q] = g_attn[w * T + lane + 32 * q];
            float m = fmaxf(fmaxf(vx[0], vx[1]), fmaxf(vx[2], vx[3]));
#pragma unroll
            for (int off = 16; off; off >>= 1)
                m = fmaxf(m, __shfl_xor_sync(0xFFFFFFFFu, m, off));
            float e[4], ssum = 0.f;
#pragma unroll
            for (int q = 0; q < 4; q++) { e[q] = expf(vx[q] - m); ssum += e[q]; }
            ssum = wsum(ssum);
            float inv = 1.f / ssum;
#pragma unroll
            for (int q = 0; q < 4; q++) aw[w][lane + 32 * q] = e[q] * inv;
            __syncthreads();

            int q = tid >> 6, il = tid & 63;
            int item = ct * 55 + il;
            if (il < 55 && item < B * H) {
                int b = item / H, jj = item - b * H;
                const float* eo = g_enc_out + b * H + jj;
                float a = 0.f;
                int t0 = q * 32;
#pragma unroll 8
                for (int tt = 0; tt < 32; tt++)
                    a += aw[b][t0 + tt] * eo[(t0 + tt) * (B * H)];
                part[q][il] = a;
            }
            __syncthreads();
            if (tid < 55) {
                int it2 = ct * 55 + tid;
                if (it2 < B * H) {
                    int b = it2 / H, jj = it2 - b * H;
                    g_applied[b * H + jj] =
                        part[0][tid] + part[1][tid] + part[2][tid] + part[3][tid];
                }
            }
        }
        grid_barrier();

        // P4: comb
        {
            float acc[8];
#pragma unroll
            for (int b = 0; b < 8; b++) acc[b] = 0.f;
            stage8k(xs[0], g_emb);
            __syncthreads();
            if (own) {
                for (int kb = 0; kb < 32; kb++) {
                    int kk = kb * 32 + lane;
                    bool in = kk < H;
                    float wv = in ? comb_W[j * COMB_LD + kk] : 0.f;
#pragma unroll
                    for (int b = 0; b < 8; b++) acc[b] += wv * (in ? xs[b][kk] : 0.f);
                }
            }
            __syncthreads();
            stage8k(xs[0], g_applied);
            __syncthreads();
            if (own) {
                for (int kb = 0; kb < 32; kb++) {
                    int kk = kb * 32 + lane;
                    bool in = kk < H;
                    float wv = in ? comb_W[j * COMB_LD + H + kk] : 0.f;
#pragma unroll
                    for (int b = 0; b < 8; b++) acc[b] += wv * (in ? xs[b][kk] : 0.f);
                }
            }
#pragma unroll
            for (int b = 0; b < 8; b++) acc[b] = wsum(acc[b]);
            if (own && lane < 8) {
                int b = lane;
                g_comb[b * H + j] = fmaxf(acc[b] + comb_b[j], 0.f);
            }
        }
        grid_barrier();

        // P5: gates + LSTM pointwise
        {
            float acc[4][8];
#pragma unroll
            for (int ga = 0; ga < 4; ga++)
#pragma unroll
                for (int b = 0; b < 8; b++) acc[ga][b] = 0.f;
            stage8k(xs[0], g_comb);
            __syncthreads();
            if (own) {
                for (int kb = 0; kb < 32; kb++) {
                    int kk = kb * 32 + lane;
                    bool in = kk < H;
                    float xv[8];
#pragma unroll
                    for (int b = 0; b < 8; b++) xv[b] = in ? xs[b][kk] : 0.f;
#pragma unroll
                    for (int ga = 0; ga < 4; ga++) {
                        float wv = in ? dec_Wih[(ga * H + j) * H + kk] : 0.f;
#pragma unroll
                        for (int b = 0; b < 8; b++) acc[ga][b] += wv * xv[b];
                    }
                }
            }
            __syncthreads();
            stage8k(xs[0], hold);
            __syncthreads();
            if (own) {
                for (int kb = 0; kb < 32; kb++) {
                    int kk = kb * 32 + lane;
                    bool in = kk < H;
                    float xv[8];
#pragma unroll
                    for (int b = 0; b < 8; b++) xv[b] = in ? xs[b][kk] : 0.f;
#pragma unroll
                    for (int ga = 0; ga < 4; ga++) {
                        float wv = in ? dec_Whh[(ga * H + j) * H + kk] : 0.f;
#pragma unroll
                        for (int b = 0; b < 8; b++) acc[ga][b] += wv * xv[b];
                    }
                }
            }
#pragma unroll
            for (int ga = 0; ga < 4; ga++)
#pragma unroll
                for (int b = 0; b < 8; b++) acc[ga][b] = wsum(acc[ga][b]);
            if (own && lane < 8) {
                int b = lane;
                float gi = sigm(acc[0][b] + g_decbias[j]);
                float gf = sigm(acc[1][b] + g_decbias[H + j]);
                float gg = tanhf(acc[2][b] + g_decbias[2 * H + j]);
                float go = sigm(acc[3][b] + g_decbias[3 * H + j]);
                float cn = gf * g_c[b * H + j] + gi * gg;
                g_c[b * H + j] = cn;
                float hn = go * tanhf(cn);
                g_hbuf[(s + 1) & 1][b * H + j] = hn;
                g_Hs[s * (B * H) + b * H + j] = hn;
            }
        }
        grid_barrier();
    }
}

// ---------------- tiny precompute kernels ----------------
__global__ void bias_sum(const float* __restrict__ a, const float* __restrict__ b,
                         float* __restrict__ o, int n) {
    int i = blockIdx.x * blockDim.x + threadIdx.x;
    if (i < n) o[i] = a[i] + b[i];
}
__global__ void calc_v(const float* __restrict__ out_b, const float* __restrict__ emb_W,
                       float* __restrict__ v) {
    int j = blockIdx.x;
    const float* row = emb_W + (size_t)j * EMB_LD;
    float acc = 0.f;
    for (int e = threadIdx.x; e < E; e += 256) acc += out_b[e] * row[e];
    __shared__ float s[256];
    s[threadIdx.x] = acc;
    __syncthreads();
    for (int off = 128; off; off >>= 1) {
        if (threadIdx.x < off) s[threadIdx.x] += s[threadIdx.x + off];
        __syncthreads();
    }
    if (threadIdx.x == 0) v[j] = s[0];
}

// ---------------- host orchestration ----------------
template <typename Tp>
static Tp* sym(const void* symbol) {
    void* p;
    cudaGetSymbolAddress(&p, symbol);
    return (Tp*)p;
}

extern "C" void kernel_launch(void* const* d_in, const int* in_sizes, int n_in,
                              void* d_out, int out_size) {
    const float* in_input  = (const float*)d_in[0];
    const float* noise1    = (const float*)d_in[2];
    const float* noise2    = (const float*)d_in[3];
    const float* init_dec  = (const float*)d_in[4];
    const float* enc_Wih   = (const float*)d_in[5];
    const float* enc_Whh   = (const float*)d_in[6];
    const float* enc_bih   = (const float*)d_in[7];
    const float* enc_bhh   = (const float*)d_in[8];
    const float* dec_Wih   = (const float*)d_in[9];
    const float* dec_Whh   = (const float*)d_in[10];
    const float* dec_bih   = (const float*)d_in[11];
    const float* dec_bhh   = (const float*)d_in[12];
    const float* emb_W     = (const float*)d_in[13];
    const float* emb_b     = (const float*)d_in[14];
    const float* attn_W    = (const float*)d_in[15];
    const float* attn_b    = (const float*)d_in[16];
    const float* comb_W    = (const float*)d_in[17];
    const float* comb_b    = (const float*)d_in[18];
    const float* out_W     = (const float*)d_in[19];
    const float* out_b     = (const float*)d_in[20];
    float* out = (float*)d_out;

    float *pre = sym<float>(g_pre_enc), *Mm = sym<float>(g_Mmat),
          *n1p = sym<float>(g_n1pre), *n2p = sym<float>(g_n2pre),
          *Hs = sym<float>(g_Hs), *hb = sym<float>(g_hbuf), *c = sym<float>(g_c),
          *encb = sym<float>(g_encbias), *decb = sym<float>(g_decbias),
          *v = sym<float>(g_v);
    __nv_bfloat16 *AinH = sym<__nv_bfloat16>(g_Ain_h), *AinL = sym<__nv_bfloat16>(g_Ain_l);
    __nv_bfloat16 *WihH = sym<__nv_bfloat16>(g_Wih_h), *WihL = sym<__nv_bfloat16>(g_Wih_l);
    __nv_bfloat16 *eWEH = sym<__nv_bfloat16>(g_eWE_h), *eWEL = sym<__nv_bfloat16>(g_eWE_l);
    __nv_bfloat16 *oWtH = sym<__nv_bfloat16>(g_oWt_h), *oWtL = sym<__nv_bfloat16>(g_oWt_l);
    __nv_bfloat16 *n1AH = sym<__nv_bfloat16>(g_n1A_h), *n1AL = sym<__nv_bfloat16>(g_n1A_l);
    __nv_bfloat16 *eWNH = sym<__nv_bfloat16>(g_eWN_h), *eWNL = sym<__nv_bfloat16>(g_eWN_l);
    __nv_bfloat16 *n2AH = sym<__nv_bfloat16>(g_n2A_h), *n2AL = sym<__nv_bfloat16>(g_n2A_l);
    __nv_bfloat16 *aW2H = sym<__nv_bfloat16>(g_aW2_h), *aW2L = sym<__nv_bfloat16>(g_aW2_l);
    __nv_bfloat16 *oWH = sym<__nv_bfloat16>(g_oW_h), *oWL = sym<__nv_bfloat16>(g_oW_l);
    __nv_bfloat16 *HsAH = sym<__nv_bfloat16>(g_HsA_h), *HsAL = sym<__nv_bfloat16>(g_HsA_l);

    cudaFuncSetAttribute(gemm_tc, cudaFuncAttributeMaxDynamicSharedMemorySize,
                         GEMM_SMEM);

    cudaMemsetAsync(hb, 0, B * H * sizeof(float));
    cudaMemsetAsync(c, 0, B * H * sizeof(float));
    bias_sum<<<(G4 + 255) / 256, 256>>>(enc_bih, enc_bhh, encb, G4);
    bias_sum<<<(G4 + 255) / 256, 256>>>(dec_bih, dec_bhh, decb, G4);
    calc_v<<<H, 256>>>(out_b, emb_W, v);

    // ---- operand conversions (fp32 -> bf16 hi/lo, padded) ----
    conv_plain<true><<<dim3(1024, (KP_E + 255) / 256), 256>>>(in_input, E, T, AinH, AinL, 1024, E, KP_E);
    conv_plain<false><<<dim3(4096, (KP_E + 255) / 256), 256>>>(enc_Wih, E, 0, WihH, WihL, G4, E, KP_E);
    conv_plain<false><<<dim3(1024, (KP_E + 255) / 256), 256>>>(emb_W, EMB_LD, 0, eWEH, eWEL, H, E, KP_E);
    conv_trans<<<dim3((KP_E + 31) / 32, 32), dim3(32, 8)>>>(out_W, H, oWtH, oWtL, E, H, KP_E, 1024);
    conv_plain<false><<<dim3(512, (KP_NZ + 255) / 256), 256>>>(noise1, NZ, 0, n1AH, n1AL, 512, NZ, KP_NZ);
    conv_plain<false><<<dim3(1024, (KP_NZ + 255) / 256), 256>>>(emb_W + E, EMB_LD, 0, eWNH, eWNL, H, NZ, KP_NZ);
    conv_plain<false><<<dim3(512, 4), 256>>>(noise2, H, 0, n2AH, n2AL, 512, H, KP_H);
    conv_plain<false><<<dim3(256, 4), 256>>>(attn_W + 2 * H, ATTN_LD, 0, aW2H, aW2L, T, H, KP_H);
    conv_plain<false><<<dim3(30720, 4), 256>>>(out_W, H, 0, oWH, oWL, E, H, KP_H);

    // ---- big GEMMs on mma.sync bf16x2 pipeline ----
    gemm_tc<<<dim3(16, 8), 256, GEMM_SMEM>>>(AinH, AinL, WihH, WihL, KP_E, encb,
                                             pre, G4, T * B, G4);
    gemm_tc<<<dim3(4, 8), 256, GEMM_SMEM>>>(eWEH, eWEL, oWtH, oWtL, KP_E, nullptr,
                                            Mm, H, H, H);
    gemm_tc<<<dim3(4, 4), 256, GEMM_SMEM>>>(n1AH, n1AL, eWNH, eWNL, KP_NZ, emb_b,
                                            n1p, H, S * B, H);
    gemm_tc<<<dim3(1, 4), 256, GEMM_SMEM>>>(n2AH, n2AL, aW2H, aW2L, KP_H, attn_b,
                                            n2p, T, S * B, T);

    // ---- recurrent network (persistent) ----
    seq_kernel<<<NCTA, 256>>>(enc_Whh, dec_Wih, dec_Whh, emb_W, attn_W,
                              comb_W, comb_b, init_dec);

    // ---- final: out = Hs @ out_W^T + out_b ----
    conv_plain<false><<<dim3(512, 4), 256>>>(Hs, H, 0, HsAH, HsAL, 512, H, KP_H);
    gemm_tc<<<dim3(120, 4), 256, GEMM_SMEM>>>(HsAH, HsAL, oWH, oWL, KP_H, out_b,
                                              out, E, S * B, E);
}

// round 7
// speedup vs baseline: 3.2234x; 1.2667x over previous
#include <cuda_runtime.h>
#include <cuda_bf16.h>
#include <math.h>

// Problem dims (fixed by setup_inputs)
constexpr int B = 8;
constexpr int T = 128;
constexpr int E = 30522;
constexpr int H = 1000;
constexpr int S = 64;
constexpr int NZ = 10000;
constexpr int G4 = 4 * H;          // 4000
constexpr int EMB_LD = E + NZ;     // 40522
constexpr int ATTN_LD = 3 * H;     // 3000
constexpr int COMB_LD = 2 * H;     // 2000
constexpr int NCTA = 148;

constexpr int KP_E  = 30528;       // E padded to 64
constexpr int KP_NZ = 10048;       // NZ padded to 64
constexpr int KP_H  = 1024;        // H padded to 64

// ---------------- fp32 scratch ----------------
__device__ float g_pre_enc[T * B * G4];
__device__ float g_enc_out[T * B * H];
__device__ float g_Mmat[H * H];
__device__ float g_n1pre[S * B * H];
__device__ float g_n2pre[S * B * T];
__device__ float g_Hs[S * B * H];
__device__ float g_hbuf[2][B * H];
__device__ float g_c[B * H];
__device__ float g_emb[B * H];
__device__ float g_attn[B * T];
__device__ float g_applied[B * H];
__device__ float g_comb[B * H];
__device__ float g_encbias[G4];
__device__ float g_decbias[G4];
__device__ float g_v[H];
__device__ float g_kpart[4100000];         // split-K partials (max 8x512x1000)
__device__ unsigned g_bar_arrive;
__device__ unsigned g_bar_gen;

// ---------------- bf16 hi/lo operand buffers (padded) ----------------
__device__ __nv_bfloat16 g_Ain_h[1024 * KP_E],  g_Ain_l[1024 * KP_E];    // pre_enc A
__device__ __nv_bfloat16 g_Wih_h[4096 * KP_E],  g_Wih_l[4096 * KP_E];    // pre_enc B
__device__ __nv_bfloat16 g_eWE_h[1024 * KP_E],  g_eWE_l[1024 * KP_E];    // Mmat A
__device__ __nv_bfloat16 g_oWt_h[1024 * KP_E],  g_oWt_l[1024 * KP_E];    // Mmat B (out_W^T)
__device__ __nv_bfloat16 g_n1A_h[512 * KP_NZ],  g_n1A_l[512 * KP_NZ];    // n1pre A
__device__ __nv_bfloat16 g_eWN_h[1024 * KP_NZ], g_eWN_l[1024 * KP_NZ];   // n1pre B
__device__ __nv_bfloat16 g_n2A_h[512 * KP_H],   g_n2A_l[512 * KP_H];     // n2pre A
__device__ __nv_bfloat16 g_aW2_h[256 * KP_H],   g_aW2_l[256 * KP_H];     // n2pre B
__device__ __nv_bfloat16 g_oW_h[30720 * KP_H],  g_oW_l[30720 * KP_H];    // final B
__device__ __nv_bfloat16 g_HsA_h[512 * KP_H],   g_HsA_l[512 * KP_H];     // final A

// ---------------- helpers ----------------
__device__ __forceinline__ unsigned s2u(const void* p) {
    unsigned a;
    asm("{ .reg .u64 t; cvta.to.shared.u64 t, %1; cvt.u32.u64 %0, t; }"
        : "=r"(a) : "l"(p));
    return a;
}
__device__ __forceinline__ void cp16(unsigned dst, const void* src) {
    asm volatile("cp.async.cg.shared.global [%0], [%1], 16;" :: "r"(dst), "l"(src)
                 : "memory");
}
__device__ __forceinline__ void cp_commit() {
    asm volatile("cp.async.commit_group;" ::: "memory");
}
template <int N>
__device__ __forceinline__ void cp_wait() {
    asm volatile("cp.async.wait_group %0;" :: "n"(N) : "memory");
}
__device__ __forceinline__ void mma_bf16(float* c, const unsigned* a, const unsigned* b) {
    asm volatile(
        "mma.sync.aligned.m16n8k16.row.col.f32.bf16.bf16.f32 "
        "{%0,%1,%2,%3}, {%4,%5,%6,%7}, {%8,%9}, {%0,%1,%2,%3};"
        : "+f"(c[0]), "+f"(c[1]), "+f"(c[2]), "+f"(c[3])
        : "r"(a[0]), "r"(a[1]), "r"(a[2]), "r"(a[3]), "r"(b[0]), "r"(b[1]));
}

// ---------------- converters: fp32 -> bf16 hi/lo (padded, zero-filled) ------
template <bool SWIZ>
__global__ void conv_plain(const float* __restrict__ src, int ldS, int swizT,
                           __nv_bfloat16* __restrict__ dh,
                           __nv_bfloat16* __restrict__ dl,
                           int Mr, int Kr, int Kpad) {
    int row = blockIdx.x;
    int col = blockIdx.y * 256 + threadIdx.x;
    if (col >= Kpad) return;
    float x = 0.f;
    if (row < Mr && col < Kr) {
        int r = SWIZ ? ((row & 7) * swizT + (row >> 3)) : row;
        x = src[(size_t)r * ldS + col];
    }
    __nv_bfloat16 h = __float2bfloat16_rn(x);
    dh[(size_t)row * Kpad + col] = h;
    dl[(size_t)row * Kpad + col] = __float2bfloat16_rn(x - __bfloat162float(h));
}

// dst[n][k] = src[k][n]
__global__ void conv_trans(const float* __restrict__ src, int ldS,
                           __nv_bfloat16* __restrict__ dh,
                           __nv_bfloat16* __restrict__ dl,
                           int Kr, int Nr, int Kpad, int Npad) {
    __shared__ float tile[32][33];
    int kb = blockIdx.x * 32, nb = blockIdx.y * 32;
    int tx = threadIdx.x, ty = threadIdx.y;   // 32 x 8
    for (int i = ty; i < 32; i += 8) {
        int k = kb + i, n = nb + tx;
        tile[i][tx] = (k < Kr && n < Nr) ? src[(size_t)k * ldS + n] : 0.f;
    }
    __syncthreads();
    for (int i = ty; i < 32; i += 8) {
        int n = nb + i, k = kb + tx;
        if (n < Npad && k < Kpad) {
            float x = tile[tx][i];
            __nv_bfloat16 h = __float2bfloat16_rn(x);
            dh[(size_t)n * Kpad + k] = h;
            dl[(size_t)n * Kpad + k] = __float2bfloat16_rn(x - __bfloat162float(h));
        }
    }
}

// ---------------- mma.sync GEMM, bf16 hi/lo, 3-stage cp.async, split-K ------
// C[M,N] = A@B^T. A: [gy*128, Kpad]; B: [gx*256, Kpad]. Kpad % 32 == 0.
// blockIdx.z = K-slice (cps chunks of 32 each). partial=1 => write fp32
// partials to C + z*M*N (ld=N, no bias); else direct with bias.
constexpr int ST_W = 20 * (128 + 128 + 256 + 256);   // 15360 words
constexpr int ST_BYTES = ST_W * 4;                   // 61440
constexpr int GEMM_SMEM = 3 * ST_BYTES;              // 184320

__global__ void __launch_bounds__(256, 1)
gemm_tc(const __nv_bfloat16* __restrict__ Ah, const __nv_bfloat16* __restrict__ Al,
        const __nv_bfloat16* __restrict__ Bh, const __nv_bfloat16* __restrict__ Bl,
        int Kpad, const float* __restrict__ bias,
        float* __restrict__ C, int ldC, int M, int N, int cps, int partial) {
    extern __shared__ unsigned sm[];
    const unsigned sbase = s2u(sm);
    const int tid = threadIdx.x;
    const int wid = tid >> 5, lane = tid & 31;
    const int g = lane >> 2, tq = lane & 3;
    const int wm = wid & 1, wn = wid >> 1;           // 2 (m) x 4 (n) warps
    const int m0 = blockIdx.y * 128, n0 = blockIdx.x * 256;
    const int nch = Kpad / 32;
    const int z = blockIdx.z;
    const int c0 = z * cps;
    const int c1 = min(nch, c0 + cps);

    float acc[4][8][4];
#pragma unroll
    for (int i = 0; i < 4; i++)
#pragma unroll
        for (int j = 0; j < 8; j++)
#pragma unroll
            for (int q = 0; q < 4; q++) acc[i][j][q] = 0.f;

    auto load_stage = [&](int st, int ci) {
        unsigned sb = sbase + st * ST_BYTES;
        int k0 = ci * 32;
#pragma unroll
        for (int q = 0; q < 12; q++) {
            int it = tid + q * 256;
            const __nv_bfloat16* gp;
            unsigned dw;
            if (it < 1024) {
                int idx = it & 511, r = idx >> 2, c = idx & 3;
                gp = (it < 512 ? Ah : Al) + (size_t)(m0 + r) * Kpad + k0 + c * 8;
                dw = (it < 512 ? 0u : 2560u) + r * 20 + c * 4;
            } else {
                int idx = (it - 1024) & 1023, r = idx >> 2, c = idx & 3;
                gp = (it < 2048 ? Bh : Bl) + (size_t)(n0 + r) * Kpad + k0 + c * 8;
                dw = (it < 2048 ? 5120u : 10240u) + r * 20 + c * 4;
            }
            cp16(sb + dw * 4, gp);
        }
        cp_commit();
    };

    if (c0 < c1)     load_stage(0, c0);
    if (c0 + 1 < c1) load_stage(1, c0 + 1);

    for (int ci = c0; ci < c1; ci++) {
        int st = (ci - c0) % 3;
        if (ci == c1 - 1) cp_wait<0>(); else cp_wait<1>();
        __syncthreads();
        if (ci + 2 < c1) load_stage((ci - c0 + 2) % 3, ci + 2);

        const unsigned b0 = st * ST_W;
#pragma unroll
        for (int ks = 0; ks < 2; ks++) {
            int ws = ks * 8 + tq;
            unsigned ahf[4][4], alf[4][4];
#pragma unroll
            for (int i = 0; i < 4; i++) {
                int am = wm * 64 + i * 16 + g;
                ahf[i][0] = sm[b0 + am * 20 + ws];
                ahf[i][1] = sm[b0 + (am + 8) * 20 + ws];
                ahf[i][2] = sm[b0 + am * 20 + ws + 4];
                ahf[i][3] = sm[b0 + (am + 8) * 20 + ws + 4];
                alf[i][0] = sm[b0 + 2560 + am * 20 + ws];
                alf[i][1] = sm[b0 + 2560 + (am + 8) * 20 + ws];
                alf[i][2] = sm[b0 + 2560 + am * 20 + ws + 4];
                alf[i][3] = sm[b0 + 2560 + (am + 8) * 20 + ws + 4];
            }
#pragma unroll
            for (int jh = 0; jh < 2; jh++) {
                unsigned bhf[4][2], blf[4][2];
#pragma unroll
                for (int j = 0; j < 4; j++) {
                    int bn = wn * 64 + jh * 32 + j * 8 + g;
                    bhf[j][0] = sm[b0 + 5120 + bn * 20 + ws];
                    bhf[j][1] = sm[b0 + 5120 + bn * 20 + ws + 4];
                    blf[j][0] = sm[b0 + 10240 + bn * 20 + ws];
                    blf[j][1] = sm[b0 + 10240 + bn * 20 + ws + 4];
                }
#pragma unroll
                for (int i = 0; i < 4; i++)
#pragma unroll
                    for (int j = 0; j < 4; j++)
                        mma_bf16(acc[i][jh * 4 + j], ahf[i], bhf[j]);
#pragma unroll
                for (int i = 0; i < 4; i++)
#pragma unroll
                    for (int j = 0; j < 4; j++)
                        mma_bf16(acc[i][jh * 4 + j], alf[i], bhf[j]);
#pragma unroll
                for (int i = 0; i < 4; i++)
#pragma unroll
                    for (int j = 0; j < 4; j++)
                        mma_bf16(acc[i][jh * 4 + j], ahf[i], blf[j]);
            }
        }
        __syncthreads();
    }

    // epilogue
    float* Cb = partial ? (C + (size_t)z * M * N) : C;
    const int ld = partial ? N : ldC;
#pragma unroll
    for (int i = 0; i < 4; i++) {
        int rr0 = m0 + wm * 64 + i * 16 + g;
#pragma unroll
        for (int j = 0; j < 8; j++) {
            int cc = n0 + wn * 64 + j * 8 + tq * 2;
#pragma unroll
            for (int q = 0; q < 4; q++) {
                int rr = rr0 + (q >> 1) * 8;
                int cn = cc + (q & 1);
                if (rr < M && cn < N) {
                    float v = acc[i][j][q];
                    if (!partial && bias) v += bias[cn];
                    Cb[(size_t)rr * ld + cn] = v;
                }
            }
        }
    }
}

// deterministic split-K reduction: out[m,n] = sum_z part[z][m,n] (+bias[n])
__global__ void reduce_k(const float* __restrict__ part,
                         const float* __restrict__ bias,
                         float* __restrict__ out,
                         int M, int N, int ldC, int slices) {
    int idx = blockIdx.x * 256 + threadIdx.x;
    if (idx >= M * N) return;
    int m = idx / N, n = idx - m * N;
    float v = bias ? bias[n] : 0.f;
    for (int z = 0; z < slices; z++) v += part[(size_t)z * M * N + idx];
    out[(size_t)m * ldC + n] = v;
}

// ---------------- persistent sequential kernel ----------------
__device__ __forceinline__ void grid_barrier() {
    __threadfence();
    __syncthreads();
    if (threadIdx.x == 0) {
        unsigned gen = atomicAdd(&g_bar_gen, 0u);
        if (atomicAdd(&g_bar_arrive, 1u) == gridDim.x - 1) {
            g_bar_arrive = 0;
            __threadfence();
            atomicAdd(&g_bar_gen, 1u);
        } else {
            volatile unsigned* vg = &g_bar_gen;
            while (*vg == gen) { }
        }
    }
    __syncthreads();
}
__device__ __forceinline__ float wsum(float v) {
#pragma unroll
    for (int off = 16; off; off >>= 1) v += __shfl_xor_sync(0xFFFFFFFFu, v, off);
    return v;
}
__device__ __forceinline__ float sigm(float x) { return 1.f / (1.f + expf(-x)); }
__device__ __forceinline__ void stage8k(float* xs, const float* src) {
    const float4* s4 = reinterpret_cast<const float4*>(src);
    float4* d4 = reinterpret_cast<float4*>(xs);
    for (int i = threadIdx.x; i < B * H / 4; i += 256) d4[i] = s4[i];
}

__global__ void __launch_bounds__(256, 1)
seq_kernel(const float* __restrict__ enc_Whh,
           const float* __restrict__ dec_Wih,
           const float* __restrict__ dec_Whh,
           const float* __restrict__ emb_W,
           const float* __restrict__ attn_W,
           const float* __restrict__ comb_W,
           const float* __restrict__ comb_b,
           const float* __restrict__ init_dec) {
    __shared__ __align__(16) float xs[B][H];
    __shared__ float aw[B][T];
    __shared__ float part[4][64];

    const int ct = blockIdx.x, tid = threadIdx.x;
    const int w = tid >> 5, lane = tid & 31;
    const int j = ct + NCTA * w;
    const bool own = (w < 7) && (j < H);

    // encoder
    for (int t = 0; t < T; t++) {
        stage8k(xs[0], g_hbuf[t & 1]);
        __syncthreads();
        float acc[4][8];
#pragma unroll
        for (int ga = 0; ga < 4; ga++)
#pragma unroll
            for (int b = 0; b < 8; b++) acc[ga][b] = 0.f;
        if (own) {
            for (int kb = 0; kb < 32; kb++) {
                int kk = kb * 32 + lane;
                bool in = kk < H;
                float xv[8];
#pragma unroll
                for (int b = 0; b < 8; b++) xv[b] = in ? xs[b][kk] : 0.f;
#pragma unroll
                for (int ga = 0; ga < 4; ga++) {
                    float wv = in ? enc_Whh[(ga * H + j) * H + kk] : 0.f;
#pragma unroll
                    for (int b = 0; b < 8; b++) acc[ga][b] += wv * xv[b];
                }
            }
        }
#pragma unroll
        for (int ga = 0; ga < 4; ga++)
#pragma unroll
            for (int b = 0; b < 8; b++) acc[ga][b] = wsum(acc[ga][b]);
        if (own && lane < 8) {
            int b = lane;
            const float* pre = g_pre_enc + (t * 8 + b) * G4;
            float gi = sigm(acc[0][b] + pre[j]);
            float gf = sigm(acc[1][b] + pre[H + j]);
            float gg = tanhf(acc[2][b] + pre[2 * H + j]);
            float go = sigm(acc[3][b] + pre[3 * H + j]);
            float cn = gf * g_c[b * H + j] + gi * gg;
            g_c[b * H + j] = cn;
            float hn = go * tanhf(cn);
            g_hbuf[(t + 1) & 1][b * H + j] = hn;
            g_enc_out[t * (B * H) + b * H + j] = hn;
        }
        grid_barrier();
    }

    // decoder
    for (int s = 0; s < S; s++) {
        const float* hold = g_hbuf[s & 1];

        // P1: emb
        {
            float acc[8];
#pragma unroll
            for (int b = 0; b < 8; b++) acc[b] = 0.f;
            if (s > 0) stage8k(xs[0], hold);
            __syncthreads();
            if (s == 0) {
                if (own) {
                    for (int kb = 0; kb < (E + 31) / 32; kb++) {
                        int kk = kb * 32 + lane;
                        bool in = kk < E;
                        float wv = in ? emb_W[(size_t)j * EMB_LD + kk] : 0.f;
#pragma unroll
                        for (int b = 0; b < 8; b++)
                            acc[b] += wv * (in ? init_dec[b * E + kk] : 0.f);
                    }
                }
            } else {
                if (own) {
                    for (int kb = 0; kb < 32; kb++) {
                        int kk = kb * 32 + lane;
                        bool in = kk < H;
                        float wv = in ? g_Mmat[j * H + kk] : 0.f;
#pragma unroll
                        for (int b = 0; b < 8; b++)
                            acc[b] += wv * (in ? xs[b][kk] : 0.f);
                    }
                }
            }
#pragma unroll
            for (int b = 0; b < 8; b++) acc[b] = wsum(acc[b]);
            if (own && lane < 8) {
                int b = lane;
                float e = acc[b] + g_n1pre[(s * 8 + b) * H + j];
                if (s > 0) e += g_v[j];
                g_emb[b * H + j] = e;
            }
        }
        grid_barrier();

        // P2: attention logits
        if (ct < T) {
            int tp = ct, b = w;
            float acc = 0.f;
            for (int kb = 0; kb < 32; kb++) {
                int kk = kb * 32 + lane;
                if (kk < H) acc += g_emb[b * H + kk] * attn_W[tp * ATTN_LD + kk];
            }
            for (int kb = 0; kb < 32; kb++) {
                int kk = kb * 32 + lane;
                if (kk < H) acc += hold[b * H + kk] * attn_W[tp * ATTN_LD + H + kk];
            }
            acc = wsum(acc);
            if (lane == 0)
                g_attn[b * T + tp] = acc + g_n2pre[(s * 8 + b) * T + tp];
        }
        grid_barrier();

        // P3: softmax + applied
        {
            float vx[4];
#pragma unroll
            for (int q = 0; q < 4; q++) vx[q] = g_attn[w * T + lane + 32 * q];
            float m = fmaxf(fmaxf(vx[0], vx[1]), fmaxf(vx[2], vx[3]));
#pragma unroll
            for (int off = 16; off; off >>= 1)
                m = fmaxf(m, __shfl_xor_sync(0xFFFFFFFFu, m, off));
            float e[4], ssum = 0.f;
#pragma unroll
            for (int q = 0; q < 4; q++) { e[q] = expf(vx[q] - m); ssum += e[q]; }
            ssum = wsum(ssum);
            float inv = 1.f / ssum;
#pragma unroll
            for (int q = 0; q < 4; q++) aw[w][lane + 32 * q] = e[q] * inv;
            __syncthreads();

            int q = tid >> 6, il = tid & 63;
            int item = ct * 55 + il;
            if (il < 55 && item < B * H) {
                int b = item / H, jj = item - b * H;
                const float* eo = g_enc_out + b * H + jj;
                float a = 0.f;
                int t0 = q * 32;
#pragma unroll 8
                for (int tt = 0; tt < 32; tt++)
                    a += aw[b][t0 + tt] * eo[(t0 + tt) * (B * H)];
                part[q][il] = a;
            }
            __syncthreads();
            if (tid < 55) {
                int it2 = ct * 55 + tid;
                if (it2 < B * H) {
                    int b = it2 / H, jj = it2 - b * H;
                    g_applied[b * H + jj] =
                        part[0][tid] + part[1][tid] + part[2][tid] + part[3][tid];
                }
            }
        }
        grid_barrier();

        // P4: comb
        {
            float acc[8];
#pragma unroll
            for (int b = 0; b < 8; b++) acc[b] = 0.f;
            stage8k(xs[0], g_emb);
            __syncthreads();
            if (own) {
                for (int kb = 0; kb < 32; kb++) {
                    int kk = kb * 32 + lane;
                    bool in = kk < H;
                    float wv = in ? comb_W[j * COMB_LD + kk] : 0.f;
#pragma unroll
                    for (int b = 0; b < 8; b++) acc[b] += wv * (in ? xs[b][kk] : 0.f);
                }
            }
            __syncthreads();
            stage8k(xs[0], g_applied);
            __syncthreads();
            if (own) {
                for (int kb = 0; kb < 32; kb++) {
                    int kk = kb * 32 + lane;
                    bool in = kk < H;
                    float wv = in ? comb_W[j * COMB_LD + H + kk] : 0.f;
#pragma unroll
                    for (int b = 0; b < 8; b++) acc[b] += wv * (in ? xs[b][kk] : 0.f);
                }
            }
#pragma unroll
            for (int b = 0; b < 8; b++) acc[b] = wsum(acc[b]);
            if (own && lane < 8) {
                int b = lane;
                g_comb[b * H + j] = fmaxf(acc[b] + comb_b[j], 0.f);
            }
        }
        grid_barrier();

        // P5: gates + LSTM pointwise
        {
            float acc[4][8];
#pragma unroll
            for (int ga = 0; ga < 4; ga++)
#pragma unroll
                for (int b = 0; b < 8; b++) acc[ga][b] = 0.f;
            stage8k(xs[0], g_comb);
            __syncthreads();
            if (own) {
                for (int kb = 0; kb < 32; kb++) {
                    int kk = kb * 32 + lane;
                    bool in = kk < H;
                    float xv[8];
#pragma unroll
                    for (int b = 0; b < 8; b++) xv[b] = in ? xs[b][kk] : 0.f;
#pragma unroll
                    for (int ga = 0; ga < 4; ga++) {
                        float wv = in ? dec_Wih[(ga * H + j) * H + kk] : 0.f;
#pragma unroll
                        for (int b = 0; b < 8; b++) acc[ga][b] += wv * xv[b];
                    }
                }
            }
            __syncthreads();
            stage8k(xs[0], hold);
            __syncthreads();
            if (own) {
                for (int kb = 0; kb < 32; kb++) {
                    int kk = kb * 32 + lane;
                    bool in = kk < H;
                    float xv[8];
#pragma unroll
                    for (int b = 0; b < 8; b++) xv[b] = in ? xs[b][kk] : 0.f;
#pragma unroll
                    for (int ga = 0; ga < 4; ga++) {
                        float wv = in ? dec_Whh[(ga * H + j) * H + kk] : 0.f;
#pragma unroll
                        for (int b = 0; b < 8; b++) acc[ga][b] += wv * xv[b];
                    }
                }
            }
#pragma unroll
            for (int ga = 0; ga < 4; ga++)
#pragma unroll
                for (int b = 0; b < 8; b++) acc[ga][b] = wsum(acc[ga][b]);
            if (own && lane < 8) {
                int b = lane;
                float gi = sigm(acc[0][b] + g_decbias[j]);
                float gf = sigm(acc[1][b] + g_decbias[H + j]);
                float gg = tanhf(acc[2][b] + g_decbias[2 * H + j]);
                float go = sigm(acc[3][b] + g_decbias[3 * H + j]);
                float cn = gf * g_c[b * H + j] + gi * gg;
                g_c[b * H + j] = cn;
                float hn = go * tanhf(cn);
                g_hbuf[(s + 1) & 1][b * H + j] = hn;
                g_Hs[s * (B * H) + b * H + j] = hn;
            }
        }
        grid_barrier();
    }
}

// ---------------- tiny precompute kernels ----------------
__global__ void bias_sum(const float* __restrict__ a, const float* __restrict__ b,
                         float* __restrict__ o, int n) {
    int i = blockIdx.x * blockDim.x + threadIdx.x;
    if (i < n) o[i] = a[i] + b[i];
}
__global__ void calc_v(const float* __restrict__ out_b, const float* __restrict__ emb_W,
                       float* __restrict__ v) {
    int j = blockIdx.x;
    const float* row = emb_W + (size_t)j * EMB_LD;
    float acc = 0.f;
    for (int e = threadIdx.x; e < E; e += 256) acc += out_b[e] * row[e];
    __shared__ float s[256];
    s[threadIdx.x] = acc;
    __syncthreads();
    for (int off = 128; off; off >>= 1) {
        if (threadIdx.x < off) s[threadIdx.x] += s[threadIdx.x + off];
        __syncthreads();
    }
    if (threadIdx.x == 0) v[j] = s[0];
}

// ---------------- host orchestration ----------------
template <typename Tp>
static Tp* sym(const void* symbol) {
    void* p;
    cudaGetSymbolAddress(&p, symbol);
    return (Tp*)p;
}

extern "C" void kernel_launch(void* const* d_in, const int* in_sizes, int n_in,
                              void* d_out, int out_size) {
    const float* in_input  = (const float*)d_in[0];
    const float* noise1    = (const float*)d_in[2];
    const float* noise2    = (const float*)d_in[3];
    const float* init_dec  = (const float*)d_in[4];
    const float* enc_Wih   = (const float*)d_in[5];
    const float* enc_Whh   = (const float*)d_in[6];
    const float* enc_bih   = (const float*)d_in[7];
    const float* enc_bhh   = (const float*)d_in[8];
    const float* dec_Wih   = (const float*)d_in[9];
    const float* dec_Whh   = (const float*)d_in[10];
    const float* dec_bih   = (const float*)d_in[11];
    const float* dec_bhh   = (const float*)d_in[12];
    const float* emb_W     = (const float*)d_in[13];
    const float* emb_b     = (const float*)d_in[14];
    const float* attn_W    = (const float*)d_in[15];
    const float* attn_b    = (const float*)d_in[16];
    const float* comb_W    = (const float*)d_in[17];
    const float* comb_b    = (const float*)d_in[18];
    const float* out_W     = (const float*)d_in[19];
    const float* out_b     = (const float*)d_in[20];
    float* out = (float*)d_out;

    float *pre = sym<float>(g_pre_enc), *Mm = sym<float>(g_Mmat),
          *n1p = sym<float>(g_n1pre), *n2p = sym<float>(g_n2pre),
          *Hs = sym<float>(g_Hs), *hb = sym<float>(g_hbuf), *c = sym<float>(g_c),
          *encb = sym<float>(g_encbias), *decb = sym<float>(g_decbias),
          *v = sym<float>(g_v), *kpart = sym<float>(g_kpart);
    __nv_bfloat16 *AinH = sym<__nv_bfloat16>(g_Ain_h), *AinL = sym<__nv_bfloat16>(g_Ain_l);
    __nv_bfloat16 *WihH = sym<__nv_bfloat16>(g_Wih_h), *WihL = sym<__nv_bfloat16>(g_Wih_l);
    __nv_bfloat16 *eWEH = sym<__nv_bfloat16>(g_eWE_h), *eWEL = sym<__nv_bfloat16>(g_eWE_l);
    __nv_bfloat16 *oWtH = sym<__nv_bfloat16>(g_oWt_h), *oWtL = sym<__nv_bfloat16>(g_oWt_l);
    __nv_bfloat16 *n1AH = sym<__nv_bfloat16>(g_n1A_h), *n1AL = sym<__nv_bfloat16>(g_n1A_l);
    __nv_bfloat16 *eWNH = sym<__nv_bfloat16>(g_eWN_h), *eWNL = sym<__nv_bfloat16>(g_eWN_l);
    __nv_bfloat16 *n2AH = sym<__nv_bfloat16>(g_n2A_h), *n2AL = sym<__nv_bfloat16>(g_n2A_l);
    __nv_bfloat16 *aW2H = sym<__nv_bfloat16>(g_aW2_h), *aW2L = sym<__nv_bfloat16>(g_aW2_l);
    __nv_bfloat16 *oWH = sym<__nv_bfloat16>(g_oW_h), *oWL = sym<__nv_bfloat16>(g_oW_l);
    __nv_bfloat16 *HsAH = sym<__nv_bfloat16>(g_HsA_h), *HsAL = sym<__nv_bfloat16>(g_HsA_l);

    cudaFuncSetAttribute(gemm_tc, cudaFuncAttributeMaxDynamicSharedMemorySize,
                         GEMM_SMEM);

    cudaMemsetAsync(hb, 0, B * H * sizeof(float));
    cudaMemsetAsync(c, 0, B * H * sizeof(float));
    bias_sum<<<(G4 + 255) / 256, 256>>>(enc_bih, enc_bhh, encb, G4);
    bias_sum<<<(G4 + 255) / 256, 256>>>(dec_bih, dec_bhh, decb, G4);
    calc_v<<<H, 256>>>(out_b, emb_W, v);

    // ---- operand conversions (fp32 -> bf16 hi/lo, padded) ----
    conv_plain<true><<<dim3(1024, (KP_E + 255) / 256), 256>>>(in_input, E, T, AinH, AinL, 1024, E, KP_E);
    conv_plain<false><<<dim3(4096, (KP_E + 255) / 256), 256>>>(enc_Wih, E, 0, WihH, WihL, G4, E, KP_E);
    conv_plain<false><<<dim3(1024, (KP_E + 255) / 256), 256>>>(emb_W, EMB_LD, 0, eWEH, eWEL, H, E, KP_E);
    conv_trans<<<dim3((KP_E + 31) / 32, 32), dim3(32, 8)>>>(out_W, H, oWtH, oWtL, E, H, KP_E, 1024);
    conv_plain<false><<<dim3(512, (KP_NZ + 255) / 256), 256>>>(noise1, NZ, 0, n1AH, n1AL, 512, NZ, KP_NZ);
    conv_plain<false><<<dim3(1024, (KP_NZ + 255) / 256), 256>>>(emb_W + E, EMB_LD, 0, eWNH, eWNL, H, NZ, KP_NZ);
    conv_plain<false><<<dim3(512, 4), 256>>>(noise2, H, 0, n2AH, n2AL, 512, H, KP_H);
    conv_plain<false><<<dim3(256, 4), 256>>>(attn_W + 2 * H, ATTN_LD, 0, aW2H, aW2L, T, H, KP_H);
    conv_plain<false><<<dim3(30720, 4), 256>>>(out_W, H, 0, oWH, oWL, E, H, KP_H);

    // ---- big GEMMs (split-K where tiles << SM count) ----
    constexpr int NCH_E = KP_E / 32;     // 954
    constexpr int NCH_NZ = KP_NZ / 32;   // 314
    constexpr int NCH_H = KP_H / 32;     // 32

    // pre_enc: 128 tiles, direct
    gemm_tc<<<dim3(16, 8, 1), 256, GEMM_SMEM>>>(AinH, AinL, WihH, WihL, KP_E, encb,
                                                pre, G4, T * B, G4, NCH_E, 0);
    // Mmat: 32 tiles x 4 K-slices
    {
        constexpr int SL = 4, CPS = (NCH_E + SL - 1) / SL;
        gemm_tc<<<dim3(4, 8, SL), 256, GEMM_SMEM>>>(eWEH, eWEL, oWtH, oWtL, KP_E,
                                                    nullptr, kpart, H, H, H, CPS, 1);
        reduce_k<<<(H * H + 255) / 256, 256>>>(kpart, nullptr, Mm, H, H, H, SL);
    }
    // n1pre: 16 tiles x 8 K-slices
    {
        constexpr int SL = 8, CPS = (NCH_NZ + SL - 1) / SL;
        gemm_tc<<<dim3(4, 4, SL), 256, GEMM_SMEM>>>(n1AH, n1AL, eWNH, eWNL, KP_NZ,
                                                    nullptr, kpart, H, S * B, H, CPS, 1);
        reduce_k<<<(S * B * H + 255) / 256, 256>>>(kpart, emb_b, n1p, S * B, H, H, SL);
    }
    // n2pre: 4 tiles x 8 K-slices
    {
        constexpr int SL = 8, CPS = (NCH_H + SL - 1) / SL;
        gemm_tc<<<dim3(1, 4, SL), 256, GEMM_SMEM>>>(n2AH, n2AL, aW2H, aW2L, KP_H,
                                                    nullptr, kpart, T, S * B, T, CPS, 1);
        reduce_k<<<(S * B * T + 255) / 256, 256>>>(kpart, attn_b, n2p, S * B, T, T, SL);
    }

    // ---- recurrent network (persistent) ----
    seq_kernel<<<NCTA, 256>>>(enc_Whh, dec_Wih, dec_Whh, emb_W, attn_W,
                              comb_W, comb_b, init_dec);

    // ---- final: out = Hs @ out_W^T + out_b ----
    conv_plain<false><<<dim3(512, 4), 256>>>(Hs, H, 0, HsAH, HsAL, 512, H, KP_H);
    gemm_tc<<<dim3(120, 4, 1), 256, GEMM_SMEM>>>(HsAH, HsAL, oWH, oWL, KP_H, out_b,
                                                 out, E, S * B, E, NCH_H, 0);
}

// round 11
// speedup vs baseline: 3.9350x; 1.2207x over previous
#include <cuda_runtime.h>
#include <cuda_bf16.h>
#include <math.h>

// Problem dims (fixed by setup_inputs)
constexpr int B = 8;
constexpr int T = 128;
constexpr int E = 30522;
constexpr int H = 1000;
constexpr int S = 64;
constexpr int NZ = 10000;
constexpr int G4 = 4 * H;          // 4000
constexpr int EMB_LD = E + NZ;     // 40522
constexpr int ATTN_LD = 3 * H;     // 3000
constexpr int COMB_LD = 2 * H;     // 2000
constexpr int NCTA = 148;

constexpr int KP_E  = 30528;       // E padded to 64
constexpr int KP_NZ = 10048;       // NZ padded to 64
constexpr int KP_H  = 1024;        // H padded to 64

// ---------------- fp32 scratch ----------------
__device__ float g_pre_enc[T * B * G4];
__device__ float g_enc_out[T * B * H];
__device__ float g_Mmat[H * H];
__device__ float g_n1pre[S * B * H];
__device__ float g_n2pre[S * B * T];
__device__ float g_Hs[S * B * H];
__device__ float g_hbuf[2][B * H];
__device__ float g_c[B * H];
__device__ float g_attn[B * T];
__device__ float g_comb[B * H];
__device__ float g_encbias[G4];
__device__ float g_decbias[G4];
__device__ float g_v[H];
__device__ float g_kpart[4100000];          // split-K partials
__device__ float g_WA[T * H];               // Wa1@M + Wa2
__device__ float g_A1M[T * H];
__device__ float g_C1M[H * H];
__device__ float g_pre_a[S * B * T];
__device__ float g_pre_c[S * B * H];
__device__ float g_n1x[S * B * H];
__device__ float g_emb0[B * H];
__device__ float g_enc2T[B * H * T];        // [b][j][t]
__device__ unsigned g_bar_arrive;
__device__ unsigned g_bar_gen;

// ---------------- bf16 hi/lo operand buffers (padded) ----------------
__device__ __nv_bfloat16 g_Ain_h[1024 * KP_E],  g_Ain_l[1024 * KP_E];
__device__ __nv_bfloat16 g_Wih_h[4096 * KP_E],  g_Wih_l[4096 * KP_E];
__device__ __nv_bfloat16 g_eWE_h[1024 * KP_E],  g_eWE_l[1024 * KP_E];
__device__ __nv_bfloat16 g_oWt_h[1024 * KP_E],  g_oWt_l[1024 * KP_E];
__device__ __nv_bfloat16 g_n1A_h[512 * KP_NZ],  g_n1A_l[512 * KP_NZ];
__device__ __nv_bfloat16 g_eWN_h[1024 * KP_NZ], g_eWN_l[1024 * KP_NZ];
__device__ __nv_bfloat16 g_n2A_h[512 * KP_H],   g_n2A_l[512 * KP_H];
__device__ __nv_bfloat16 g_aW2_h[256 * KP_H],   g_aW2_l[256 * KP_H];
__device__ __nv_bfloat16 g_oW_h[30720 * KP_H],  g_oW_l[30720 * KP_H];
__device__ __nv_bfloat16 g_HsA_h[512 * KP_H],   g_HsA_l[512 * KP_H];
__device__ __nv_bfloat16 g_Wa1_h[256 * KP_H],   g_Wa1_l[256 * KP_H];
__device__ __nv_bfloat16 g_Wc1_h[1024 * KP_H],  g_Wc1_l[1024 * KP_H];
__device__ __nv_bfloat16 g_Wc2_h[1024 * KP_H],  g_Wc2_l[1024 * KP_H];
__device__ __nv_bfloat16 g_Mt_h[1024 * KP_H],   g_Mt_l[1024 * KP_H];
__device__ __nv_bfloat16 g_id_h[128 * KP_E],    g_id_l[128 * KP_E];
__device__ __nv_bfloat16 g_n1x_h[512 * KP_H],   g_n1x_l[512 * KP_H];
__device__ __nv_bfloat16 g_eo_h[1024 * KP_H],   g_eo_l[1024 * KP_H];

// ---------------- helpers ----------------
__device__ __forceinline__ unsigned s2u(const void* p) {
    unsigned a;
    asm("{ .reg .u64 t; cvta.to.shared.u64 t, %1; cvt.u32.u64 %0, t; }"
        : "=r"(a) : "l"(p));
    return a;
}
__device__ __forceinline__ void cp16(unsigned dst, const void* src) {
    asm volatile("cp.async.cg.shared.global [%0], [%1], 16;" :: "r"(dst), "l"(src)
                 : "memory");
}
__device__ __forceinline__ void cp_commit() {
    asm volatile("cp.async.commit_group;" ::: "memory");
}
template <int N>
__device__ __forceinline__ void cp_wait() {
    asm volatile("cp.async.wait_group %0;" :: "n"(N) : "memory");
}
__device__ __forceinline__ void mma_bf16(float* c, const unsigned* a, const unsigned* b) {
    asm volatile(
        "mma.sync.aligned.m16n8k16.row.col.f32.bf16.bf16.f32 "
        "{%0,%1,%2,%3}, {%4,%5,%6,%7}, {%8,%9}, {%0,%1,%2,%3};"
        : "+f"(c[0]), "+f"(c[1]), "+f"(c[2]), "+f"(c[3])
        : "r"(a[0]), "r"(a[1]), "r"(a[2]), "r"(a[3]), "r"(b[0]), "r"(b[1]));
}

// ---------------- vectorized converter: 8 cols/thread ----------------
template <bool SWIZ>
__global__ void conv8(const float* __restrict__ src, int ldS, int swizT,
                      __nv_bfloat16* __restrict__ dh,
                      __nv_bfloat16* __restrict__ dl,
                      int Mr, int Kr, int Kpad) {
    int row = blockIdx.x;
    int c0 = (blockIdx.y * 256 + threadIdx.x) * 8;
    if (c0 >= Kpad) return;
    const float* sp = nullptr;
    if (row < Mr) {
        int r = SWIZ ? ((row & 7) * swizT + (row >> 3)) : row;
        sp = src + (size_t)r * ldS;
    }
    float x[8];
#pragma unroll
    for (int i = 0; i < 8; i++) {
        int col = c0 + i;
        x[i] = (sp && col < Kr) ? sp[col] : 0.f;
    }
    unsigned hw[4], lw[4];
#pragma unroll
    for (int p = 0; p < 4; p++) {
        __nv_bfloat16 h0 = __float2bfloat16_rn(x[2 * p]);
        __nv_bfloat16 h1 = __float2bfloat16_rn(x[2 * p + 1]);
        __nv_bfloat16 l0 = __float2bfloat16_rn(x[2 * p] - __bfloat162float(h0));
        __nv_bfloat16 l1 = __float2bfloat16_rn(x[2 * p + 1] - __bfloat162float(h1));
        hw[p] = (unsigned)*(unsigned short*)&h0 | ((unsigned)*(unsigned short*)&h1 << 16);
        lw[p] = (unsigned)*(unsigned short*)&l0 | ((unsigned)*(unsigned short*)&l1 << 16);
    }
    *(uint4*)(dh + (size_t)row * Kpad + c0) = make_uint4(hw[0], hw[1], hw[2], hw[3]);
    *(uint4*)(dl + (size_t)row * Kpad + c0) = make_uint4(lw[0], lw[1], lw[2], lw[3]);
}

// dst[n][k] = src[k][n]
__global__ void conv_trans(const float* __restrict__ src, int ldS,
                           __nv_bfloat16* __restrict__ dh,
                           __nv_bfloat16* __restrict__ dl,
                           int Kr, int Nr, int Kpad, int Npad) {
    __shared__ float tile[32][33];
    int kb = blockIdx.x * 32, nb = blockIdx.y * 32;
    int tx = threadIdx.x, ty = threadIdx.y;   // 32 x 8
    for (int i = ty; i < 32; i += 8) {
        int k = kb + i, n = nb + tx;
        tile[i][tx] = (k < Kr && n < Nr) ? src[(size_t)k * ldS + n] : 0.f;
    }
    __syncthreads();
    for (int i = ty; i < 32; i += 8) {
        int n = nb + i, k = kb + tx;
        if (n < Npad && k < Kpad) {
            float x = tile[tx][i];
            __nv_bfloat16 h = __float2bfloat16_rn(x);
            dh[(size_t)n * Kpad + k] = h;
            dl[(size_t)n * Kpad + k] = __float2bfloat16_rn(x - __bfloat162float(h));
        }
    }
}

// ---------------- mma.sync GEMM, bf16 hi/lo, 3-stage cp.async, split-K ------
constexpr int ST_W = 20 * (128 + 128 + 256 + 256);   // 15360 words
constexpr int ST_BYTES = ST_W * 4;
constexpr int GEMM_SMEM = 3 * ST_BYTES;

__global__ void __launch_bounds__(256, 1)
gemm_tc(const __nv_bfloat16* __restrict__ Ah, const __nv_bfloat16* __restrict__ Al,
        const __nv_bfloat16* __restrict__ Bh, const __nv_bfloat16* __restrict__ Bl,
        int Kpad, const float* __restrict__ bias,
        float* __restrict__ C, int ldC, int M, int N, int cps, int partial) {
    extern __shared__ unsigned sm[];
    const unsigned sbase = s2u(sm);
    const int tid = threadIdx.x;
    const int wid = tid >> 5, lane = tid & 31;
    const int g = lane >> 2, tq = lane & 3;
    const int wm = wid & 1, wn = wid >> 1;
    const int m0 = blockIdx.y * 128, n0 = blockIdx.x * 256;
    const int nch = Kpad / 32;
    const int z = blockIdx.z;
    const int c0 = z * cps;
    const int c1 = min(nch, c0 + cps);

    float acc[4][8][4];
#pragma unroll
    for (int i = 0; i < 4; i++)
#pragma unroll
        for (int j = 0; j < 8; j++)
#pragma unroll
            for (int q = 0; q < 4; q++) acc[i][j][q] = 0.f;

    auto load_stage = [&](int st, int ci) {
        unsigned sb = sbase + st * ST_BYTES;
        int k0 = ci * 32;
#pragma unroll
        for (int q = 0; q < 12; q++) {
            int it = tid + q * 256;
            const __nv_bfloat16* gp;
            unsigned dw;
            if (it < 1024) {
                int idx = it & 511, r = idx >> 2, c = idx & 3;
                gp = (it < 512 ? Ah : Al) + (size_t)(m0 + r) * Kpad + k0 + c * 8;
                dw = (it < 512 ? 0u : 2560u) + r * 20 + c * 4;
            } else {
                int idx = (it - 1024) & 1023, r = idx >> 2, c = idx & 3;
                gp = (it < 2048 ? Bh : Bl) + (size_t)(n0 + r) * Kpad + k0 + c * 8;
                dw = (it < 2048 ? 5120u : 10240u) + r * 20 + c * 4;
            }
            cp16(sb + dw * 4, gp);
        }
        cp_commit();
    };

    if (c0 < c1)     load_stage(0, c0);
    if (c0 + 1 < c1) load_stage(1, c0 + 1);

    for (int ci = c0; ci < c1; ci++) {
        int st = (ci - c0) % 3;
        if (ci == c1 - 1) cp_wait<0>(); else cp_wait<1>();
        __syncthreads();
        if (ci + 2 < c1) load_stage((ci - c0 + 2) % 3, ci + 2);

        const unsigned b0 = st * ST_W;
#pragma unroll
        for (int ks = 0; ks < 2; ks++) {
            int ws = ks * 8 + tq;
            unsigned ahf[4][4], alf[4][4];
#pragma unroll
            for (int i = 0; i < 4; i++) {
                int am = wm * 64 + i * 16 + g;
                ahf[i][0] = sm[b0 + am * 20 + ws];
                ahf[i][1] = sm[b0 + (am + 8) * 20 + ws];
                ahf[i][2] = sm[b0 + am * 20 + ws + 4];
                ahf[i][3] = sm[b0 + (am + 8) * 20 + ws + 4];
                alf[i][0] = sm[b0 + 2560 + am * 20 + ws];
                alf[i][1] = sm[b0 + 2560 + (am + 8) * 20 + ws];
                alf[i][2] = sm[b0 + 2560 + am * 20 + ws + 4];
                alf[i][3] = sm[b0 + 2560 + (am + 8) * 20 + ws + 4];
            }
#pragma unroll
            for (int jh = 0; jh < 2; jh++) {
                unsigned bhf[4][2], blf[4][2];
#pragma unroll
                for (int j = 0; j < 4; j++) {
                    int bn = wn * 64 + jh * 32 + j * 8 + g;
                    bhf[j][0] = sm[b0 + 5120 + bn * 20 + ws];
                    bhf[j][1] = sm[b0 + 5120 + bn * 20 + ws + 4];
                    blf[j][0] = sm[b0 + 10240 + bn * 20 + ws];
                    blf[j][1] = sm[b0 + 10240 + bn * 20 + ws + 4];
                }
#pragma unroll
                for (int i = 0; i < 4; i++)
#pragma unroll
                    for (int j = 0; j < 4; j++)
                        mma_bf16(acc[i][jh * 4 + j], ahf[i], bhf[j]);
#pragma unroll
                for (int i = 0; i < 4; i++)
#pragma unroll
                    for (int j = 0; j < 4; j++)
                        mma_bf16(acc[i][jh * 4 + j], alf[i], bhf[j]);
#pragma unroll
                for (int i = 0; i < 4; i++)
#pragma unroll
                    for (int j = 0; j < 4; j++)
                        mma_bf16(acc[i][jh * 4 + j], ahf[i], blf[j]);
            }
        }
        __syncthreads();
    }

    float* Cb = partial ? (C + (size_t)z * M * N) : C;
    const int ld = partial ? N : ldC;
#pragma unroll
    for (int i = 0; i < 4; i++) {
        int rr0 = m0 + wm * 64 + i * 16 + g;
#pragma unroll
        for (int j = 0; j < 8; j++) {
            int cc = n0 + wn * 64 + j * 8 + tq * 2;
#pragma unroll
            for (int q = 0; q < 4; q++) {
                int rr = rr0 + (q >> 1) * 8;
                int cn = cc + (q & 1);
                if (rr < M && cn < N) {
                    float v = acc[i][j][q];
                    if (!partial && bias) v += bias[cn];
                    Cb[(size_t)rr * ld + cn] = v;
                }
            }
        }
    }
}

// deterministic split-K reduce. emode 0: out[m*ldC+n]; 1: enc2T layout.
__global__ void reduce_k(const float* __restrict__ part,
                         const float* __restrict__ bias,
                         const float* __restrict__ add,
                         float* __restrict__ out,
                         int M, int N, int ldC, int slices, int emode) {
    int idx = blockIdx.x * 256 + threadIdx.x;
    if (idx >= M * N) return;
    int m = idx / N, n = idx - m * N;
    float v = bias ? bias[n] : 0.f;
    if (add) v += add[idx];
    for (int z = 0; z < slices; z++) v += part[(size_t)z * M * N + idx];
    if (emode == 1) out[((size_t)(m & 7) * H + n) * T + (m >> 3)] = v;
    else out[(size_t)m * ldC + n] = v;
}

// ---------------- persistent kernels ----------------
__device__ __forceinline__ void grid_barrier() {
    __threadfence();
    __syncthreads();
    if (threadIdx.x == 0) {
        unsigned gen = atomicAdd(&g_bar_gen, 0u);
        if (atomicAdd(&g_bar_arrive, 1u) == gridDim.x - 1) {
            g_bar_arrive = 0;
            __threadfence();
            atomicAdd(&g_bar_gen, 1u);
        } else {
            volatile unsigned* vg = &g_bar_gen;
            while (*vg == gen) { }
        }
    }
    __syncthreads();
}
__device__ __forceinline__ float wsum(float v) {
#pragma unroll
    for (int off = 16; off; off >>= 1) v += __shfl_xor_sync(0xFFFFFFFFu, v, off);
    return v;
}
__device__ __forceinline__ float sigm(float x) { return 1.f / (1.f + expf(-x)); }
__device__ __forceinline__ void stage8k(float* xs, const float* src) {
    const float4* s4 = reinterpret_cast<const float4*>(src);
    float4* d4 = reinterpret_cast<float4*>(xs);
    for (int i = threadIdx.x; i < B * H / 4; i += 256) d4[i] = s4[i];
}

__global__ void __launch_bounds__(256, 1)
enc_kernel(const float* __restrict__ enc_Whh) {
    __shared__ __align__(16) float xs[B][H];
    const int ct = blockIdx.x, tid = threadIdx.x;
    const int w = tid >> 5, lane = tid & 31;
    const int j = ct + NCTA * w;
    const bool own = (w < 7) && (j < H);

    for (int t = 0; t < T; t++) {
        stage8k(xs[0], g_hbuf[t & 1]);
        __syncthreads();
        float acc[4][8];
#pragma unroll
        for (int ga = 0; ga < 4; ga++)
#pragma unroll
            for (int b = 0; b < 8; b++) acc[ga][b] = 0.f;
        if (own) {
            for (int kb = 0; kb < 32; kb++) {
                int kk = kb * 32 + lane;
                bool in = kk < H;
                float xv[8];
#pragma unroll
                for (int b = 0; b < 8; b++) xv[b] = in ? xs[b][kk] : 0.f;
#pragma unroll
                for (int ga = 0; ga < 4; ga++) {
                    float wv = in ? enc_Whh[(ga * H + j) * H + kk] : 0.f;
#pragma unroll
                    for (int b = 0; b < 8; b++) acc[ga][b] += wv * xv[b];
                }
            }
        }
#pragma unroll
        for (int ga = 0; ga < 4; ga++)
#pragma unroll
            for (int b = 0; b < 8; b++) acc[ga][b] = wsum(acc[ga][b]);
        if (own && lane < 8) {
            int b = lane;
            const float* pre = g_pre_enc + (t * 8 + b) * G4;
            float gi = sigm(acc[0][b] + pre[j]);
            float gf = sigm(acc[1][b] + pre[H + j]);
            float gg = tanhf(acc[2][b] + pre[2 * H + j]);
            float go = sigm(acc[3][b] + pre[3 * H + j]);
            float cn = gf * g_c[b * H + j] + gi * gg;
            g_c[b * H + j] = cn;
            float hn = go * tanhf(cn);
            g_hbuf[(t + 1) & 1][b * H + j] = hn;
            g_enc_out[t * (B * H) + b * H + j] = hn;
        }
        grid_barrier();
    }
}

// decoder: 3 phases/step. dynamic smem: xs(h) 8000f | cs(comb) 8000f | aw 1024f
constexpr int DEC_SMEM = (8000 + 8000 + 1024) * 4;

__global__ void __launch_bounds__(256, 1)
dec_kernel(const float* __restrict__ dec_Wih,
           const float* __restrict__ dec_Whh,
           const float* __restrict__ attn_W) {
    extern __shared__ __align__(16) float dsm[];
    float* xs = dsm;             // [8][1000] h
    float* cs = dsm + 8000;      // [8][1000] comb
    float* aw = dsm + 16000;     // [8][128]

    const int ct = blockIdx.x, tid = threadIdx.x;
    const int w = tid >> 5, lane = tid & 31;
    const int j = ct + NCTA * w;
    const bool own = (w < 7) && (j < H);

    for (int s = 0; s < S; s++) {
        stage8k(xs, g_hbuf[s & 1]);
        __syncthreads();

        // ---- phase A: rc = C1M@h partials; attn logits ----
        float rc[8];
#pragma unroll
        for (int b = 0; b < 8; b++) rc[b] = 0.f;
        if (s > 0 && own) {
            for (int kb = 0; kb < 32; kb++) {
                int kk = kb * 32 + lane;
                if (kk < H) {
                    float cw = g_C1M[j * H + kk];
#pragma unroll
                    for (int b = 0; b < 8; b++) rc[b] += cw * xs[b * H + kk];
                }
            }
        }
        if (ct < T) {
            int tp = ct, b = w;
            float acc = 0.f;
            if (s == 0) {
                for (int kb = 0; kb < 32; kb++) {
                    int kk = kb * 32 + lane;
                    if (kk < H) acc += xs[b * H + kk] * attn_W[tp * ATTN_LD + H + kk];
                }
            } else {
                for (int kb = 0; kb < 32; kb++) {
                    int kk = kb * 32 + lane;
                    if (kk < H) acc += xs[b * H + kk] * g_WA[tp * H + kk];
                }
            }
            acc = wsum(acc);
            if (lane == 0)
                g_attn[b * T + tp] = acc + g_pre_a[(s * 8 + b) * T + tp];
        }
        grid_barrier();

        // ---- phase B: local softmax + comb ----
        {
            int b = w;
            float vx[4];
#pragma unroll
            for (int q = 0; q < 4; q++) vx[q] = g_attn[b * T + lane + 32 * q];
            float m = fmaxf(fmaxf(vx[0], vx[1]), fmaxf(vx[2], vx[3]));
#pragma unroll
            for (int off = 16; off; off >>= 1)
                m = fmaxf(m, __shfl_xor_sync(0xFFFFFFFFu, m, off));
            float e[4], ssum = 0.f;
#pragma unroll
            for (int q = 0; q < 4; q++) { e[q] = expf(vx[q] - m); ssum += e[q]; }
            ssum = wsum(ssum);
            float inv = 1.f / ssum;
#pragma unroll
            for (int q = 0; q < 4; q++) aw[b * T + lane + 32 * q] = e[q] * inv;
        }
        __syncthreads();
        if (own) {
#pragma unroll
            for (int b = 0; b < 8; b++) {
                const float* e2 = g_enc2T + ((size_t)b * H + j) * T;
                float a = 0.f;
#pragma unroll
                for (int it = 0; it < 4; it++)
                    a += aw[b * T + lane + 32 * it] * e2[lane + 32 * it];
                rc[b] += a;
            }
#pragma unroll
            for (int b = 0; b < 8; b++) rc[b] = wsum(rc[b]);
            if (lane < 8) {
                int b = lane;
                g_comb[b * H + j] = fmaxf(rc[b] + g_pre_c[(s * 8 + b) * H + j], 0.f);
            }
        }
        grid_barrier();

        // ---- phase C: gates + LSTM ----
        stage8k(cs, g_comb);
        __syncthreads();
        float acc4[4][8];
#pragma unroll
        for (int ga = 0; ga < 4; ga++)
#pragma unroll
            for (int b = 0; b < 8; b++) acc4[ga][b] = 0.f;
        if (own) {
            for (int kb = 0; kb < 32; kb++) {
                int kk = kb * 32 + lane;
                bool in = kk < H;
                float cv[8], hv[8];
#pragma unroll
                for (int b = 0; b < 8; b++) {
                    cv[b] = in ? cs[b * H + kk] : 0.f;
                    hv[b] = in ? xs[b * H + kk] : 0.f;
                }
#pragma unroll
                for (int ga = 0; ga < 4; ga++) {
                    float wih = in ? dec_Wih[(ga * H + j) * H + kk] : 0.f;
                    float whh = in ? dec_Whh[(ga * H + j) * H + kk] : 0.f;
#pragma unroll
                    for (int b = 0; b < 8; b++)
                        acc4[ga][b] += wih * cv[b] + whh * hv[b];
                }
            }
        }
#pragma unroll
        for (int ga = 0; ga < 4; ga++)
#pragma unroll
            for (int b = 0; b < 8; b++) acc4[ga][b] = wsum(acc4[ga][b]);
        if (own && lane < 8) {
            int b = lane;
            float gi = sigm(acc4[0][b] + g_decbias[j]);
            float gf = sigm(acc4[1][b] + g_decbias[H + j]);
            float gg = tanhf(acc4[2][b] + g_decbias[2 * H + j]);
            float go = sigm(acc4[3][b] + g_decbias[3 * H + j]);
            float cn = gf * g_c[b * H + j] + gi * gg;
            g_c[b * H + j] = cn;
            float hn = go * tanhf(cn);
            g_hbuf[(s + 1) & 1][b * H + j] = hn;
            g_Hs[s * (B * H) + b * H + j] = hn;
        }
        grid_barrier();
    }
}

// ---------------- tiny kernels ----------------
__global__ void bias_sum(const float* __restrict__ a, const float* __restrict__ b,
                         float* __restrict__ o, int n) {
    int i = blockIdx.x * blockDim.x + threadIdx.x;
    if (i < n) o[i] = a[i] + b[i];
}
__global__ void calc_v(const float* __restrict__ out_b, const float* __restrict__ emb_W,
                       float* __restrict__ v) {
    int j = blockIdx.x;
    const float* row = emb_W + (size_t)j * EMB_LD;
    float acc = 0.f;
    for (int e = threadIdx.x; e < E; e += 256) acc += out_b[e] * row[e];
    __shared__ float s[256];
    s[threadIdx.x] = acc;
    __syncthreads();
    for (int off = 128; off; off >>= 1) {
        if (threadIdx.x < off) s[threadIdx.x] += s[threadIdx.x + off];
        __syncthreads();
    }
    if (threadIdx.x == 0) v[j] = s[0];
}
__global__ void make_WA(const float* __restrict__ A1M, const float* __restrict__ attn_W,
                        float* __restrict__ WA) {
    int i = blockIdx.x * 256 + threadIdx.x;
    if (i >= T * H) return;
    int t = i / H, k = i - t * H;
    WA[i] = A1M[i] + attn_W[t * ATTN_LD + H + k];
}
__global__ void make_n1x(const float* __restrict__ n1p, const float* __restrict__ emb0,
                         const float* __restrict__ v, float* __restrict__ n1x) {
    int i = blockIdx.x * 256 + threadIdx.x;
    if (i >= S * B * H) return;
    int row = i / H, k = i - row * H;
    n1x[i] = n1p[i] + (row < 8 ? emb0[i] : v[k]);
}

// ---------------- host orchestration ----------------
template <typename Tp>
static Tp* sym(const void* symbol) {
    void* p;
    cudaGetSymbolAddress(&p, symbol);
    return (Tp*)p;
}

extern "C" void kernel_launch(void* const* d_in, const int* in_sizes, int n_in,
                              void* d_out, int out_size) {
    const float* in_input  = (const float*)d_in[0];
    const float* noise1    = (const float*)d_in[2];
    const float* noise2    = (const float*)d_in[3];
    const float* init_dec  = (const float*)d_in[4];
    const float* enc_Wih   = (const float*)d_in[5];
    const float* enc_Whh   = (const float*)d_in[6];
    const float* enc_bih   = (const float*)d_in[7];
    const float* enc_bhh   = (const float*)d_in[8];
    const float* dec_Wih   = (const float*)d_in[9];
    const float* dec_Whh   = (const float*)d_in[10];
    const float* dec_bih   = (const float*)d_in[11];
    const float* dec_bhh   = (const float*)d_in[12];
    const float* emb_W     = (const float*)d_in[13];
    const float* emb_b     = (const float*)d_in[14];
    const float* attn_W    = (const float*)d_in[15];
    const float* attn_b    = (const float*)d_in[16];
    const float* comb_W    = (const float*)d_in[17];
    const float* comb_b    = (const float*)d_in[18];
    const float* out_W     = (const float*)d_in[19];
    const float* out_b     = (const float*)d_in[20];
    float* out = (float*)d_out;

    float *pre = sym<float>(g_pre_enc), *Mm = sym<float>(g_Mmat),
          *n1p = sym<float>(g_n1pre), *n2p = sym<float>(g_n2pre),
          *Hs = sym<float>(g_Hs), *hb = sym<float>(g_hbuf), *c = sym<float>(g_c),
          *encb = sym<float>(g_encbias), *decb = sym<float>(g_decbias),
          *v = sym<float>(g_v), *kpart = sym<float>(g_kpart),
          *WA = sym<float>(g_WA), *A1M = sym<float>(g_A1M), *C1M = sym<float>(g_C1M),
          *pre_a = sym<float>(g_pre_a), *pre_c = sym<float>(g_pre_c),
          *n1x = sym<float>(g_n1x), *emb0 = sym<float>(g_emb0),
          *enc2T = sym<float>(g_enc2T), *enc_out = sym<float>(g_enc_out);
    __nv_bfloat16 *AinH = sym<__nv_bfloat16>(g_Ain_h), *AinL = sym<__nv_bfloat16>(g_Ain_l);
    __nv_bfloat16 *WihH = sym<__nv_bfloat16>(g_Wih_h), *WihL = sym<__nv_bfloat16>(g_Wih_l);
    __nv_bfloat16 *eWEH = sym<__nv_bfloat16>(g_eWE_h), *eWEL = sym<__nv_bfloat16>(g_eWE_l);
    __nv_bfloat16 *oWtH = sym<__nv_bfloat16>(g_oWt_h), *oWtL = sym<__nv_bfloat16>(g_oWt_l);
    __nv_bfloat16 *n1AH = sym<__nv_bfloat16>(g_n1A_h), *n1AL = sym<__nv_bfloat16>(g_n1A_l);
    __nv_bfloat16 *eWNH = sym<__nv_bfloat16>(g_eWN_h), *eWNL = sym<__nv_bfloat16>(g_eWN_l);
    __nv_bfloat16 *n2AH = sym<__nv_bfloat16>(g_n2A_h), *n2AL = sym<__nv_bfloat16>(g_n2A_l);
    __nv_bfloat16 *aW2H = sym<__nv_bfloat16>(g_aW2_h), *aW2L = sym<__nv_bfloat16>(g_aW2_l);
    __nv_bfloat16 *oWH = sym<__nv_bfloat16>(g_oW_h), *oWL = sym<__nv_bfloat16>(g_oW_l);
    __nv_bfloat16 *HsAH = sym<__nv_bfloat16>(g_HsA_h), *HsAL = sym<__nv_bfloat16>(g_HsA_l);
    __nv_bfloat16 *Wa1H = sym<__nv_bfloat16>(g_Wa1_h), *Wa1L = sym<__nv_bfloat16>(g_Wa1_l);
    __nv_bfloat16 *Wc1H = sym<__nv_bfloat16>(g_Wc1_h), *Wc1L = sym<__nv_bfloat16>(g_Wc1_l);
    __nv_bfloat16 *Wc2H = sym<__nv_bfloat16>(g_Wc2_h), *Wc2L = sym<__nv_bfloat16>(g_Wc2_l);
    __nv_bfloat16 *MtH = sym<__nv_bfloat16>(g_Mt_h), *MtL = sym<__nv_bfloat16>(g_Mt_l);
    __nv_bfloat16 *idH = sym<__nv_bfloat16>(g_id_h), *idL = sym<__nv_bfloat16>(g_id_l);
    __nv_bfloat16 *n1xH = sym<__nv_bfloat16>(g_n1x_h), *n1xL = sym<__nv_bfloat16>(g_n1x_l);
    __nv_bfloat16 *eoH = sym<__nv_bfloat16>(g_eo_h), *eoL = sym<__nv_bfloat16>(g_eo_l);

    cudaFuncSetAttribute(gemm_tc, cudaFuncAttributeMaxDynamicSharedMemorySize, GEMM_SMEM);
    cudaFuncSetAttribute(dec_kernel, cudaFuncAttributeMaxDynamicSharedMemorySize, DEC_SMEM);

    cudaMemsetAsync(hb, 0, B * H * sizeof(float));
    cudaMemsetAsync(c, 0, B * H * sizeof(float));
    bias_sum<<<(G4 + 255) / 256, 256>>>(enc_bih, enc_bhh, encb, G4);
    bias_sum<<<(G4 + 255) / 256, 256>>>(dec_bih, dec_bhh, decb, G4);
    calc_v<<<H, 256>>>(out_b, emb_W, v);

    // ---- conversions ----
    const int GYE = (KP_E + 2047) / 2048, GYH = 1, GYNZ = (KP_NZ + 2047) / 2048;
    conv8<true><<<dim3(1024, GYE), 256>>>(in_input, E, T, AinH, AinL, 1024, E, KP_E);
    conv8<false><<<dim3(4096, GYE), 256>>>(enc_Wih, E, 0, WihH, WihL, G4, E, KP_E);
    conv8<false><<<dim3(1024, GYE), 256>>>(emb_W, EMB_LD, 0, eWEH, eWEL, H, E, KP_E);
    conv_trans<<<dim3((KP_E + 31) / 32, 32), dim3(32, 8)>>>(out_W, H, oWtH, oWtL, E, H, KP_E, 1024);
    conv8<false><<<dim3(512, GYNZ), 256>>>(noise1, NZ, 0, n1AH, n1AL, 512, NZ, KP_NZ);
    conv8<false><<<dim3(1024, GYNZ), 256>>>(emb_W + E, EMB_LD, 0, eWNH, eWNL, H, NZ, KP_NZ);
    conv8<false><<<dim3(512, GYH), 256>>>(noise2, H, 0, n2AH, n2AL, 512, H, KP_H);
    conv8<false><<<dim3(256, GYH), 256>>>(attn_W + 2 * H, ATTN_LD, 0, aW2H, aW2L, T, H, KP_H);
    conv8<false><<<dim3(30720, GYH), 256>>>(out_W, H, 0, oWH, oWL, E, H, KP_H);
    conv8<false><<<dim3(256, GYH), 256>>>(attn_W, ATTN_LD, 0, Wa1H, Wa1L, T, H, KP_H);
    conv8<false><<<dim3(1024, GYH), 256>>>(comb_W, COMB_LD, 0, Wc1H, Wc1L, H, H, KP_H);
    conv8<false><<<dim3(1024, GYH), 256>>>(comb_W + H, COMB_LD, 0, Wc2H, Wc2L, H, H, KP_H);
    // FIX (R10 failure root cause): init_dec is plain [B,E] row-major — must NOT
    // use the swizzled row map (swizT=0 collapsed all 8 batch rows onto row 0).
    conv8<false><<<dim3(128, GYE), 256>>>(init_dec, E, 0, idH, idL, 8, E, KP_E);

    constexpr int NCH_E = KP_E / 32, NCH_NZ = KP_NZ / 32, NCH_H = KP_H / 32;

    // ---- big GEMMs ----
    gemm_tc<<<dim3(16, 8, 1), 256, GEMM_SMEM>>>(AinH, AinL, WihH, WihL, KP_E, encb,
                                                pre, G4, T * B, G4, NCH_E, 0);
    {   // Mmat = emb_W_E @ out_W
        constexpr int SL = 4, CPS = (NCH_E + SL - 1) / SL;
        gemm_tc<<<dim3(4, 8, SL), 256, GEMM_SMEM>>>(eWEH, eWEL, oWtH, oWtL, KP_E,
                                                    nullptr, kpart, H, H, H, CPS, 1);
        reduce_k<<<(H * H + 255) / 256, 256>>>(kpart, nullptr, nullptr, Mm, H, H, H, SL, 0);
    }
    conv_trans<<<dim3((KP_H + 31) / 32, 32), dim3(32, 8)>>>(Mm, H, MtH, MtL, H, H, KP_H, 1024);
    {   // A1M = Wa1 @ M
        constexpr int SL = 8, CPS = (NCH_H + SL - 1) / SL;
        gemm_tc<<<dim3(4, 1, SL), 256, GEMM_SMEM>>>(Wa1H, Wa1L, MtH, MtL, KP_H,
                                                    nullptr, kpart, H, T, H, CPS, 1);
        reduce_k<<<(T * H + 255) / 256, 256>>>(kpart, nullptr, nullptr, A1M, T, H, H, SL, 0);
        make_WA<<<(T * H + 255) / 256, 256>>>(A1M, attn_W, WA);
    }
    {   // C1M = Wc1 @ M
        constexpr int SL = 4, CPS = (NCH_H + SL - 1) / SL;
        gemm_tc<<<dim3(4, 8, SL), 256, GEMM_SMEM>>>(Wc1H, Wc1L, MtH, MtL, KP_H,
                                                    nullptr, kpart, H, H, H, CPS, 1);
        reduce_k<<<(H * H + 255) / 256, 256>>>(kpart, nullptr, nullptr, C1M, H, H, H, SL, 0);
    }
    {   // n1pre = noise1 @ emb_W_N^T + emb_b
        constexpr int SL = 8, CPS = (NCH_NZ + SL - 1) / SL;
        gemm_tc<<<dim3(4, 4, SL), 256, GEMM_SMEM>>>(n1AH, n1AL, eWNH, eWNL, KP_NZ,
                                                    nullptr, kpart, H, S * B, H, CPS, 1);
        reduce_k<<<(S * B * H + 255) / 256, 256>>>(kpart, emb_b, nullptr, n1p, S * B, H, H, SL, 0);
    }
    {   // emb0 = init_dec @ emb_W_E^T
        constexpr int SL = 8, CPS = (NCH_E + SL - 1) / SL;
        gemm_tc<<<dim3(4, 1, SL), 256, GEMM_SMEM>>>(idH, idL, eWEH, eWEL, KP_E,
                                                    nullptr, kpart, H, 8, H, CPS, 1);
        reduce_k<<<(8 * H + 255) / 256, 256>>>(kpart, nullptr, nullptr, emb0, 8, H, H, SL, 0);
    }
    make_n1x<<<(S * B * H + 255) / 256, 256>>>(n1p, emb0, v, n1x);
    conv8<false><<<dim3(512, GYH), 256>>>(n1x, H, 0, n1xH, n1xL, S * B, H, KP_H);
    {   // n2pre = noise2 @ Wa3^T + attn_b
        constexpr int SL = 8, CPS = (NCH_H + SL - 1) / SL;
        gemm_tc<<<dim3(1, 4, SL), 256, GEMM_SMEM>>>(n2AH, n2AL, aW2H, aW2L, KP_H,
                                                    nullptr, kpart, T, S * B, T, CPS, 1);
        reduce_k<<<(S * B * T + 255) / 256, 256>>>(kpart, attn_b, nullptr, n2p, S * B, T, T, SL, 0);
    }
    {   // pre_a = n1x @ Wa1^T + n2pre
        constexpr int SL = 8, CPS = (NCH_H + SL - 1) / SL;
        gemm_tc<<<dim3(1, 4, SL), 256, GEMM_SMEM>>>(n1xH, n1xL, Wa1H, Wa1L, KP_H,
                                                    nullptr, kpart, T, S * B, T, CPS, 1);
        reduce_k<<<(S * B * T + 255) / 256, 256>>>(kpart, nullptr, n2p, pre_a, S * B, T, T, SL, 0);
    }
    {   // pre_c = n1x @ Wc1^T + comb_b
        constexpr int SL = 8, CPS = (NCH_H + SL - 1) / SL;
        gemm_tc<<<dim3(4, 4, SL), 256, GEMM_SMEM>>>(n1xH, n1xL, Wc1H, Wc1L, KP_H,
                                                    nullptr, kpart, H, S * B, H, CPS, 1);
        reduce_k<<<(S * B * H + 255) / 256, 256>>>(kpart, comb_b, nullptr, pre_c, S * B, H, H, SL, 0);
    }

    // ---- encoder ----
    enc_kernel<<<NCTA, 256>>>(enc_Whh);

    // ---- enc2T = (enc_out @ Wc2^T) in [b][j][t] layout ----
    conv8<false><<<dim3(1024, GYH), 256>>>(enc_out, H, 0, eoH, eoL, T * B, H, KP_H);
    {
        constexpr int SL = 4, CPS = (NCH_H + SL - 1) / SL;
        gemm_tc<<<dim3(4, 8, SL), 256, GEMM_SMEM>>>(eoH, eoL, Wc2H, Wc2L, KP_H,
                                                    nullptr, kpart, H, T * B, H, CPS, 1);
        reduce_k<<<(T * B * H + 255) / 256, 256>>>(kpart, nullptr, nullptr, enc2T,
                                                   T * B, H, H, SL, 1);
    }

    // ---- decoder ----
    dec_kernel<<<NCTA, 256, DEC_SMEM>>>(dec_Wih, dec_Whh, attn_W);

    // ---- final: out = Hs @ out_W^T + out_b ----
    conv8<false><<<dim3(512, GYH), 256>>>(Hs, H, 0, HsAH, HsAL, S * B, H, KP_H);
    gemm_tc<<<dim3(120, 4, 1), 256, GEMM_SMEM>>>(HsAH, HsAL, oWH, oWL, KP_H, out_b,
                                                 out, E, S * B, E, NCH_H, 0);
}

// round 12
// speedup vs baseline: 4.5461x; 1.1553x over previous
#include <cuda_runtime.h>
#include <cuda_bf16.h>
#include <math.h>

// Problem dims (fixed by setup_inputs)
constexpr int B = 8;
constexpr int T = 128;
constexpr int E = 30522;
constexpr int H = 1000;
constexpr int S = 64;
constexpr int NZ = 10000;
constexpr int G4 = 4 * H;          // 4000
constexpr int EMB_LD = E + NZ;     // 40522
constexpr int ATTN_LD = 3 * H;     // 3000
constexpr int COMB_LD = 2 * H;     // 2000
constexpr int NCTA = 148;

constexpr int KP_E  = 30528;       // E padded to 64
constexpr int KP_NZ = 10048;       // NZ padded to 64
constexpr int KP_H  = 1024;        // H padded to 64

// ---------------- fp32 scratch ----------------
__device__ float g_pre_enc[T * B * G4];
__device__ float g_enc_out[T * B * H];
__device__ float g_Mmat[H * H];
__device__ float g_n1pre[S * B * H];
__device__ float g_n2pre[S * B * T];
__device__ float g_Hs[S * B * H];
__device__ float g_hbuf[2][B * H];
__device__ float g_c[B * H];
__device__ float g_attn[B * T];
__device__ float g_comb[B * H];
__device__ float g_encbias[G4];
__device__ float g_decbias[G4];
__device__ float g_v[H];
__device__ float g_kpart[33000000];         // split-K partials (131 MB)
__device__ float g_WA[T * H];               // Wa1@M + Wa2
__device__ float g_A1M[T * H];
__device__ float g_C1M[H * H];
__device__ float g_pre_a[S * B * T];
__device__ float g_pre_c[S * B * H];
__device__ float g_n1x[S * B * H];
__device__ float g_emb0[B * H];
__device__ float g_enc2T[B * H * T];        // [b][j][t]
__device__ unsigned g_bar_arrive;
__device__ unsigned g_bar_gen;

// ---------------- bf16 hi/lo operand buffers (padded) ----------------
__device__ __nv_bfloat16 g_Ain_h[1024 * KP_E],  g_Ain_l[1024 * KP_E];
__device__ __nv_bfloat16 g_Wih_h[4096 * KP_E],  g_Wih_l[4096 * KP_E];
__device__ __nv_bfloat16 g_eWE_h[1024 * KP_E],  g_eWE_l[1024 * KP_E];
__device__ __nv_bfloat16 g_oWt_h[1024 * KP_E],  g_oWt_l[1024 * KP_E];
__device__ __nv_bfloat16 g_n1A_h[512 * KP_NZ],  g_n1A_l[512 * KP_NZ];
__device__ __nv_bfloat16 g_eWN_h[1024 * KP_NZ], g_eWN_l[1024 * KP_NZ];
__device__ __nv_bfloat16 g_n2A_h[512 * KP_H],   g_n2A_l[512 * KP_H];
__device__ __nv_bfloat16 g_aW2_h[256 * KP_H],   g_aW2_l[256 * KP_H];
__device__ __nv_bfloat16 g_oW_h[30720 * KP_H],  g_oW_l[30720 * KP_H];
__device__ __nv_bfloat16 g_HsA_h[512 * KP_H],   g_HsA_l[512 * KP_H];
__device__ __nv_bfloat16 g_Wa1_h[256 * KP_H],   g_Wa1_l[256 * KP_H];
__device__ __nv_bfloat16 g_Wc1_h[1024 * KP_H],  g_Wc1_l[1024 * KP_H];
__device__ __nv_bfloat16 g_Wc2_h[1024 * KP_H],  g_Wc2_l[1024 * KP_H];
__device__ __nv_bfloat16 g_Mt_h[1024 * KP_H],   g_Mt_l[1024 * KP_H];
__device__ __nv_bfloat16 g_id_h[128 * KP_E],    g_id_l[128 * KP_E];
__device__ __nv_bfloat16 g_n1x_h[512 * KP_H],   g_n1x_l[512 * KP_H];
__device__ __nv_bfloat16 g_eo_h[1024 * KP_H],   g_eo_l[1024 * KP_H];

// ---------------- helpers ----------------
__device__ __forceinline__ unsigned s2u(const void* p) {
    unsigned a;
    asm("{ .reg .u64 t; cvta.to.shared.u64 t, %1; cvt.u32.u64 %0, t; }"
        : "=r"(a) : "l"(p));
    return a;
}
__device__ __forceinline__ void cp16(unsigned dst, const void* src) {
    asm volatile("cp.async.cg.shared.global [%0], [%1], 16;" :: "r"(dst), "l"(src)
                 : "memory");
}
__device__ __forceinline__ void cp_commit() {
    asm volatile("cp.async.commit_group;" ::: "memory");
}
template <int N>
__device__ __forceinline__ void cp_wait() {
    asm volatile("cp.async.wait_group %0;" :: "n"(N) : "memory");
}
__device__ __forceinline__ void mma_bf16(float* c, const unsigned* a, const unsigned* b) {
    asm volatile(
        "mma.sync.aligned.m16n8k16.row.col.f32.bf16.bf16.f32 "
        "{%0,%1,%2,%3}, {%4,%5,%6,%7}, {%8,%9}, {%0,%1,%2,%3};"
        : "+f"(c[0]), "+f"(c[1]), "+f"(c[2]), "+f"(c[3])
        : "r"(a[0]), "r"(a[1]), "r"(a[2]), "r"(a[3]), "r"(b[0]), "r"(b[1]));
}

// ---------------- vectorized converter: 8 cols/thread ----------------
template <bool SWIZ>
__global__ void conv8(const float* __restrict__ src, int ldS, int swizT,
                      __nv_bfloat16* __restrict__ dh,
                      __nv_bfloat16* __restrict__ dl,
                      int Mr, int Kr, int Kpad) {
    int row = blockIdx.x;
    int c0 = (blockIdx.y * 256 + threadIdx.x) * 8;
    if (c0 >= Kpad) return;
    const float* sp = nullptr;
    if (row < Mr) {
        int r = SWIZ ? ((row & 7) * swizT + (row >> 3)) : row;
        sp = src + (size_t)r * ldS;
    }
    float x[8];
#pragma unroll
    for (int i = 0; i < 8; i++) {
        int col = c0 + i;
        x[i] = (sp && col < Kr) ? sp[col] : 0.f;
    }
    unsigned hw[4], lw[4];
#pragma unroll
    for (int p = 0; p < 4; p++) {
        __nv_bfloat16 h0 = __float2bfloat16_rn(x[2 * p]);
        __nv_bfloat16 h1 = __float2bfloat16_rn(x[2 * p + 1]);
        __nv_bfloat16 l0 = __float2bfloat16_rn(x[2 * p] - __bfloat162float(h0));
        __nv_bfloat16 l1 = __float2bfloat16_rn(x[2 * p + 1] - __bfloat162float(h1));
        hw[p] = (unsigned)*(unsigned short*)&h0 | ((unsigned)*(unsigned short*)&h1 << 16);
        lw[p] = (unsigned)*(unsigned short*)&l0 | ((unsigned)*(unsigned short*)&l1 << 16);
    }
    *(uint4*)(dh + (size_t)row * Kpad + c0) = make_uint4(hw[0], hw[1], hw[2], hw[3]);
    *(uint4*)(dl + (size_t)row * Kpad + c0) = make_uint4(lw[0], lw[1], lw[2], lw[3]);
}

// dst[n][k] = src[k][n]
__global__ void conv_trans(const float* __restrict__ src, int ldS,
                           __nv_bfloat16* __restrict__ dh,
                           __nv_bfloat16* __restrict__ dl,
                           int Kr, int Nr, int Kpad, int Npad) {
    __shared__ float tile[32][33];
    int kb = blockIdx.x * 32, nb = blockIdx.y * 32;
    int tx = threadIdx.x, ty = threadIdx.y;   // 32 x 8
    for (int i = ty; i < 32; i += 8) {
        int k = kb + i, n = nb + tx;
        tile[i][tx] = (k < Kr && n < Nr) ? src[(size_t)k * ldS + n] : 0.f;
    }
    __syncthreads();
    for (int i = ty; i < 32; i += 8) {
        int n = nb + i, k = kb + tx;
        if (n < Npad && k < Kpad) {
            float x = tile[tx][i];
            __nv_bfloat16 h = __float2bfloat16_rn(x);
            dh[(size_t)n * Kpad + k] = h;
            dl[(size_t)n * Kpad + k] = __float2bfloat16_rn(x - __bfloat162float(h));
        }
    }
}

// ---------------- mma.sync GEMM, bf16 hi/lo, 3-stage cp.async, split-K ------
constexpr int ST_W = 20 * (128 + 128 + 256 + 256);   // 15360 words
constexpr int ST_BYTES = ST_W * 4;
constexpr int GEMM_SMEM = 3 * ST_BYTES;

__global__ void __launch_bounds__(256, 1)
gemm_tc(const __nv_bfloat16* __restrict__ Ah, const __nv_bfloat16* __restrict__ Al,
        const __nv_bfloat16* __restrict__ Bh, const __nv_bfloat16* __restrict__ Bl,
        int Kpad, const float* __restrict__ bias,
        float* __restrict__ C, int ldC, int M, int N, int cps, int partial) {
    extern __shared__ unsigned sm[];
    const unsigned sbase = s2u(sm);
    const int tid = threadIdx.x;
    const int wid = tid >> 5, lane = tid & 31;
    const int g = lane >> 2, tq = lane & 3;
    const int wm = wid & 1, wn = wid >> 1;
    const int m0 = blockIdx.y * 128, n0 = blockIdx.x * 256;
    const int nch = Kpad / 32;
    const int z = blockIdx.z;
    const int c0 = z * cps;
    const int c1 = min(nch, c0 + cps);

    float acc[4][8][4];
#pragma unroll
    for (int i = 0; i < 4; i++)
#pragma unroll
        for (int j = 0; j < 8; j++)
#pragma unroll
            for (int q = 0; q < 4; q++) acc[i][j][q] = 0.f;

    auto load_stage = [&](int st, int ci) {
        unsigned sb = sbase + st * ST_BYTES;
        int k0 = ci * 32;
#pragma unroll
        for (int q = 0; q < 12; q++) {
            int it = tid + q * 256;
            const __nv_bfloat16* gp;
            unsigned dw;
            if (it < 1024) {
                int idx = it & 511, r = idx >> 2, c = idx & 3;
                gp = (it < 512 ? Ah : Al) + (size_t)(m0 + r) * Kpad + k0 + c * 8;
                dw = (it < 512 ? 0u : 2560u) + r * 20 + c * 4;
            } else {
                int idx = (it - 1024) & 1023, r = idx >> 2, c = idx & 3;
                gp = (it < 2048 ? Bh : Bl) + (size_t)(n0 + r) * Kpad + k0 + c * 8;
                dw = (it < 2048 ? 5120u : 10240u) + r * 20 + c * 4;
            }
            cp16(sb + dw * 4, gp);
        }
        cp_commit();
    };

    if (c0 < c1)     load_stage(0, c0);
    if (c0 + 1 < c1) load_stage(1, c0 + 1);

    for (int ci = c0; ci < c1; ci++) {
        int st = (ci - c0) % 3;
        if (ci == c1 - 1) cp_wait<0>(); else cp_wait<1>();
        __syncthreads();
        if (ci + 2 < c1) load_stage((ci - c0 + 2) % 3, ci + 2);

        const unsigned b0 = st * ST_W;
#pragma unroll
        for (int ks = 0; ks < 2; ks++) {
            int ws = ks * 8 + tq;
            unsigned ahf[4][4], alf[4][4];
#pragma unroll
            for (int i = 0; i < 4; i++) {
                int am = wm * 64 + i * 16 + g;
                ahf[i][0] = sm[b0 + am * 20 + ws];
                ahf[i][1] = sm[b0 + (am + 8) * 20 + ws];
                ahf[i][2] = sm[b0 + am * 20 + ws + 4];
                ahf[i][3] = sm[b0 + (am + 8) * 20 + ws + 4];
                alf[i][0] = sm[b0 + 2560 + am * 20 + ws];
                alf[i][1] = sm[b0 + 2560 + (am + 8) * 20 + ws];
                alf[i][2] = sm[b0 + 2560 + am * 20 + ws + 4];
                alf[i][3] = sm[b0 + 2560 + (am + 8) * 20 + ws + 4];
            }
#pragma unroll
            for (int jh = 0; jh < 2; jh++) {
                unsigned bhf[4][2], blf[4][2];
#pragma unroll
                for (int j = 0; j < 4; j++) {
                    int bn = wn * 64 + jh * 32 + j * 8 + g;
                    bhf[j][0] = sm[b0 + 5120 + bn * 20 + ws];
                    bhf[j][1] = sm[b0 + 5120 + bn * 20 + ws + 4];
                    blf[j][0] = sm[b0 + 10240 + bn * 20 + ws];
                    blf[j][1] = sm[b0 + 10240 + bn * 20 + ws + 4];
                }
#pragma unroll
                for (int i = 0; i < 4; i++)
#pragma unroll
                    for (int j = 0; j < 4; j++)
                        mma_bf16(acc[i][jh * 4 + j], ahf[i], bhf[j]);
#pragma unroll
                for (int i = 0; i < 4; i++)
#pragma unroll
                    for (int j = 0; j < 4; j++)
                        mma_bf16(acc[i][jh * 4 + j], alf[i], bhf[j]);
#pragma unroll
                for (int i = 0; i < 4; i++)
#pragma unroll
                    for (int j = 0; j < 4; j++)
                        mma_bf16(acc[i][jh * 4 + j], ahf[i], blf[j]);
            }
        }
        __syncthreads();
    }

    float* Cb = partial ? (C + (size_t)z * M * N) : C;
    const int ld = partial ? N : ldC;
#pragma unroll
    for (int i = 0; i < 4; i++) {
        int rr0 = m0 + wm * 64 + i * 16 + g;
#pragma unroll
        for (int j = 0; j < 8; j++) {
            int cc = n0 + wn * 64 + j * 8 + tq * 2;
#pragma unroll
            for (int q = 0; q < 4; q++) {
                int rr = rr0 + (q >> 1) * 8;
                int cn = cc + (q & 1);
                if (rr < M && cn < N) {
                    float v = acc[i][j][q];
                    if (!partial && bias) v += bias[cn];
                    Cb[(size_t)rr * ld + cn] = v;
                }
            }
        }
    }
}

// deterministic split-K reduce. emode 0: out[m*ldC+n]; 1: enc2T layout.
__global__ void reduce_k(const float* __restrict__ part,
                         const float* __restrict__ bias,
                         const float* __restrict__ add,
                         float* __restrict__ out,
                         int M, int N, int ldC, int slices, int emode) {
    size_t idx = (size_t)blockIdx.x * 256 + threadIdx.x;
    if (idx >= (size_t)M * N) return;
    int m = (int)(idx / N), n = (int)(idx - (size_t)m * N);
    float v = bias ? bias[n] : 0.f;
    if (add) v += add[idx];
    for (int z = 0; z < slices; z++) v += part[(size_t)z * M * N + idx];
    if (emode == 1) out[((size_t)(m & 7) * H + n) * T + (m >> 3)] = v;
    else out[(size_t)m * ldC + n] = v;
}

// ---------------- persistent kernels ----------------
__device__ __forceinline__ void grid_barrier() {
    __threadfence();
    __syncthreads();
    if (threadIdx.x == 0) {
        unsigned gen = atomicAdd(&g_bar_gen, 0u);
        if (atomicAdd(&g_bar_arrive, 1u) == gridDim.x - 1) {
            g_bar_arrive = 0;
            __threadfence();
            atomicAdd(&g_bar_gen, 1u);
        } else {
            volatile unsigned* vg = &g_bar_gen;
            while (*vg == gen) { }
        }
    }
    __syncthreads();
}
__device__ __forceinline__ float wsum(float v) {
#pragma unroll
    for (int off = 16; off; off >>= 1) v += __shfl_xor_sync(0xFFFFFFFFu, v, off);
    return v;
}
__device__ __forceinline__ float sigm(float x) { return 1.f / (1.f + expf(-x)); }
__device__ __forceinline__ void stage8k(float* xs, const float* src) {
    const float4* s4 = reinterpret_cast<const float4*>(src);
    float4* d4 = reinterpret_cast<float4*>(xs);
    for (int i = threadIdx.x; i < B * H / 4; i += 256) d4[i] = s4[i];
}
__device__ __forceinline__ float dot4(float4 a, float4 b) {
    return a.x * b.x + a.y * b.y + a.z * b.z + a.w * b.w;
}

__global__ void __launch_bounds__(256, 1)
enc_kernel(const float* __restrict__ enc_Whh) {
    __shared__ __align__(16) float xs[B][H];
    const int ct = blockIdx.x, tid = threadIdx.x;
    const int w = tid >> 5, lane = tid & 31;
    const int j = ct + NCTA * w;
    const bool own = (w < 7) && (j < H);

    for (int t = 0; t < T; t++) {
        stage8k(xs[0], g_hbuf[t & 1]);
        __syncthreads();
        float acc[4][8];
#pragma unroll
        for (int ga = 0; ga < 4; ga++)
#pragma unroll
            for (int b = 0; b < 8; b++) acc[ga][b] = 0.f;
        if (own) {
#pragma unroll
            for (int kb = 0; kb < 8; kb++) {
                int kk = kb * 128 + lane * 4;
                if (kk < H) {
                    float4 xv[8];
#pragma unroll
                    for (int b = 0; b < 8; b++)
                        xv[b] = *reinterpret_cast<const float4*>(&xs[b][kk]);
#pragma unroll
                    for (int ga = 0; ga < 4; ga++) {
                        float4 wv = *reinterpret_cast<const float4*>(
                            &enc_Whh[(size_t)(ga * H + j) * H + kk]);
#pragma unroll
                        for (int b = 0; b < 8; b++) acc[ga][b] += dot4(wv, xv[b]);
                    }
                }
            }
        }
#pragma unroll
        for (int ga = 0; ga < 4; ga++)
#pragma unroll
            for (int b = 0; b < 8; b++) acc[ga][b] = wsum(acc[ga][b]);
        if (own && lane < 8) {
            int b = lane;
            const float* pre = g_pre_enc + (t * 8 + b) * G4;
            float gi = sigm(acc[0][b] + pre[j]);
            float gf = sigm(acc[1][b] + pre[H + j]);
            float gg = tanhf(acc[2][b] + pre[2 * H + j]);
            float go = sigm(acc[3][b] + pre[3 * H + j]);
            float cn = gf * g_c[b * H + j] + gi * gg;
            g_c[b * H + j] = cn;
            float hn = go * tanhf(cn);
            g_hbuf[(t + 1) & 1][b * H + j] = hn;
            g_enc_out[t * (B * H) + b * H + j] = hn;
        }
        grid_barrier();
    }
}

// decoder: 3 phases/step. dynamic smem: xs(h) 8000f | cs(comb) 8000f | aw 1024f
constexpr int DEC_SMEM = (8000 + 8000 + 1024) * 4;

__global__ void __launch_bounds__(256, 1)
dec_kernel(const float* __restrict__ dec_Wih,
           const float* __restrict__ dec_Whh,
           const float* __restrict__ attn_W) {
    extern __shared__ __align__(16) float dsm[];
    float* xs = dsm;             // [8][1000] h
    float* cs = dsm + 8000;      // [8][1000] comb
    float* aw = dsm + 16000;     // [8][128]

    const int ct = blockIdx.x, tid = threadIdx.x;
    const int w = tid >> 5, lane = tid & 31;
    const int j = ct + NCTA * w;
    const bool own = (w < 7) && (j < H);

    for (int s = 0; s < S; s++) {
        stage8k(xs, g_hbuf[s & 1]);
        __syncthreads();

        // ---- phase A: rc = C1M@h partials; attn logits ----
        float rc[8];
#pragma unroll
        for (int b = 0; b < 8; b++) rc[b] = 0.f;
        if (s > 0 && own) {
#pragma unroll
            for (int kb = 0; kb < 8; kb++) {
                int kk = kb * 128 + lane * 4;
                if (kk < H) {
                    float4 cw = *reinterpret_cast<const float4*>(&g_C1M[(size_t)j * H + kk]);
#pragma unroll
                    for (int b = 0; b < 8; b++)
                        rc[b] += dot4(cw, *reinterpret_cast<const float4*>(&xs[b * H + kk]));
                }
            }
        }
        if (ct < T) {
            int tp = ct, b = w;
            float acc = 0.f;
            if (s == 0) {
#pragma unroll
                for (int kb = 0; kb < 8; kb++) {
                    int kk = kb * 128 + lane * 4;
                    if (kk < H) {
                        float4 wv = *reinterpret_cast<const float4*>(
                            &attn_W[(size_t)tp * ATTN_LD + H + kk]);
                        acc += dot4(wv, *reinterpret_cast<const float4*>(&xs[b * H + kk]));
                    }
                }
            } else {
#pragma unroll
                for (int kb = 0; kb < 8; kb++) {
                    int kk = kb * 128 + lane * 4;
                    if (kk < H) {
                        float4 wv = *reinterpret_cast<const float4*>(&g_WA[(size_t)tp * H + kk]);
                        acc += dot4(wv, *reinterpret_cast<const float4*>(&xs[b * H + kk]));
                    }
                }
            }
            acc = wsum(acc);
            if (lane == 0)
                g_attn[b * T + tp] = acc + g_pre_a[(s * 8 + b) * T + tp];
        }
        grid_barrier();

        // ---- phase B: local softmax + comb ----
        {
            int b = w;
            float vx[4];
#pragma unroll
            for (int q = 0; q < 4; q++) vx[q] = g_attn[b * T + lane + 32 * q];
            float m = fmaxf(fmaxf(vx[0], vx[1]), fmaxf(vx[2], vx[3]));
#pragma unroll
            for (int off = 16; off; off >>= 1)
                m = fmaxf(m, __shfl_xor_sync(0xFFFFFFFFu, m, off));
            float e[4], ssum = 0.f;
#pragma unroll
            for (int q = 0; q < 4; q++) { e[q] = expf(vx[q] - m); ssum += e[q]; }
            ssum = wsum(ssum);
            float inv = 1.f / ssum;
#pragma unroll
            for (int q = 0; q < 4; q++) aw[b * T + lane + 32 * q] = e[q] * inv;
        }
        __syncthreads();
        if (own) {
#pragma unroll
            for (int b = 0; b < 8; b++) {
                const float* e2 = g_enc2T + ((size_t)b * H + j) * T;
                float a = 0.f;
#pragma unroll
                for (int it = 0; it < 4; it++)
                    a += aw[b * T + lane + 32 * it] * e2[lane + 32 * it];
                rc[b] += a;
            }
#pragma unroll
            for (int b = 0; b < 8; b++) rc[b] = wsum(rc[b]);
            if (lane < 8) {
                int b = lane;
                g_comb[b * H + j] = fmaxf(rc[b] + g_pre_c[(s * 8 + b) * H + j], 0.f);
            }
        }
        grid_barrier();

        // ---- phase C: gates + LSTM ----
        stage8k(cs, g_comb);
        __syncthreads();
        float acc4[4][8];
#pragma unroll
        for (int ga = 0; ga < 4; ga++)
#pragma unroll
            for (int b = 0; b < 8; b++) acc4[ga][b] = 0.f;
        if (own) {
#pragma unroll
            for (int kb = 0; kb < 8; kb++) {
                int kk = kb * 128 + lane * 4;
                if (kk < H) {
                    float4 cv[8], hv[8];
#pragma unroll
                    for (int b = 0; b < 8; b++) {
                        cv[b] = *reinterpret_cast<const float4*>(&cs[b * H + kk]);
                        hv[b] = *reinterpret_cast<const float4*>(&xs[b * H + kk]);
                    }
#pragma unroll
                    for (int ga = 0; ga < 4; ga++) {
                        float4 wih = *reinterpret_cast<const float4*>(
                            &dec_Wih[(size_t)(ga * H + j) * H + kk]);
                        float4 whh = *reinterpret_cast<const float4*>(
                            &dec_Whh[(size_t)(ga * H + j) * H + kk]);
#pragma unroll
                        for (int b = 0; b < 8; b++)
                            acc4[ga][b] += dot4(wih, cv[b]) + dot4(whh, hv[b]);
                    }
                }
            }
        }
#pragma unroll
        for (int ga = 0; ga < 4; ga++)
#pragma unroll
            for (int b = 0; b < 8; b++) acc4[ga][b] = wsum(acc4[ga][b]);
        if (own && lane < 8) {
            int b = lane;
            float gi = sigm(acc4[0][b] + g_decbias[j]);
            float gf = sigm(acc4[1][b] + g_decbias[H + j]);
            float gg = tanhf(acc4[2][b] + g_decbias[2 * H + j]);
            float go = sigm(acc4[3][b] + g_decbias[3 * H + j]);
            float cn = gf * g_c[b * H + j] + gi * gg;
            g_c[b * H + j] = cn;
            float hn = go * tanhf(cn);
            g_hbuf[(s + 1) & 1][b * H + j] = hn;
            g_Hs[s * (B * H) + b * H + j] = hn;
        }
        grid_barrier();
    }
}

// ---------------- tiny kernels ----------------
__global__ void bias_sum(const float* __restrict__ a, const float* __restrict__ b,
                         float* __restrict__ o, int n) {
    int i = blockIdx.x * blockDim.x + threadIdx.x;
    if (i < n) o[i] = a[i] + b[i];
}
__global__ void calc_v(const float* __restrict__ out_b, const float* __restrict__ emb_W,
                       float* __restrict__ v) {
    int j = blockIdx.x;
    const float* row = emb_W + (size_t)j * EMB_LD;
    float acc = 0.f;
    for (int e = threadIdx.x; e < E; e += 256) acc += out_b[e] * row[e];
    __shared__ float s[256];
    s[threadIdx.x] = acc;
    __syncthreads();
    for (int off = 128; off; off >>= 1) {
        if (threadIdx.x < off) s[threadIdx.x] += s[threadIdx.x + off];
        __syncthreads();
    }
    if (threadIdx.x == 0) v[j] = s[0];
}
__global__ void make_WA(const float* __restrict__ A1M, const float* __restrict__ attn_W,
                        float* __restrict__ WA) {
    int i = blockIdx.x * 256 + threadIdx.x;
    if (i >= T * H) return;
    int t = i / H, k = i - t * H;
    WA[i] = A1M[i] + attn_W[t * ATTN_LD + H + k];
}
__global__ void make_n1x(const float* __restrict__ n1p, const float* __restrict__ emb0,
                         const float* __restrict__ v, float* __restrict__ n1x) {
    int i = blockIdx.x * 256 + threadIdx.x;
    if (i >= S * B * H) return;
    int row = i / H, k = i - row * H;
    n1x[i] = n1p[i] + (row < 8 ? emb0[i] : v[k]);
}

// ---------------- host orchestration ----------------
template <typename Tp>
static Tp* sym(const void* symbol) {
    void* p;
    cudaGetSymbolAddress(&p, symbol);
    return (Tp*)p;
}

extern "C" void kernel_launch(void* const* d_in, const int* in_sizes, int n_in,
                              void* d_out, int out_size) {
    const float* in_input  = (const float*)d_in[0];
    const float* noise1    = (const float*)d_in[2];
    const float* noise2    = (const float*)d_in[3];
    const float* init_dec  = (const float*)d_in[4];
    const float* enc_Wih   = (const float*)d_in[5];
    const float* enc_Whh   = (const float*)d_in[6];
    const float* enc_bih   = (const float*)d_in[7];
    const float* enc_bhh   = (const float*)d_in[8];
    const float* dec_Wih   = (const float*)d_in[9];
    const float* dec_Whh   = (const float*)d_in[10];
    const float* dec_bih   = (const float*)d_in[11];
    const float* dec_bhh   = (const float*)d_in[12];
    const float* emb_W     = (const float*)d_in[13];
    const float* emb_b     = (const float*)d_in[14];
    const float* attn_W    = (const float*)d_in[15];
    const float* attn_b    = (const float*)d_in[16];
    const float* comb_W    = (const float*)d_in[17];
    const float* comb_b    = (const float*)d_in[18];
    const float* out_W     = (const float*)d_in[19];
    const float* out_b     = (const float*)d_in[20];
    float* out = (float*)d_out;

    float *pre = sym<float>(g_pre_enc), *Mm = sym<float>(g_Mmat),
          *n1p = sym<float>(g_n1pre), *n2p = sym<float>(g_n2pre),
          *Hs = sym<float>(g_Hs), *hb = sym<float>(g_hbuf), *c = sym<float>(g_c),
          *encb = sym<float>(g_encbias), *decb = sym<float>(g_decbias),
          *v = sym<float>(g_v), *kpart = sym<float>(g_kpart),
          *WA = sym<float>(g_WA), *A1M = sym<float>(g_A1M), *C1M = sym<float>(g_C1M),
          *pre_a = sym<float>(g_pre_a), *pre_c = sym<float>(g_pre_c),
          *n1x = sym<float>(g_n1x), *emb0 = sym<float>(g_emb0),
          *enc2T = sym<float>(g_enc2T), *enc_out = sym<float>(g_enc_out);
    __nv_bfloat16 *AinH = sym<__nv_bfloat16>(g_Ain_h), *AinL = sym<__nv_bfloat16>(g_Ain_l);
    __nv_bfloat16 *WihH = sym<__nv_bfloat16>(g_Wih_h), *WihL = sym<__nv_bfloat16>(g_Wih_l);
    __nv_bfloat16 *eWEH = sym<__nv_bfloat16>(g_eWE_h), *eWEL = sym<__nv_bfloat16>(g_eWE_l);
    __nv_bfloat16 *oWtH = sym<__nv_bfloat16>(g_oWt_h), *oWtL = sym<__nv_bfloat16>(g_oWt_l);
    __nv_bfloat16 *n1AH = sym<__nv_bfloat16>(g_n1A_h), *n1AL = sym<__nv_bfloat16>(g_n1A_l);
    __nv_bfloat16 *eWNH = sym<__nv_bfloat16>(g_eWN_h), *eWNL = sym<__nv_bfloat16>(g_eWN_l);
    __nv_bfloat16 *n2AH = sym<__nv_bfloat16>(g_n2A_h), *n2AL = sym<__nv_bfloat16>(g_n2A_l);
    __nv_bfloat16 *aW2H = sym<__nv_bfloat16>(g_aW2_h), *aW2L = sym<__nv_bfloat16>(g_aW2_l);
    __nv_bfloat16 *oWH = sym<__nv_bfloat16>(g_oW_h), *oWL = sym<__nv_bfloat16>(g_oW_l);
    __nv_bfloat16 *HsAH = sym<__nv_bfloat16>(g_HsA_h), *HsAL = sym<__nv_bfloat16>(g_HsA_l);
    __nv_bfloat16 *Wa1H = sym<__nv_bfloat16>(g_Wa1_h), *Wa1L = sym<__nv_bfloat16>(g_Wa1_l);
    __nv_bfloat16 *Wc1H = sym<__nv_bfloat16>(g_Wc1_h), *Wc1L = sym<__nv_bfloat16>(g_Wc1_l);
    __nv_bfloat16 *Wc2H = sym<__nv_bfloat16>(g_Wc2_h), *Wc2L = sym<__nv_bfloat16>(g_Wc2_l);
    __nv_bfloat16 *MtH = sym<__nv_bfloat16>(g_Mt_h), *MtL = sym<__nv_bfloat16>(g_Mt_l);
    __nv_bfloat16 *idH = sym<__nv_bfloat16>(g_id_h), *idL = sym<__nv_bfloat16>(g_id_l);
    __nv_bfloat16 *n1xH = sym<__nv_bfloat16>(g_n1x_h), *n1xL = sym<__nv_bfloat16>(g_n1x_l);
    __nv_bfloat16 *eoH = sym<__nv_bfloat16>(g_eo_h), *eoL = sym<__nv_bfloat16>(g_eo_l);

    cudaFuncSetAttribute(gemm_tc, cudaFuncAttributeMaxDynamicSharedMemorySize, GEMM_SMEM);
    cudaFuncSetAttribute(dec_kernel, cudaFuncAttributeMaxDynamicSharedMemorySize, DEC_SMEM);

    const int GYE = (KP_E + 2047) / 2048, GYH = 1, GYNZ = (KP_NZ + 2047) / 2048;
    constexpr int NCH_E = KP_E / 32, NCH_NZ = KP_NZ / 32, NCH_H = KP_H / 32;

    // ---- launches 1-5 (so gemm_tc is 6th -> ncu -s 5 -c 1 captures it) ----
    conv8<true><<<dim3(1024, GYE), 256>>>(in_input, E, T, AinH, AinL, 1024, E, KP_E);
    conv8<false><<<dim3(4096, GYE), 256>>>(enc_Wih, E, 0, WihH, WihL, G4, E, KP_E);
    bias_sum<<<(G4 + 255) / 256, 256>>>(enc_bih, enc_bhh, encb, G4);
    bias_sum<<<(G4 + 255) / 256, 256>>>(dec_bih, dec_bhh, decb, G4);
    calc_v<<<H, 256>>>(out_b, emb_W, v);

    // ---- launch 6: pre_enc GEMM (split-K SL=8 for full-chip waves) ----
    {
        constexpr int SL = 8, CPS = (NCH_E + SL - 1) / SL;
        gemm_tc<<<dim3(16, 8, SL), 256, GEMM_SMEM>>>(AinH, AinL, WihH, WihL, KP_E,
                                                     nullptr, kpart, G4, T * B, G4, CPS, 1);
        reduce_k<<<(int)(((size_t)T * B * G4 + 255) / 256), 256>>>(
            kpart, encb, nullptr, pre, T * B, G4, G4, SL, 0);
    }

    // ---- init + remaining conversions ----
    cudaMemsetAsync(hb, 0, B * H * sizeof(float));
    cudaMemsetAsync(c, 0, B * H * sizeof(float));
    conv8<false><<<dim3(1024, GYE), 256>>>(emb_W, EMB_LD, 0, eWEH, eWEL, H, E, KP_E);
    conv_trans<<<dim3((KP_E + 31) / 32, 32), dim3(32, 8)>>>(out_W, H, oWtH, oWtL, E, H, KP_E, 1024);
    conv8<false><<<dim3(512, GYNZ), 256>>>(noise1, NZ, 0, n1AH, n1AL, 512, NZ, KP_NZ);
    conv8<false><<<dim3(1024, GYNZ), 256>>>(emb_W + E, EMB_LD, 0, eWNH, eWNL, H, NZ, KP_NZ);
    conv8<false><<<dim3(512, GYH), 256>>>(noise2, H, 0, n2AH, n2AL, 512, H, KP_H);
    conv8<false><<<dim3(256, GYH), 256>>>(attn_W + 2 * H, ATTN_LD, 0, aW2H, aW2L, T, H, KP_H);
    conv8<false><<<dim3(30720, GYH), 256>>>(out_W, H, 0, oWH, oWL, E, H, KP_H);
    conv8<false><<<dim3(256, GYH), 256>>>(attn_W, ATTN_LD, 0, Wa1H, Wa1L, T, H, KP_H);
    conv8<false><<<dim3(1024, GYH), 256>>>(comb_W, COMB_LD, 0, Wc1H, Wc1L, H, H, KP_H);
    conv8<false><<<dim3(1024, GYH), 256>>>(comb_W + H, COMB_LD, 0, Wc2H, Wc2L, H, H, KP_H);
    conv8<false><<<dim3(128, GYE), 256>>>(init_dec, E, 0, idH, idL, 8, E, KP_E);

    // ---- precompute GEMMs (split-K) ----
    {   // Mmat = emb_W_E @ out_W
        constexpr int SL = 4, CPS = (NCH_E + SL - 1) / SL;
        gemm_tc<<<dim3(4, 8, SL), 256, GEMM_SMEM>>>(eWEH, eWEL, oWtH, oWtL, KP_E,
                                                    nullptr, kpart, H, H, H, CPS, 1);
        reduce_k<<<(H * H + 255) / 256, 256>>>(kpart, nullptr, nullptr, Mm, H, H, H, SL, 0);
    }
    conv_trans<<<dim3((KP_H + 31) / 32, 32), dim3(32, 8)>>>(Mm, H, MtH, MtL, H, H, KP_H, 1024);
    {   // A1M = Wa1 @ M
        constexpr int SL = 8, CPS = (NCH_H + SL - 1) / SL;
        gemm_tc<<<dim3(4, 1, SL), 256, GEMM_SMEM>>>(Wa1H, Wa1L, MtH, MtL, KP_H,
                                                    nullptr, kpart, H, T, H, CPS, 1);
        reduce_k<<<(T * H + 255) / 256, 256>>>(kpart, nullptr, nullptr, A1M, T, H, H, SL, 0);
        make_WA<<<(T * H + 255) / 256, 256>>>(A1M, attn_W, WA);
    }
    {   // C1M = Wc1 @ M
        constexpr int SL = 4, CPS = (NCH_H + SL - 1) / SL;
        gemm_tc<<<dim3(4, 8, SL), 256, GEMM_SMEM>>>(Wc1H, Wc1L, MtH, MtL, KP_H,
                                                    nullptr, kpart, H, H, H, CPS, 1);
        reduce_k<<<(H * H + 255) / 256, 256>>>(kpart, nullptr, nullptr, C1M, H, H, H, SL, 0);
    }
    {   // n1pre = noise1 @ emb_W_N^T + emb_b
        constexpr int SL = 8, CPS = (NCH_NZ + SL - 1) / SL;
        gemm_tc<<<dim3(4, 4, SL), 256, GEMM_SMEM>>>(n1AH, n1AL, eWNH, eWNL, KP_NZ,
                                                    nullptr, kpart, H, S * B, H, CPS, 1);
        reduce_k<<<(S * B * H + 255) / 256, 256>>>(kpart, emb_b, nullptr, n1p, S * B, H, H, SL, 0);
    }
    {   // emb0 = init_dec @ emb_W_E^T
        constexpr int SL = 8, CPS = (NCH_E + SL - 1) / SL;
        gemm_tc<<<dim3(4, 1, SL), 256, GEMM_SMEM>>>(idH, idL, eWEH, eWEL, KP_E,
                                                    nullptr, kpart, H, 8, H, CPS, 1);
        reduce_k<<<(8 * H + 255) / 256, 256>>>(kpart, nullptr, nullptr, emb0, 8, H, H, SL, 0);
    }
    make_n1x<<<(S * B * H + 255) / 256, 256>>>(n1p, emb0, v, n1x);
    conv8<false><<<dim3(512, GYH), 256>>>(n1x, H, 0, n1xH, n1xL, S * B, H, KP_H);
    {   // n2pre = noise2 @ Wa3^T + attn_b
        constexpr int SL = 8, CPS = (NCH_H + SL - 1) / SL;
        gemm_tc<<<dim3(1, 4, SL), 256, GEMM_SMEM>>>(n2AH, n2AL, aW2H, aW2L, KP_H,
                                                    nullptr, kpart, T, S * B, T, CPS, 1);
        reduce_k<<<(S * B * T + 255) / 256, 256>>>(kpart, attn_b, nullptr, n2p, S * B, T, T, SL, 0);
    }
    {   // pre_a = n1x @ Wa1^T + n2pre
        constexpr int SL = 8, CPS = (NCH_H + SL - 1) / SL;
        gemm_tc<<<dim3(1, 4, SL), 256, GEMM_SMEM>>>(n1xH, n1xL, Wa1H, Wa1L, KP_H,
                                                    nullptr, kpart, T, S * B, T, CPS, 1);
        reduce_k<<<(S * B * T + 255) / 256, 256>>>(kpart, nullptr, n2p, pre_a, S * B, T, T, SL, 0);
    }
    {   // pre_c = n1x @ Wc1^T + comb_b
        constexpr int SL = 8, CPS = (NCH_H + SL - 1) / SL;
        gemm_tc<<<dim3(4, 4, SL), 256, GEMM_SMEM>>>(n1xH, n1xL, Wc1H, Wc1L, KP_H,
                                                    nullptr, kpart, H, S * B, H, CPS, 1);
        reduce_k<<<(S * B * H + 255) / 256, 256>>>(kpart, comb_b, nullptr, pre_c, S * B, H, H, SL, 0);
    }

    // ---- encoder ----
    enc_kernel<<<NCTA, 256>>>(enc_Whh);

    // ---- enc2T = (enc_out @ Wc2^T) in [b][j][t] layout ----
    conv8<false><<<dim3(1024, GYH), 256>>>(enc_out, H, 0, eoH, eoL, T * B, H, KP_H);
    {
        constexpr int SL = 4, CPS = (NCH_H + SL - 1) / SL;
        gemm_tc<<<dim3(4, 8, SL), 256, GEMM_SMEM>>>(eoH, eoL, Wc2H, Wc2L, KP_H,
                                                    nullptr, kpart, H, T * B, H, CPS, 1);
        reduce_k<<<(T * B * H + 255) / 256, 256>>>(kpart, nullptr, nullptr, enc2T,
                                                   T * B, H, H, SL, 1);
    }

    // ---- decoder ----
    dec_kernel<<<NCTA, 256, DEC_SMEM>>>(dec_Wih, dec_Whh, attn_W);

    // ---- final: out = Hs @ out_W^T + out_b (split-K SL=2 for wave balance) ----
    conv8<false><<<dim3(512, GYH), 256>>>(Hs, H, 0, HsAH, HsAL, S * B, H, KP_H);
    {
        constexpr int SL = 2, CPS = (NCH_H + SL - 1) / SL;
        gemm_tc<<<dim3(120, 4, SL), 256, GEMM_SMEM>>>(HsAH, HsAL, oWH, oWL, KP_H,
                                                      nullptr, kpart, E, S * B, E, CPS, 1);
        reduce_k<<<(int)(((size_t)S * B * E + 255) / 256), 256>>>(
            kpart, out_b, nullptr, out, S * B, E, E, SL, 0);
    }
}

// round 14
// speedup vs baseline: 5.2873x; 1.1630x over previous
#include <cuda_runtime.h>
#include <cuda_bf16.h>
#include <cuda_fp16.h>
#include <math.h>

// Problem dims (fixed by setup_inputs)
constexpr int B = 8;
constexpr int T = 128;
constexpr int E = 30522;
constexpr int H = 1000;
constexpr int S = 64;
constexpr int NZ = 10000;
constexpr int G4 = 4 * H;          // 4000
constexpr int EMB_LD = E + NZ;     // 40522
constexpr int ATTN_LD = 3 * H;     // 3000
constexpr int COMB_LD = 2 * H;     // 2000
constexpr int NCTA = 148;

constexpr int KP_E  = 30528;       // E padded to 64
constexpr int KP_NZ = 10048;       // NZ padded to 64
constexpr int KP_H  = 1024;        // H padded to 64

// ---------------- fp32 scratch ----------------
__device__ float g_pre_enc[T * B * G4];
__device__ float g_enc_out[T * B * H];
__device__ float g_Mmat[H * H];
__device__ float g_n1pre[S * B * H];
__device__ float g_n2pre[S * B * T];
__device__ float g_Hs[S * B * H];
__device__ float g_hbuf[2][B * H];
__device__ float g_c[B * H];
__device__ float g_attn[B * T];
__device__ float g_comb[B * H];
__device__ float g_encbias[G4];
__device__ float g_decbias[G4];
__device__ float g_v[H];
__device__ float g_kpart[33000000];         // split-K partials (131 MB)
__device__ float g_WA[T * H];               // Wa1@M + Wa2
__device__ float g_A1M[T * H];
__device__ float g_C1M[H * H];
__device__ float g_pre_a[S * B * T];
__device__ float g_pre_c[S * B * H];
__device__ float g_n1x[S * B * H];
__device__ float g_emb0[B * H];
__device__ float g_enc2T[B * H * T];        // [b][j][t]
__device__ unsigned g_bar_arrive;
__device__ unsigned g_bar_gen;

// ---------------- fp16 hi/lo operand buffers (padded) ----------------
__device__ __half g_Ain_h[1024 * KP_E],  g_Ain_l[1024 * KP_E];
__device__ __half g_Wih_h[4096 * KP_E],  g_Wih_l[4096 * KP_E];
__device__ __half g_eWE_h[1024 * KP_E],  g_eWE_l[1024 * KP_E];
__device__ __half g_oWt_h[1024 * KP_E],  g_oWt_l[1024 * KP_E];
__device__ __half g_n1A_h[512 * KP_NZ],  g_n1A_l[512 * KP_NZ];
__device__ __half g_eWN_h[1024 * KP_NZ], g_eWN_l[1024 * KP_NZ];
__device__ __half g_n2A_h[512 * KP_H],   g_n2A_l[512 * KP_H];
__device__ __half g_aW2_h[256 * KP_H],   g_aW2_l[256 * KP_H];
__device__ __half g_oW_h[30720 * KP_H],  g_oW_l[30720 * KP_H];
__device__ __half g_HsA_h[512 * KP_H],   g_HsA_l[512 * KP_H];
__device__ __half g_Wa1_h[256 * KP_H],   g_Wa1_l[256 * KP_H];
__device__ __half g_Wc1_h[1024 * KP_H],  g_Wc1_l[1024 * KP_H];
__device__ __half g_Wc2_h[1024 * KP_H],  g_Wc2_l[1024 * KP_H];
__device__ __half g_Mt_h[1024 * KP_H],   g_Mt_l[1024 * KP_H];
__device__ __half g_id_h[128 * KP_E],    g_id_l[128 * KP_E];
__device__ __half g_n1x_h[512 * KP_H],   g_n1x_l[512 * KP_H];
__device__ __half g_eo_h[1024 * KP_H],   g_eo_l[1024 * KP_H];

// ---------------- helpers ----------------
__device__ __forceinline__ unsigned s2u(const void* p) {
    unsigned a;
    asm("{ .reg .u64 t; cvta.to.shared.u64 t, %1; cvt.u32.u64 %0, t; }"
        : "=r"(a) : "l"(p));
    return a;
}
__device__ __forceinline__ void cp16(unsigned dst, const void* src) {
    asm volatile("cp.async.cg.shared.global [%0], [%1], 16;" :: "r"(dst), "l"(src)
                 : "memory");
}
__device__ __forceinline__ void cp_commit() {
    asm volatile("cp.async.commit_group;" ::: "memory");
}
template <int N>
__device__ __forceinline__ void cp_wait() {
    asm volatile("cp.async.wait_group %0;" :: "n"(N) : "memory");
}
__device__ __forceinline__ void mma_f16(float* c, const unsigned* a, const unsigned* b) {
    asm volatile(
        "mma.sync.aligned.m16n8k16.row.col.f32.f16.f16.f32 "
        "{%0,%1,%2,%3}, {%4,%5,%6,%7}, {%8,%9}, {%0,%1,%2,%3};"
        : "+f"(c[0]), "+f"(c[1]), "+f"(c[2]), "+f"(c[3])
        : "r"(a[0]), "r"(a[1]), "r"(a[2]), "r"(a[3]), "r"(b[0]), "r"(b[1]));
}

// ---------------- vectorized converter: 8 cols/thread, fp16 hi/lo ----------
template <bool SWIZ>
__global__ void conv8(const float* __restrict__ src, int ldS, int swizT,
                      __half* __restrict__ dh,
                      __half* __restrict__ dl,
                      int Mr, int Kr, int Kpad) {
    int row = blockIdx.x;
    int c0 = (blockIdx.y * 256 + threadIdx.x) * 8;
    if (c0 >= Kpad) return;
    const float* sp = nullptr;
    if (row < Mr) {
        int r = SWIZ ? ((row & 7) * swizT + (row >> 3)) : row;
        sp = src + (size_t)r * ldS;
    }
    float x[8];
#pragma unroll
    for (int i = 0; i < 8; i++) {
        int col = c0 + i;
        x[i] = (sp && col < Kr) ? sp[col] : 0.f;
    }
    unsigned hw[4], lw[4];
#pragma unroll
    for (int p = 0; p < 4; p++) {
        __half h0 = __float2half_rn(x[2 * p]);
        __half h1 = __float2half_rn(x[2 * p + 1]);
        __half l0 = __float2half_rn(x[2 * p] - __half2float(h0));
        __half l1 = __float2half_rn(x[2 * p + 1] - __half2float(h1));
        hw[p] = (unsigned)__half_as_ushort(h0) | ((unsigned)__half_as_ushort(h1) << 16);
        lw[p] = (unsigned)__half_as_ushort(l0) | ((unsigned)__half_as_ushort(l1) << 16);
    }
    *(uint4*)(dh + (size_t)row * Kpad + c0) = make_uint4(hw[0], hw[1], hw[2], hw[3]);
    *(uint4*)(dl + (size_t)row * Kpad + c0) = make_uint4(lw[0], lw[1], lw[2], lw[3]);
}

// dst[n][k] = src[k][n]
__global__ void conv_trans(const float* __restrict__ src, int ldS,
                           __half* __restrict__ dh,
                           __half* __restrict__ dl,
                           int Kr, int Nr, int Kpad, int Npad) {
    __shared__ float tile[32][33];
    int kb = blockIdx.x * 32, nb = blockIdx.y * 32;
    int tx = threadIdx.x, ty = threadIdx.y;   // 32 x 8
    for (int i = ty; i < 32; i += 8) {
        int k = kb + i, n = nb + tx;
        tile[i][tx] = (k < Kr && n < Nr) ? src[(size_t)k * ldS + n] : 0.f;
    }
    __syncthreads();
    for (int i = ty; i < 32; i += 8) {
        int n = nb + i, k = kb + tx;
        if (n < Npad && k < Kpad) {
            float x = tile[tx][i];
            __half h = __float2half_rn(x);
            dh[(size_t)n * Kpad + k] = h;
            dl[(size_t)n * Kpad + k] = __float2half_rn(x - __half2float(h));
        }
    }
}

// ---------------- mma.sync GEMM, fp16 hi/lo, 3-stage cp.async, split-K ------
// NTERMS==3: C = Ah·Bh + Al·Bh + Ah·Bl (error ~2^-24)
// NTERMS==2: C = Ah·Bh + Al·Bh        (error = single B truncation ~2^-12 RMS/√3)
constexpr int ST_W = 20 * (128 + 128 + 256 + 256);   // 15360 words
constexpr int ST_BYTES = ST_W * 4;
constexpr int GEMM_SMEM = 3 * ST_BYTES;

template <int NTERMS>
__global__ void __launch_bounds__(256, 1)
gemm_tc(const __half* __restrict__ Ah, const __half* __restrict__ Al,
        const __half* __restrict__ Bh, const __half* __restrict__ Bl,
        int Kpad, const float* __restrict__ bias,
        float* __restrict__ C, int ldC, int M, int N, int cps, int partial) {
    extern __shared__ unsigned sm[];
    const unsigned sbase = s2u(sm);
    const int tid = threadIdx.x;
    const int wid = tid >> 5, lane = tid & 31;
    const int g = lane >> 2, tq = lane & 3;
    const int wm = wid & 1, wn = wid >> 1;
    const int m0 = blockIdx.y * 128, n0 = blockIdx.x * 256;
    const int nch = Kpad / 32;
    const int z = blockIdx.z;
    const int c0 = z * cps;
    const int c1 = min(nch, c0 + cps);

    float acc[4][8][4];
#pragma unroll
    for (int i = 0; i < 4; i++)
#pragma unroll
        for (int j = 0; j < 8; j++)
#pragma unroll
            for (int q = 0; q < 4; q++) acc[i][j][q] = 0.f;

    auto load_stage = [&](int st, int ci) {
        unsigned sb = sbase + st * ST_BYTES;
        int k0 = ci * 32;
        constexpr int NQ = (NTERMS == 3) ? 12 : 8;
#pragma unroll
        for (int q = 0; q < NQ; q++) {
            int it = tid + q * 256;
            const __half* gp;
            unsigned dw;
            if (it < 1024) {
                int idx = it & 511, r = idx >> 2, c = idx & 3;
                gp = (it < 512 ? Ah : Al) + (size_t)(m0 + r) * Kpad + k0 + c * 8;
                dw = (it < 512 ? 0u : 2560u) + r * 20 + c * 4;
            } else {
                int idx = (it - 1024) & 1023, r = idx >> 2, c = idx & 3;
                gp = (it < 2048 ? Bh : Bl) + (size_t)(n0 + r) * Kpad + k0 + c * 8;
                dw = (it < 2048 ? 5120u : 10240u) + r * 20 + c * 4;
            }
            cp16(sb + dw * 4, gp);
        }
        cp_commit();
    };

    if (c0 < c1)     load_stage(0, c0);
    if (c0 + 1 < c1) load_stage(1, c0 + 1);

    for (int ci = c0; ci < c1; ci++) {
        int st = (ci - c0) % 3;
        if (ci == c1 - 1) cp_wait<0>(); else cp_wait<1>();
        __syncthreads();
        if (ci + 2 < c1) load_stage((ci - c0 + 2) % 3, ci + 2);

        const unsigned b0 = st * ST_W;
#pragma unroll
        for (int ks = 0; ks < 2; ks++) {
            int ws = ks * 8 + tq;
            unsigned ahf[4][4], alf[4][4];
#pragma unroll
            for (int i = 0; i < 4; i++) {
                int am = wm * 64 + i * 16 + g;
                ahf[i][0] = sm[b0 + am * 20 + ws];
                ahf[i][1] = sm[b0 + (am + 8) * 20 + ws];
                ahf[i][2] = sm[b0 + am * 20 + ws + 4];
                ahf[i][3] = sm[b0 + (am + 8) * 20 + ws + 4];
                alf[i][0] = sm[b0 + 2560 + am * 20 + ws];
                alf[i][1] = sm[b0 + 2560 + (am + 8) * 20 + ws];
                alf[i][2] = sm[b0 + 2560 + am * 20 + ws + 4];
                alf[i][3] = sm[b0 + 2560 + (am + 8) * 20 + ws + 4];
            }
#pragma unroll
            for (int jh = 0; jh < 2; jh++) {
                unsigned bhf[4][2], blf[4][2];
#pragma unroll
                for (int j = 0; j < 4; j++) {
                    int bn = wn * 64 + jh * 32 + j * 8 + g;
                    bhf[j][0] = sm[b0 + 5120 + bn * 20 + ws];
                    bhf[j][1] = sm[b0 + 5120 + bn * 20 + ws + 4];
                    if (NTERMS == 3) {
                        blf[j][0] = sm[b0 + 10240 + bn * 20 + ws];
                        blf[j][1] = sm[b0 + 10240 + bn * 20 + ws + 4];
                    }
                }
#pragma unroll
                for (int i = 0; i < 4; i++)
#pragma unroll
                    for (int j = 0; j < 4; j++)
                        mma_f16(acc[i][jh * 4 + j], ahf[i], bhf[j]);
#pragma unroll
                for (int i = 0; i < 4; i++)
#pragma unroll
                    for (int j = 0; j < 4; j++)
                        mma_f16(acc[i][jh * 4 + j], alf[i], bhf[j]);
                if (NTERMS == 3) {
#pragma unroll
                    for (int i = 0; i < 4; i++)
#pragma unroll
                        for (int j = 0; j < 4; j++)
                            mma_f16(acc[i][jh * 4 + j], ahf[i], blf[j]);
                }
            }
        }
        __syncthreads();
    }

    float* Cb = partial ? (C + (size_t)z * M * N) : C;
    const int ld = partial ? N : ldC;
#pragma unroll
    for (int i = 0; i < 4; i++) {
        int rr0 = m0 + wm * 64 + i * 16 + g;
#pragma unroll
        for (int j = 0; j < 8; j++) {
            int cc = n0 + wn * 64 + j * 8 + tq * 2;
#pragma unroll
            for (int q = 0; q < 4; q++) {
                int rr = rr0 + (q >> 1) * 8;
                int cn = cc + (q & 1);
                if (rr < M && cn < N) {
                    float v = acc[i][j][q];
                    if (!partial && bias) v += bias[cn];
                    Cb[(size_t)rr * ld + cn] = v;
                }
            }
        }
    }
}

// deterministic split-K reduce. emode 0: out[m*ldC+n]; 1: enc2T layout.
__global__ void reduce_k(const float* __restrict__ part,
                         const float* __restrict__ bias,
                         const float* __restrict__ add,
                         float* __restrict__ out,
                         int M, int N, int ldC, int slices, int emode) {
    size_t idx = (size_t)blockIdx.x * 256 + threadIdx.x;
    if (idx >= (size_t)M * N) return;
    int m = (int)(idx / N), n = (int)(idx - (size_t)m * N);
    float v = bias ? bias[n] : 0.f;
    if (add) v += add[idx];
    for (int z = 0; z < slices; z++) v += part[(size_t)z * M * N + idx];
    if (emode == 1) out[((size_t)(m & 7) * H + n) * T + (m >> 3)] = v;
    else out[(size_t)m * ldC + n] = v;
}

// ---------------- persistent kernels ----------------
__device__ __forceinline__ void grid_barrier() {
    __threadfence();
    __syncthreads();
    if (threadIdx.x == 0) {
        unsigned gen = atomicAdd(&g_bar_gen, 0u);
        if (atomicAdd(&g_bar_arrive, 1u) == gridDim.x - 1) {
            g_bar_arrive = 0;
            __threadfence();
            atomicAdd(&g_bar_gen, 1u);
        } else {
            volatile unsigned* vg = &g_bar_gen;
            while (*vg == gen) { }
        }
    }
    __syncthreads();
}
__device__ __forceinline__ float wsum(float v) {
#pragma unroll
    for (int off = 16; off; off >>= 1) v += __shfl_xor_sync(0xFFFFFFFFu, v, off);
    return v;
}
__device__ __forceinline__ float sigm(float x) { return 1.f / (1.f + expf(-x)); }
__device__ __forceinline__ void stage8k(float* xs, const float* src) {
    const float4* s4 = reinterpret_cast<const float4*>(src);
    float4* d4 = reinterpret_cast<float4*>(xs);
    for (int i = threadIdx.x; i < B * H / 4; i += 256) d4[i] = s4[i];
}
__device__ __forceinline__ float dot4(float4 a, float4 b) {
    return a.x * b.x + a.y * b.y + a.z * b.z + a.w * b.w;
}

__global__ void __launch_bounds__(256, 1)
enc_kernel(const float* __restrict__ enc_Whh) {
    __shared__ __align__(16) float xs[B][H];
    const int ct = blockIdx.x, tid = threadIdx.x;
    const int w = tid >> 5, lane = tid & 31;
    const int j = ct + NCTA * w;
    const bool own = (w < 7) && (j < H);

    for (int t = 0; t < T; t++) {
        stage8k(xs[0], g_hbuf[t & 1]);
        __syncthreads();
        float acc[4][8];
#pragma unroll
        for (int ga = 0; ga < 4; ga++)
#pragma unroll
            for (int b = 0; b < 8; b++) acc[ga][b] = 0.f;
        if (own) {
#pragma unroll
            for (int kb = 0; kb < 8; kb++) {
                int kk = kb * 128 + lane * 4;
                if (kk < H) {
                    float4 xv[8];
#pragma unroll
                    for (int b = 0; b < 8; b++)
                        xv[b] = *reinterpret_cast<const float4*>(&xs[b][kk]);
#pragma unroll
                    for (int ga = 0; ga < 4; ga++) {
                        float4 wv = *reinterpret_cast<const float4*>(
                            &enc_Whh[(size_t)(ga * H + j) * H + kk]);
#pragma unroll
                        for (int b = 0; b < 8; b++) acc[ga][b] += dot4(wv, xv[b]);
                    }
                }
            }
        }
#pragma unroll
        for (int ga = 0; ga < 4; ga++)
#pragma unroll
            for (int b = 0; b < 8; b++) acc[ga][b] = wsum(acc[ga][b]);
        if (own && lane < 8) {
            int b = lane;
            const float* pre = g_pre_enc + (t * 8 + b) * G4;
            float gi = sigm(acc[0][b] + pre[j]);
            float gf = sigm(acc[1][b] + pre[H + j]);
            float gg = tanhf(acc[2][b] + pre[2 * H + j]);
            float go = sigm(acc[3][b] + pre[3 * H + j]);
            float cn = gf * g_c[b * H + j] + gi * gg;
            g_c[b * H + j] = cn;
            float hn = go * tanhf(cn);
            g_hbuf[(t + 1) & 1][b * H + j] = hn;
            g_enc_out[t * (B * H) + b * H + j] = hn;
        }
        grid_barrier();
    }
}

// decoder: 3 phases/step. dynamic smem: xs(h) 8000f | cs(comb) 8000f | aw 1024f
constexpr int DEC_SMEM = (8000 + 8000 + 1024) * 4;

__global__ void __launch_bounds__(256, 1)
dec_kernel(const float* __restrict__ dec_Wih,
           const float* __restrict__ dec_Whh,
           const float* __restrict__ attn_W) {
    extern __shared__ __align__(16) float dsm[];
    float* xs = dsm;             // [8][1000] h
    float* cs = dsm + 8000;      // [8][1000] comb
    float* aw = dsm + 16000;     // [8][128]

    const int ct = blockIdx.x, tid = threadIdx.x;
    const int w = tid >> 5, lane = tid & 31;
    const int j = ct + NCTA * w;
    const bool own = (w < 7) && (j < H);

    for (int s = 0; s < S; s++) {
        stage8k(xs, g_hbuf[s & 1]);
        __syncthreads();

        // ---- phase A: rc = C1M@h partials; attn logits ----
        float rc[8];
#pragma unroll
        for (int b = 0; b < 8; b++) rc[b] = 0.f;
        if (s > 0 && own) {
#pragma unroll
            for (int kb = 0; kb < 8; kb++) {
                int kk = kb * 128 + lane * 4;
                if (kk < H) {
                    float4 cw = *reinterpret_cast<const float4*>(&g_C1M[(size_t)j * H + kk]);
#pragma unroll
                    for (int b = 0; b < 8; b++)
                        rc[b] += dot4(cw, *reinterpret_cast<const float4*>(&xs[b * H + kk]));
                }
            }
        }
        if (ct < T) {
            int tp = ct, b = w;
            float acc = 0.f;
            if (s == 0) {
#pragma unroll
                for (int kb = 0; kb < 8; kb++) {
                    int kk = kb * 128 + lane * 4;
                    if (kk < H) {
                        float4 wv = *reinterpret_cast<const float4*>(
                            &attn_W[(size_t)tp * ATTN_LD + H + kk]);
                        acc += dot4(wv, *reinterpret_cast<const float4*>(&xs[b * H + kk]));
                    }
                }
            } else {
#pragma unroll
                for (int kb = 0; kb < 8; kb++) {
                    int kk = kb * 128 + lane * 4;
                    if (kk < H) {
                        float4 wv = *reinterpret_cast<const float4*>(&g_WA[(size_t)tp * H + kk]);
                        acc += dot4(wv, *reinterpret_cast<const float4*>(&xs[b * H + kk]));
                    }
                }
            }
            acc = wsum(acc);
            if (lane == 0)
                g_attn[b * T + tp] = acc + g_pre_a[(s * 8 + b) * T + tp];
        }
        grid_barrier();

        // ---- phase B: local softmax + comb ----
        {
            int b = w;
            float vx[4];
#pragma unroll
            for (int q = 0; q < 4; q++) vx[q] = g_attn[b * T + lane + 32 * q];
            float m = fmaxf(fmaxf(vx[0], vx[1]), fmaxf(vx[2], vx[3]));
#pragma unroll
            for (int off = 16; off; off >>= 1)
                m = fmaxf(m, __shfl_xor_sync(0xFFFFFFFFu, m, off));
            float e[4], ssum = 0.f;
#pragma unroll
            for (int q = 0; q < 4; q++) { e[q] = expf(vx[q] - m); ssum += e[q]; }
            ssum = wsum(ssum);
            float inv = 1.f / ssum;
#pragma unroll
            for (int q = 0; q < 4; q++) aw[b * T + lane + 32 * q] = e[q] * inv;
        }
        __syncthreads();
        if (own) {
#pragma unroll
            for (int b = 0; b < 8; b++) {
                const float* e2 = g_enc2T + ((size_t)b * H + j) * T;
                float a = 0.f;
#pragma unroll
                for (int it = 0; it < 4; it++)
                    a += aw[b * T + lane + 32 * it] * e2[lane + 32 * it];
                rc[b] += a;
            }
#pragma unroll
            for (int b = 0; b < 8; b++) rc[b] = wsum(rc[b]);
            if (lane < 8) {
                int b = lane;
                g_comb[b * H + j] = fmaxf(rc[b] + g_pre_c[(s * 8 + b) * H + j], 0.f);
            }
        }
        grid_barrier();

        // ---- phase C: gates + LSTM ----
        stage8k(cs, g_comb);
        __syncthreads();
        float acc4[4][8];
#pragma unroll
        for (int ga = 0; ga < 4; ga++)
#pragma unroll
            for (int b = 0; b < 8; b++) acc4[ga][b] = 0.f;
        if (own) {
#pragma unroll
            for (int kb = 0; kb < 8; kb++) {
                int kk = kb * 128 + lane * 4;
                if (kk < H) {
                    float4 cv[8], hv[8];
#pragma unroll
                    for (int b = 0; b < 8; b++) {
                        cv[b] = *reinterpret_cast<const float4*>(&cs[b * H + kk]);
                        hv[b] = *reinterpret_cast<const float4*>(&xs[b * H + kk]);
                    }
#pragma unroll
                    for (int ga = 0; ga < 4; ga++) {
                        float4 wih = *reinterpret_cast<const float4*>(
                            &dec_Wih[(size_t)(ga * H + j) * H + kk]);
                        float4 whh = *reinterpret_cast<const float4*>(
                            &dec_Whh[(size_t)(ga * H + j) * H + kk]);
#pragma unroll
                        for (int b = 0; b < 8; b++)
                            acc4[ga][b] += dot4(wih, cv[b]) + dot4(whh, hv[b]);
                    }
                }
            }
        }
#pragma unroll
        for (int ga = 0; ga < 4; ga++)
#pragma unroll
            for (int b = 0; b < 8; b++) acc4[ga][b] = wsum(acc4[ga][b]);
        if (own && lane < 8) {
            int b = lane;
            float gi = sigm(acc4[0][b] + g_decbias[j]);
            float gf = sigm(acc4[1][b] + g_decbias[H + j]);
            float gg = tanhf(acc4[2][b] + g_decbias[2 * H + j]);
            float go = sigm(acc4[3][b] + g_decbias[3 * H + j]);
            float cn = gf * g_c[b * H + j] + gi * gg;
            g_c[b * H + j] = cn;
            float hn = go * tanhf(cn);
            g_hbuf[(s + 1) & 1][b * H + j] = hn;
            g_Hs[s * (B * H) + b * H + j] = hn;
        }
        grid_barrier();
    }
}

// ---------------- tiny kernels ----------------
__global__ void bias_sum(const float* __restrict__ a, const float* __restrict__ b,
                         float* __restrict__ o, int n) {
    int i = blockIdx.x * blockDim.x + threadIdx.x;
    if (i < n) o[i] = a[i] + b[i];
}
__global__ void calc_v(const float* __restrict__ out_b, const float* __restrict__ emb_W,
                       float* __restrict__ v) {
    int j = blockIdx.x;
    const float* row = emb_W + (size_t)j * EMB_LD;
    float acc = 0.f;
    for (int e = threadIdx.x; e < E; e += 256) acc += out_b[e] * row[e];
    __shared__ float s[256];
    s[threadIdx.x] = acc;
    __syncthreads();
    for (int off = 128; off; off >>= 1) {
        if (threadIdx.x < off) s[threadIdx.x] += s[threadIdx.x + off];
        __syncthreads();
    }
    if (threadIdx.x == 0) v[j] = s[0];
}
__global__ void make_WA(const float* __restrict__ A1M, const float* __restrict__ attn_W,
                        float* __restrict__ WA) {
    int i = blockIdx.x * 256 + threadIdx.x;
    if (i >= T * H) return;
    int t = i / H, k = i - t * H;
    WA[i] = A1M[i] + attn_W[t * ATTN_LD + H + k];
}
__global__ void make_n1x(const float* __restrict__ n1p, const float* __restrict__ emb0,
                         const float* __restrict__ v, float* __restrict__ n1x) {
    int i = blockIdx.x * 256 + threadIdx.x;
    if (i >= S * B * H) return;
    int row = i / H, k = i - row * H;
    n1x[i] = n1p[i] + (row < 8 ? emb0[i] : v[k]);
}

// ---------------- host orchestration ----------------
template <typename Tp>
static Tp* sym(const void* symbol) {
    void* p;
    cudaGetSymbolAddress(&p, symbol);
    return (Tp*)p;
}

extern "C" void kernel_launch(void* const* d_in, const int* in_sizes, int n_in,
                              void* d_out, int out_size) {
    const float* in_input  = (const float*)d_in[0];
    const float* noise1    = (const float*)d_in[2];
    const float* noise2    = (const float*)d_in[3];
    const float* init_dec  = (const float*)d_in[4];
    const float* enc_Wih   = (const float*)d_in[5];
    const float* enc_Whh   = (const float*)d_in[6];
    const float* enc_bih   = (const float*)d_in[7];
    const float* enc_bhh   = (const float*)d_in[8];
    const float* dec_Wih   = (const float*)d_in[9];
    const float* dec_Whh   = (const float*)d_in[10];
    const float* dec_bih   = (const float*)d_in[11];
    const float* dec_bhh   = (const float*)d_in[12];
    const float* emb_W     = (const float*)d_in[13];
    const float* emb_b     = (const float*)d_in[14];
    const float* attn_W    = (const float*)d_in[15];
    const float* attn_b    = (const float*)d_in[16];
    const float* comb_W    = (const float*)d_in[17];
    const float* comb_b    = (const float*)d_in[18];
    const float* out_W     = (const float*)d_in[19];
    const float* out_b     = (const float*)d_in[20];
    float* out = (float*)d_out;

    float *pre = sym<float>(g_pre_enc), *Mm = sym<float>(g_Mmat),
          *n1p = sym<float>(g_n1pre), *n2p = sym<float>(g_n2pre),
          *Hs = sym<float>(g_Hs), *hb = sym<float>(g_hbuf), *c = sym<float>(g_c),
          *encb = sym<float>(g_encbias), *decb = sym<float>(g_decbias),
          *v = sym<float>(g_v), *kpart = sym<float>(g_kpart),
          *WA = sym<float>(g_WA), *A1M = sym<float>(g_A1M), *C1M = sym<float>(g_C1M),
          *pre_a = sym<float>(g_pre_a), *pre_c = sym<float>(g_pre_c),
          *n1x = sym<float>(g_n1x), *emb0 = sym<float>(g_emb0),
          *enc2T = sym<float>(g_enc2T), *enc_out = sym<float>(g_enc_out);
    __half *AinH = sym<__half>(g_Ain_h), *AinL = sym<__half>(g_Ain_l);
    __half *WihH = sym<__half>(g_Wih_h), *WihL = sym<__half>(g_Wih_l);
    __half *eWEH = sym<__half>(g_eWE_h), *eWEL = sym<__half>(g_eWE_l);
    __half *oWtH = sym<__half>(g_oWt_h), *oWtL = sym<__half>(g_oWt_l);
    __half *n1AH = sym<__half>(g_n1A_h), *n1AL = sym<__half>(g_n1A_l);
    __half *eWNH = sym<__half>(g_eWN_h), *eWNL = sym<__half>(g_eWN_l);
    __half *n2AH = sym<__half>(g_n2A_h), *n2AL = sym<__half>(g_n2A_l);
    __half *aW2H = sym<__half>(g_aW2_h), *aW2L = sym<__half>(g_aW2_l);
    __half *oWH = sym<__half>(g_oW_h), *oWL = sym<__half>(g_oW_l);
    __half *HsAH = sym<__half>(g_HsA_h), *HsAL = sym<__half>(g_HsA_l);
    __half *Wa1H = sym<__half>(g_Wa1_h), *Wa1L = sym<__half>(g_Wa1_l);
    __half *Wc1H = sym<__half>(g_Wc1_h), *Wc1L = sym<__half>(g_Wc1_l);
    __half *Wc2H = sym<__half>(g_Wc2_h), *Wc2L = sym<__half>(g_Wc2_l);
    __half *MtH = sym<__half>(g_Mt_h), *MtL = sym<__half>(g_Mt_l);
    __half *idH = sym<__half>(g_id_h), *idL = sym<__half>(g_id_l);
    __half *n1xH = sym<__half>(g_n1x_h), *n1xL = sym<__half>(g_n1x_l);
    __half *eoH = sym<__half>(g_eo_h), *eoL = sym<__half>(g_eo_l);

    cudaFuncSetAttribute(gemm_tc<2>, cudaFuncAttributeMaxDynamicSharedMemorySize, GEMM_SMEM);
    cudaFuncSetAttribute(gemm_tc<3>, cudaFuncAttributeMaxDynamicSharedMemorySize, GEMM_SMEM);
    cudaFuncSetAttribute(dec_kernel, cudaFuncAttributeMaxDynamicSharedMemorySize, DEC_SMEM);

    const int GYE = (KP_E + 2047) / 2048, GYH = 1, GYNZ = (KP_NZ + 2047) / 2048;
    constexpr int NCH_E = KP_E / 32, NCH_NZ = KP_NZ / 32, NCH_H = KP_H / 32;

    // ---- launches 1-5 (so gemm_tc is 6th -> ncu -s 5 -c 1 captures it) ----
    conv8<true><<<dim3(1024, GYE), 256>>>(in_input, E, T, AinH, AinL, 1024, E, KP_E);
    conv8<false><<<dim3(4096, GYE), 256>>>(enc_Wih, E, 0, WihH, WihL, G4, E, KP_E);
    bias_sum<<<(G4 + 255) / 256, 256>>>(enc_bih, enc_bhh, encb, G4);
    bias_sum<<<(G4 + 255) / 256, 256>>>(dec_bih, dec_bhh, decb, G4);
    calc_v<<<H, 256>>>(out_b, emb_W, v);

    // ---- launch 6: pre_enc GEMM (2-term fp16, split-K SL=8) ----
    {
        constexpr int SL = 8, CPS = (NCH_E + SL - 1) / SL;
        gemm_tc<2><<<dim3(16, 8, SL), 256, GEMM_SMEM>>>(AinH, AinL, WihH, WihL, KP_E,
                                                        nullptr, kpart, G4, T * B, G4, CPS, 1);
        reduce_k<<<(int)(((size_t)T * B * G4 + 255) / 256), 256>>>(
            kpart, encb, nullptr, pre, T * B, G4, G4, SL, 0);
    }

    // ---- init + remaining conversions ----
    cudaMemsetAsync(hb, 0, B * H * sizeof(float));
    cudaMemsetAsync(c, 0, B * H * sizeof(float));
    conv8<false><<<dim3(1024, GYE), 256>>>(emb_W, EMB_LD, 0, eWEH, eWEL, H, E, KP_E);
    conv_trans<<<dim3((KP_E + 31) / 32, 32), dim3(32, 8)>>>(out_W, H, oWtH, oWtL, E, H, KP_E, 1024);
    conv8<false><<<dim3(512, GYNZ), 256>>>(noise1, NZ, 0, n1AH, n1AL, 512, NZ, KP_NZ);
    conv8<false><<<dim3(1024, GYNZ), 256>>>(emb_W + E, EMB_LD, 0, eWNH, eWNL, H, NZ, KP_NZ);
    conv8<false><<<dim3(512, GYH), 256>>>(noise2, H, 0, n2AH, n2AL, 512, H, KP_H);
    conv8<false><<<dim3(256, GYH), 256>>>(attn_W + 2 * H, ATTN_LD, 0, aW2H, aW2L, T, H, KP_H);
    conv8<false><<<dim3(30720, GYH), 256>>>(out_W, H, 0, oWH, oWL, E, H, KP_H);
    conv8<false><<<dim3(256, GYH), 256>>>(attn_W, ATTN_LD, 0, Wa1H, Wa1L, T, H, KP_H);
    conv8<false><<<dim3(1024, GYH), 256>>>(comb_W, COMB_LD, 0, Wc1H, Wc1L, H, H, KP_H);
    conv8<false><<<dim3(1024, GYH), 256>>>(comb_W + H, COMB_LD, 0, Wc2H, Wc2L, H, H, KP_H);
    conv8<false><<<dim3(128, GYE), 256>>>(init_dec, E, 0, idH, idL, 8, E, KP_E);

    // ---- precompute GEMMs ----
    {   // Mmat = emb_W_E @ out_W   (2-term fp16)
        constexpr int SL = 4, CPS = (NCH_E + SL - 1) / SL;
        gemm_tc<2><<<dim3(4, 8, SL), 256, GEMM_SMEM>>>(eWEH, eWEL, oWtH, oWtL, KP_E,
                                                       nullptr, kpart, H, H, H, CPS, 1);
        reduce_k<<<(H * H + 255) / 256, 256>>>(kpart, nullptr, nullptr, Mm, H, H, H, SL, 0);
    }
    conv_trans<<<dim3((KP_H + 31) / 32, 32), dim3(32, 8)>>>(Mm, H, MtH, MtL, H, H, KP_H, 1024);
    {   // A1M = Wa1 @ M  (3-term)
        constexpr int SL = 8, CPS = (NCH_H + SL - 1) / SL;
        gemm_tc<3><<<dim3(4, 1, SL), 256, GEMM_SMEM>>>(Wa1H, Wa1L, MtH, MtL, KP_H,
                                                       nullptr, kpart, H, T, H, CPS, 1);
        reduce_k<<<(T * H + 255) / 256, 256>>>(kpart, nullptr, nullptr, A1M, T, H, H, SL, 0);
        make_WA<<<(T * H + 255) / 256, 256>>>(A1M, attn_W, WA);
    }
    {   // C1M = Wc1 @ M  (3-term)
        constexpr int SL = 4, CPS = (NCH_H + SL - 1) / SL;
        gemm_tc<3><<<dim3(4, 8, SL), 256, GEMM_SMEM>>>(Wc1H, Wc1L, MtH, MtL, KP_H,
                                                       nullptr, kpart, H, H, H, CPS, 1);
        reduce_k<<<(H * H + 255) / 256, 256>>>(kpart, nullptr, nullptr, C1M, H, H, H, SL, 0);
    }
    {   // n1pre = noise1 @ emb_W_N^T + emb_b  (3-term)
        constexpr int SL = 8, CPS = (NCH_NZ + SL - 1) / SL;
        gemm_tc<3><<<dim3(4, 4, SL), 256, GEMM_SMEM>>>(n1AH, n1AL, eWNH, eWNL, KP_NZ,
                                                       nullptr, kpart, H, S * B, H, CPS, 1);
        reduce_k<<<(S * B * H + 255) / 256, 256>>>(kpart, emb_b, nullptr, n1p, S * B, H, H, SL, 0);
    }
    {   // emb0 = init_dec @ emb_W_E^T  (3-term)
        constexpr int SL = 8, CPS = (NCH_E + SL - 1) / SL;
        gemm_tc<3><<<dim3(4, 1, SL), 256, GEMM_SMEM>>>(idH, idL, eWEH, eWEL, KP_E,
                                                       nullptr, kpart, H, 8, H, CPS, 1);
        reduce_k<<<(8 * H + 255) / 256, 256>>>(kpart, nullptr, nullptr, emb0, 8, H, H, SL, 0);
    }
    make_n1x<<<(S * B * H + 255) / 256, 256>>>(n1p, emb0, v, n1x);
    conv8<false><<<dim3(512, GYH), 256>>>(n1x, H, 0, n1xH, n1xL, S * B, H, KP_H);
    {   // n2pre = noise2 @ Wa3^T + attn_b  (3-term)
        constexpr int SL = 8, CPS = (NCH_H + SL - 1) / SL;
        gemm_tc<3><<<dim3(1, 4, SL), 256, GEMM_SMEM>>>(n2AH, n2AL, aW2H, aW2L, KP_H,
                                                       nullptr, kpart, T, S * B, T, CPS, 1);
        reduce_k<<<(S * B * T + 255) / 256, 256>>>(kpart, attn_b, nullptr, n2p, S * B, T, T, SL, 0);
    }
    {   // pre_a = n1x @ Wa1^T + n2pre  (3-term)
        constexpr int SL = 8, CPS = (NCH_H + SL - 1) / SL;
        gemm_tc<3><<<dim3(1, 4, SL), 256, GEMM_SMEM>>>(n1xH, n1xL, Wa1H, Wa1L, KP_H,
                                                       nullptr, kpart, T, S * B, T, CPS, 1);
        reduce_k<<<(S * B * T + 255) / 256, 256>>>(kpart, nullptr, n2p, pre_a, S * B, T, T, SL, 0);
    }
    {   // pre_c = n1x @ Wc1^T + comb_b  (3-term)
        constexpr int SL = 8, CPS = (NCH_H + SL - 1) / SL;
        gemm_tc<3><<<dim3(4, 4, SL), 256, GEMM_SMEM>>>(n1xH, n1xL, Wc1H, Wc1L, KP_H,
                                                       nullptr, kpart, H, S * B, H, CPS, 1);
        reduce_k<<<(S * B * H + 255) / 256, 256>>>(kpart, comb_b, nullptr, pre_c, S * B, H, H, SL, 0);
    }

    // ---- encoder ----
    enc_kernel<<<NCTA, 256>>>(enc_Whh);

    // ---- enc2T = (enc_out @ Wc2^T) in [b][j][t] layout  (3-term) ----
    conv8<false><<<dim3(1024, GYH), 256>>>(enc_out, H, 0, eoH, eoL, T * B, H, KP_H);
    {
        constexpr int SL = 4, CPS = (NCH_H + SL - 1) / SL;
        gemm_tc<3><<<dim3(4, 8, SL), 256, GEMM_SMEM>>>(eoH, eoL, Wc2H, Wc2L, KP_H,
                                                       nullptr, kpart, H, T * B, H, CPS, 1);
        reduce_k<<<(T * B * H + 255) / 256, 256>>>(kpart, nullptr, nullptr, enc2T,
                                                   T * B, H, H, SL, 1);
    }

    // ---- decoder ----
    dec_kernel<<<NCTA, 256, DEC_SMEM>>>(dec_Wih, dec_Whh, attn_W);

    // ---- final: out = Hs @ out_W^T + out_b (2-term fp16, split-K SL=2) ----
    conv8<false><<<dim3(512, GYH), 256>>>(Hs, H, 0, HsAH, HsAL, S * B, H, KP_H);
    {
        constexpr int SL = 2, CPS = (NCH_H + SL - 1) / SL;
        gemm_tc<2><<<dim3(120, 4, SL), 256, GEMM_SMEM>>>(HsAH, HsAL, oWH, oWL, KP_H,
                                                         nullptr, kpart, E, S * B, E, CPS, 1);
        reduce_k<<<(int)(((size_t)S * B * E + 255) / 256), 256>>>(
            kpart, out_b, nullptr, out, S * B, E, E, SL, 0);
    }
}

// round 15
// speedup vs baseline: 5.8614x; 1.1086x over previous
#include <cuda_runtime.h>
#include <cuda_bf16.h>
#include <cuda_fp16.h>
#include <math.h>

// Problem dims (fixed by setup_inputs)
constexpr int B = 8;
constexpr int T = 128;
constexpr int E = 30522;
constexpr int H = 1000;
constexpr int S = 64;
constexpr int NZ = 10000;
constexpr int G4 = 4 * H;          // 4000
constexpr int EMB_LD = E + NZ;     // 40522
constexpr int ATTN_LD = 3 * H;     // 3000
constexpr int COMB_LD = 2 * H;     // 2000
constexpr int NCTA = 148;

constexpr int KP_E  = 30528;       // E padded to 64
constexpr int KP_NZ = 10048;       // NZ padded to 64
constexpr int KP_H  = 1024;        // H padded to 64

// ---------------- fp32 scratch ----------------
__device__ float g_pre_enc[T * B * G4];
__device__ float g_enc_out[T * B * H];
__device__ float g_Mmat[H * H];
__device__ float g_n1pre[S * B * H];
__device__ float g_n2pre[S * B * T];
__device__ float g_Hs[S * B * H];
__device__ float g_hbuf[2][B * H];
__device__ float g_c[B * H];
__device__ float g_attn[B * T];
__device__ float g_comb[B * H];
__device__ float g_encbias[G4];
__device__ float g_decbias[G4];
__device__ float g_v[H];
__device__ float g_kpart[33000000];         // split-K partials (131 MB)
__device__ float g_WA[T * H];               // Wa1@M + Wa2
__device__ float g_A1M[T * H];
__device__ float g_C1M[H * H];
__device__ float g_pre_a[S * B * T];
__device__ float g_pre_c[S * B * H];
__device__ float g_n1x[S * B * H];
__device__ float g_emb0[B * H];
__device__ float g_enc2T[B * H * T];        // [b][j][t]
__device__ unsigned g_bar_arrive;
__device__ unsigned g_bar_gen;

// ---------------- fp16 hi/lo operand buffers (padded) ----------------
__device__ __half g_Ain_h[1024 * KP_E],  g_Ain_l[1024 * KP_E];
__device__ __half g_Wih_h[4096 * KP_E],  g_Wih_l[4096 * KP_E];
__device__ __half g_eWE_h[1024 * KP_E],  g_eWE_l[1024 * KP_E];
__device__ __half g_oWt_h[1024 * KP_E],  g_oWt_l[1024 * KP_E];
__device__ __half g_n1A_h[512 * KP_NZ],  g_n1A_l[512 * KP_NZ];
__device__ __half g_eWN_h[1024 * KP_NZ], g_eWN_l[1024 * KP_NZ];
__device__ __half g_n2A_h[512 * KP_H],   g_n2A_l[512 * KP_H];
__device__ __half g_aW2_h[256 * KP_H],   g_aW2_l[256 * KP_H];
__device__ __half g_oW_h[30720 * KP_H],  g_oW_l[30720 * KP_H];
__device__ __half g_HsA_h[512 * KP_H],   g_HsA_l[512 * KP_H];
__device__ __half g_Wa1_h[256 * KP_H],   g_Wa1_l[256 * KP_H];
__device__ __half g_Wc1_h[1024 * KP_H],  g_Wc1_l[1024 * KP_H];
__device__ __half g_Wc2_h[1024 * KP_H],  g_Wc2_l[1024 * KP_H];
__device__ __half g_Mt_h[1024 * KP_H],   g_Mt_l[1024 * KP_H];
__device__ __half g_id_h[128 * KP_E],    g_id_l[128 * KP_E];
__device__ __half g_n1x_h[512 * KP_H],   g_n1x_l[512 * KP_H];
__device__ __half g_eo_h[1024 * KP_H],   g_eo_l[1024 * KP_H];

// ---------------- helpers ----------------
__device__ __forceinline__ unsigned s2u(const void* p) {
    unsigned a;
    asm("{ .reg .u64 t; cvta.to.shared.u64 t, %1; cvt.u32.u64 %0, t; }"
        : "=r"(a) : "l"(p));
    return a;
}
__device__ __forceinline__ void cp16(unsigned dst, const void* src) {
    asm volatile("cp.async.cg.shared.global [%0], [%1], 16;" :: "r"(dst), "l"(src)
                 : "memory");
}
__device__ __forceinline__ void cp_commit() {
    asm volatile("cp.async.commit_group;" ::: "memory");
}
template <int N>
__device__ __forceinline__ void cp_wait() {
    asm volatile("cp.async.wait_group %0;" :: "n"(N) : "memory");
}
__device__ __forceinline__ void mma_f16(float* c, const unsigned* a, const unsigned* b) {
    asm volatile(
        "mma.sync.aligned.m16n8k16.row.col.f32.f16.f16.f32 "
        "{%0,%1,%2,%3}, {%4,%5,%6,%7}, {%8,%9}, {%0,%1,%2,%3};"
        : "+f"(c[0]), "+f"(c[1]), "+f"(c[2]), "+f"(c[3])
        : "r"(a[0]), "r"(a[1]), "r"(a[2]), "r"(a[3]), "r"(b[0]), "r"(b[1]));
}

// ---------------- vectorized converter: 8 cols/thread, fp16 hi/lo ----------
// WLO=false skips the lo-buffer store (for operands only used in 1/2-term GEMMs).
template <bool SWIZ, bool WLO>
__global__ void conv8(const float* __restrict__ src, int ldS, int swizT,
                      __half* __restrict__ dh,
                      __half* __restrict__ dl,
                      int Mr, int Kr, int Kpad) {
    int row = blockIdx.x;
    int c0 = (blockIdx.y * 256 + threadIdx.x) * 8;
    if (c0 >= Kpad) return;
    const float* sp = nullptr;
    if (row < Mr) {
        int r = SWIZ ? ((row & 7) * swizT + (row >> 3)) : row;
        sp = src + (size_t)r * ldS;
    }
    float x[8];
#pragma unroll
    for (int i = 0; i < 8; i++) {
        int col = c0 + i;
        x[i] = (sp && col < Kr) ? sp[col] : 0.f;
    }
    unsigned hw[4], lw[4];
#pragma unroll
    for (int p = 0; p < 4; p++) {
        __half h0 = __float2half_rn(x[2 * p]);
        __half h1 = __float2half_rn(x[2 * p + 1]);
        hw[p] = (unsigned)__half_as_ushort(h0) | ((unsigned)__half_as_ushort(h1) << 16);
        if (WLO) {
            __half l0 = __float2half_rn(x[2 * p] - __half2float(h0));
            __half l1 = __float2half_rn(x[2 * p + 1] - __half2float(h1));
            lw[p] = (unsigned)__half_as_ushort(l0) | ((unsigned)__half_as_ushort(l1) << 16);
        }
    }
    *(uint4*)(dh + (size_t)row * Kpad + c0) = make_uint4(hw[0], hw[1], hw[2], hw[3]);
    if (WLO)
        *(uint4*)(dl + (size_t)row * Kpad + c0) = make_uint4(lw[0], lw[1], lw[2], lw[3]);
}

// dst[n][k] = src[k][n]
__global__ void conv_trans(const float* __restrict__ src, int ldS,
                           __half* __restrict__ dh,
                           __half* __restrict__ dl,
                           int Kr, int Nr, int Kpad, int Npad) {
    __shared__ float tile[32][33];
    int kb = blockIdx.x * 32, nb = blockIdx.y * 32;
    int tx = threadIdx.x, ty = threadIdx.y;   // 32 x 8
    for (int i = ty; i < 32; i += 8) {
        int k = kb + i, n = nb + tx;
        tile[i][tx] = (k < Kr && n < Nr) ? src[(size_t)k * ldS + n] : 0.f;
    }
    __syncthreads();
    for (int i = ty; i < 32; i += 8) {
        int n = nb + i, k = kb + tx;
        if (n < Npad && k < Kpad) {
            float x = tile[tx][i];
            __half h = __float2half_rn(x);
            dh[(size_t)n * Kpad + k] = h;
            dl[(size_t)n * Kpad + k] = __float2half_rn(x - __half2float(h));
        }
    }
}

// ---------------- mma.sync GEMM, fp16 hi/lo, 3-stage cp.async, split-K ------
// NTERMS==3: C = Ah·Bh + Al·Bh + Ah·Bl   (error ~2^-24)
// NTERMS==2: C = Ah·Bh + Al·Bh           (B truncation, ~1.4e-4 RMS)
// NTERMS==1: C = Ah·Bh                   (A+B truncation, ~2e-4 RMS)
constexpr int ST_W = 20 * (128 + 128 + 256 + 256);   // 15360 words
constexpr int ST_BYTES = ST_W * 4;
constexpr int GEMM_SMEM = 3 * ST_BYTES;

template <int NTERMS>
__global__ void __launch_bounds__(256, 1)
gemm_tc(const __half* __restrict__ Ah, const __half* __restrict__ Al,
        const __half* __restrict__ Bh, const __half* __restrict__ Bl,
        int Kpad, const float* __restrict__ bias,
        float* __restrict__ C, int ldC, int M, int N, int cps, int partial) {
    extern __shared__ unsigned sm[];
    const unsigned sbase = s2u(sm);
    const int tid = threadIdx.x;
    const int wid = tid >> 5, lane = tid & 31;
    const int g = lane >> 2, tq = lane & 3;
    const int wm = wid & 1, wn = wid >> 1;
    const int m0 = blockIdx.y * 128, n0 = blockIdx.x * 256;
    const int nch = Kpad / 32;
    const int z = blockIdx.z;
    const int c0 = z * cps;
    const int c1 = min(nch, c0 + cps);

    float acc[4][8][4];
#pragma unroll
    for (int i = 0; i < 4; i++)
#pragma unroll
        for (int j = 0; j < 8; j++)
#pragma unroll
            for (int q = 0; q < 4; q++) acc[i][j][q] = 0.f;

    auto load_stage = [&](int st, int ci) {
        unsigned sb = sbase + st * ST_BYTES;
        int k0 = ci * 32;
        constexpr int NQ = (NTERMS == 3) ? 12 : (NTERMS == 2 ? 8 : 6);
#pragma unroll
        for (int q = 0; q < NQ; q++) {
            int it = tid + q * 256;
            const __half* gp;
            unsigned dw;
            if (NTERMS == 1) {
                if (it < 512) {
                    int r = it >> 2, c = it & 3;
                    gp = Ah + (size_t)(m0 + r) * Kpad + k0 + c * 8;
                    dw = r * 20 + c * 4;
                } else {
                    int idx = it - 512, r = idx >> 2, c = idx & 3;
                    gp = Bh + (size_t)(n0 + r) * Kpad + k0 + c * 8;
                    dw = 5120u + r * 20 + c * 4;
                }
            } else {
                if (it < 1024) {
                    int idx = it & 511, r = idx >> 2, c = idx & 3;
                    gp = (it < 512 ? Ah : Al) + (size_t)(m0 + r) * Kpad + k0 + c * 8;
                    dw = (it < 512 ? 0u : 2560u) + r * 20 + c * 4;
                } else {
                    int idx = (it - 1024) & 1023, r = idx >> 2, c = idx & 3;
                    gp = (it < 2048 ? Bh : Bl) + (size_t)(n0 + r) * Kpad + k0 + c * 8;
                    dw = (it < 2048 ? 5120u : 10240u) + r * 20 + c * 4;
                }
            }
            cp16(sb + dw * 4, gp);
        }
        cp_commit();
    };

    if (c0 < c1)     load_stage(0, c0);
    if (c0 + 1 < c1) load_stage(1, c0 + 1);

    for (int ci = c0; ci < c1; ci++) {
        int st = (ci - c0) % 3;
        if (ci == c1 - 1) cp_wait<0>(); else cp_wait<1>();
        __syncthreads();
        if (ci + 2 < c1) load_stage((ci - c0 + 2) % 3, ci + 2);

        const unsigned b0 = st * ST_W;
#pragma unroll
        for (int ks = 0; ks < 2; ks++) {
            int ws = ks * 8 + tq;
            unsigned ahf[4][4], alf[4][4];
#pragma unroll
            for (int i = 0; i < 4; i++) {
                int am = wm * 64 + i * 16 + g;
                ahf[i][0] = sm[b0 + am * 20 + ws];
                ahf[i][1] = sm[b0 + (am + 8) * 20 + ws];
                ahf[i][2] = sm[b0 + am * 20 + ws + 4];
                ahf[i][3] = sm[b0 + (am + 8) * 20 + ws + 4];
                if (NTERMS >= 2) {
                    alf[i][0] = sm[b0 + 2560 + am * 20 + ws];
                    alf[i][1] = sm[b0 + 2560 + (am + 8) * 20 + ws];
                    alf[i][2] = sm[b0 + 2560 + am * 20 + ws + 4];
                    alf[i][3] = sm[b0 + 2560 + (am + 8) * 20 + ws + 4];
                }
            }
#pragma unroll
            for (int jh = 0; jh < 2; jh++) {
                unsigned bhf[4][2], blf[4][2];
#pragma unroll
                for (int j = 0; j < 4; j++) {
                    int bn = wn * 64 + jh * 32 + j * 8 + g;
                    bhf[j][0] = sm[b0 + 5120 + bn * 20 + ws];
                    bhf[j][1] = sm[b0 + 5120 + bn * 20 + ws + 4];
                    if (NTERMS == 3) {
                        blf[j][0] = sm[b0 + 10240 + bn * 20 + ws];
                        blf[j][1] = sm[b0 + 10240 + bn * 20 + ws + 4];
                    }
                }
#pragma unroll
                for (int i = 0; i < 4; i++)
#pragma unroll
                    for (int j = 0; j < 4; j++)
                        mma_f16(acc[i][jh * 4 + j], ahf[i], bhf[j]);
                if (NTERMS >= 2) {
#pragma unroll
                    for (int i = 0; i < 4; i++)
#pragma unroll
                        for (int j = 0; j < 4; j++)
                            mma_f16(acc[i][jh * 4 + j], alf[i], bhf[j]);
                }
                if (NTERMS == 3) {
#pragma unroll
                    for (int i = 0; i < 4; i++)
#pragma unroll
                        for (int j = 0; j < 4; j++)
                            mma_f16(acc[i][jh * 4 + j], ahf[i], blf[j]);
                }
            }
        }
        __syncthreads();
    }

    float* Cb = partial ? (C + (size_t)z * M * N) : C;
    const int ld = partial ? N : ldC;
#pragma unroll
    for (int i = 0; i < 4; i++) {
        int rr0 = m0 + wm * 64 + i * 16 + g;
#pragma unroll
        for (int j = 0; j < 8; j++) {
            int cc = n0 + wn * 64 + j * 8 + tq * 2;
#pragma unroll
            for (int q = 0; q < 4; q++) {
                int rr = rr0 + (q >> 1) * 8;
                int cn = cc + (q & 1);
                if (rr < M && cn < N) {
                    float v = acc[i][j][q];
                    if (!partial && bias) v += bias[cn];
                    Cb[(size_t)rr * ld + cn] = v;
                }
            }
        }
    }
}

// deterministic split-K reduce. emode 0: out[m*ldC+n]; 1: enc2T layout.
__global__ void reduce_k(const float* __restrict__ part,
                         const float* __restrict__ bias,
                         const float* __restrict__ add,
                         float* __restrict__ out,
                         int M, int N, int ldC, int slices, int emode) {
    size_t idx = (size_t)blockIdx.x * 256 + threadIdx.x;
    if (idx >= (size_t)M * N) return;
    int m = (int)(idx / N), n = (int)(idx - (size_t)m * N);
    float v = bias ? bias[n] : 0.f;
    if (add) v += add[idx];
    for (int z = 0; z < slices; z++) v += part[(size_t)z * M * N + idx];
    if (emode == 1) out[((size_t)(m & 7) * H + n) * T + (m >> 3)] = v;
    else out[(size_t)m * ldC + n] = v;
}

// ---------------- persistent kernels ----------------
__device__ __forceinline__ void grid_barrier() {
    __threadfence();
    __syncthreads();
    if (threadIdx.x == 0) {
        unsigned gen = atomicAdd(&g_bar_gen, 0u);
        if (atomicAdd(&g_bar_arrive, 1u) == gridDim.x - 1) {
            g_bar_arrive = 0;
            __threadfence();
            atomicAdd(&g_bar_gen, 1u);
        } else {
            volatile unsigned* vg = &g_bar_gen;
            while (*vg == gen) { }
        }
    }
    __syncthreads();
}
__device__ __forceinline__ float wsum(float v) {
#pragma unroll
    for (int off = 16; off; off >>= 1) v += __shfl_xor_sync(0xFFFFFFFFu, v, off);
    return v;
}
__device__ __forceinline__ float sigm(float x) { return 1.f / (1.f + expf(-x)); }
__device__ __forceinline__ void stage8k(float* xs, const float* src) {
    const float4* s4 = reinterpret_cast<const float4*>(src);
    float4* d4 = reinterpret_cast<float4*>(xs);
    for (int i = threadIdx.x; i < B * H / 4; i += 256) d4[i] = s4[i];
}
__device__ __forceinline__ float dot4(float4 a, float4 b) {
    return a.x * b.x + a.y * b.y + a.z * b.z + a.w * b.w;
}

__global__ void __launch_bounds__(256, 1)
enc_kernel(const float* __restrict__ enc_Whh) {
    __shared__ __align__(16) float xs[B][H];
    const int ct = blockIdx.x, tid = threadIdx.x;
    const int w = tid >> 5, lane = tid & 31;
    const int j = ct + NCTA * w;
    const bool own = (w < 7) && (j < H);

    for (int t = 0; t < T; t++) {
        stage8k(xs[0], g_hbuf[t & 1]);
        __syncthreads();
        float acc[4][8];
#pragma unroll
        for (int ga = 0; ga < 4; ga++)
#pragma unroll
            for (int b = 0; b < 8; b++) acc[ga][b] = 0.f;
        if (own) {
#pragma unroll
            for (int kb = 0; kb < 8; kb++) {
                int kk = kb * 128 + lane * 4;
                if (kk < H) {
                    float4 xv[8];
#pragma unroll
                    for (int b = 0; b < 8; b++)
                        xv[b] = *reinterpret_cast<const float4*>(&xs[b][kk]);
#pragma unroll
                    for (int ga = 0; ga < 4; ga++) {
                        float4 wv = *reinterpret_cast<const float4*>(
                            &enc_Whh[(size_t)(ga * H + j) * H + kk]);
#pragma unroll
                        for (int b = 0; b < 8; b++) acc[ga][b] += dot4(wv, xv[b]);
                    }
                }
            }
        }
#pragma unroll
        for (int ga = 0; ga < 4; ga++)
#pragma unroll
            for (int b = 0; b < 8; b++) acc[ga][b] = wsum(acc[ga][b]);
        if (own && lane < 8) {
            int b = lane;
            const float* pre = g_pre_enc + (t * 8 + b) * G4;
            float gi = sigm(acc[0][b] + pre[j]);
            float gf = sigm(acc[1][b] + pre[H + j]);
            float gg = tanhf(acc[2][b] + pre[2 * H + j]);
            float go = sigm(acc[3][b] + pre[3 * H + j]);
            float cn = gf * g_c[b * H + j] + gi * gg;
            g_c[b * H + j] = cn;
            float hn = go * tanhf(cn);
            g_hbuf[(t + 1) & 1][b * H + j] = hn;
            g_enc_out[t * (B * H) + b * H + j] = hn;
        }
        grid_barrier();
    }
}

// decoder: 3 phases/step. dynamic smem: xs(h) 8000f | cs(comb) 8000f | aw 1024f
constexpr int DEC_SMEM = (8000 + 8000 + 1024) * 4;

__global__ void __launch_bounds__(256, 1)
dec_kernel(const float* __restrict__ dec_Wih,
           const float* __restrict__ dec_Whh,
           const float* __restrict__ attn_W) {
    extern __shared__ __align__(16) float dsm[];
    float* xs = dsm;             // [8][1000] h
    float* cs = dsm + 8000;      // [8][1000] comb
    float* aw = dsm + 16000;     // [8][128]

    const int ct = blockIdx.x, tid = threadIdx.x;
    const int w = tid >> 5, lane = tid & 31;
    const int j = ct + NCTA * w;
    const bool own = (w < 7) && (j < H);

    for (int s = 0; s < S; s++) {
        stage8k(xs, g_hbuf[s & 1]);
        __syncthreads();

        // ---- phase A: rc = C1M@h partials; attn logits ----
        float rc[8];
#pragma unroll
        for (int b = 0; b < 8; b++) rc[b] = 0.f;
        if (s > 0 && own) {
#pragma unroll
            for (int kb = 0; kb < 8; kb++) {
                int kk = kb * 128 + lane * 4;
                if (kk < H) {
                    float4 cw = *reinterpret_cast<const float4*>(&g_C1M[(size_t)j * H + kk]);
#pragma unroll
                    for (int b = 0; b < 8; b++)
                        rc[b] += dot4(cw, *reinterpret_cast<const float4*>(&xs[b * H + kk]));
                }
            }
        }
        if (ct < T) {
            int tp = ct, b = w;
            float acc = 0.f;
            if (s == 0) {
#pragma unroll
                for (int kb = 0; kb < 8; kb++) {
                    int kk = kb * 128 + lane * 4;
                    if (kk < H) {
                        float4 wv = *reinterpret_cast<const float4*>(
                            &attn_W[(size_t)tp * ATTN_LD + H + kk]);
                        acc += dot4(wv, *reinterpret_cast<const float4*>(&xs[b * H + kk]));
                    }
                }
            } else {
#pragma unroll
                for (int kb = 0; kb < 8; kb++) {
                    int kk = kb * 128 + lane * 4;
                    if (kk < H) {
                        float4 wv = *reinterpret_cast<const float4*>(&g_WA[(size_t)tp * H + kk]);
                        acc += dot4(wv, *reinterpret_cast<const float4*>(&xs[b * H + kk]));
                    }
                }
            }
            acc = wsum(acc);
            if (lane == 0)
                g_attn[b * T + tp] = acc + g_pre_a[(s * 8 + b) * T + tp];
        }
        grid_barrier();

        // ---- phase B: local softmax + comb ----
        {
            int b = w;
            float vx[4];
#pragma unroll
            for (int q = 0; q < 4; q++) vx[q] = g_attn[b * T + lane + 32 * q];
            float m = fmaxf(fmaxf(vx[0], vx[1]), fmaxf(vx[2], vx[3]));
#pragma unroll
            for (int off = 16; off; off >>= 1)
                m = fmaxf(m, __shfl_xor_sync(0xFFFFFFFFu, m, off));
            float e[4], ssum = 0.f;
#pragma unroll
            for (int q = 0; q < 4; q++) { e[q] = expf(vx[q] - m); ssum += e[q]; }
            ssum = wsum(ssum);
            float inv = 1.f / ssum;
#pragma unroll
            for (int q = 0; q < 4; q++) aw[b * T + lane + 32 * q] = e[q] * inv;
        }
        __syncthreads();
        if (own) {
#pragma unroll
            for (int b = 0; b < 8; b++) {
                const float* e2 = g_enc2T + ((size_t)b * H + j) * T;
                float a = 0.f;
#pragma unroll
                for (int it = 0; it < 4; it++)
                    a += aw[b * T + lane + 32 * it] * e2[lane + 32 * it];
                rc[b] += a;
            }
#pragma unroll
            for (int b = 0; b < 8; b++) rc[b] = wsum(rc[b]);
            if (lane < 8) {
                int b = lane;
                g_comb[b * H + j] = fmaxf(rc[b] + g_pre_c[(s * 8 + b) * H + j], 0.f);
            }
        }
        grid_barrier();

        // ---- phase C: gates + LSTM ----
        stage8k(cs, g_comb);
        __syncthreads();
        float acc4[4][8];
#pragma unroll
        for (int ga = 0; ga < 4; ga++)
#pragma unroll
            for (int b = 0; b < 8; b++) acc4[ga][b] = 0.f;
        if (own) {
#pragma unroll
            for (int kb = 0; kb < 8; kb++) {
                int kk = kb * 128 + lane * 4;
                if (kk < H) {
                    float4 cv[8], hv[8];
#pragma unroll
                    for (int b = 0; b < 8; b++) {
                        cv[b] = *reinterpret_cast<const float4*>(&cs[b * H + kk]);
                        hv[b] = *reinterpret_cast<const float4*>(&xs[b * H + kk]);
                    }
#pragma unroll
                    for (int ga = 0; ga < 4; ga++) {
                        float4 wih = *reinterpret_cast<const float4*>(
                            &dec_Wih[(size_t)(ga * H + j) * H + kk]);
                        float4 whh = *reinterpret_cast<const float4*>(
                            &dec_Whh[(size_t)(ga * H + j) * H + kk]);
#pragma unroll
                        for (int b = 0; b < 8; b++)
                            acc4[ga][b] += dot4(wih, cv[b]) + dot4(whh, hv[b]);
                    }
                }
            }
        }
#pragma unroll
        for (int ga = 0; ga < 4; ga++)
#pragma unroll
            for (int b = 0; b < 8; b++) acc4[ga][b] = wsum(acc4[ga][b]);
        if (own && lane < 8) {
            int b = lane;
            float gi = sigm(acc4[0][b] + g_decbias[j]);
            float gf = sigm(acc4[1][b] + g_decbias[H + j]);
            float gg = tanhf(acc4[2][b] + g_decbias[2 * H + j]);
            float go = sigm(acc4[3][b] + g_decbias[3 * H + j]);
            float cn = gf * g_c[b * H + j] + gi * gg;
            g_c[b * H + j] = cn;
            float hn = go * tanhf(cn);
            g_hbuf[(s + 1) & 1][b * H + j] = hn;
            g_Hs[s * (B * H) + b * H + j] = hn;
        }
        grid_barrier();
    }
}

// ---------------- tiny kernels ----------------
__global__ void bias_sum(const float* __restrict__ a, const float* __restrict__ b,
                         float* __restrict__ o, int n) {
    int i = blockIdx.x * blockDim.x + threadIdx.x;
    if (i < n) o[i] = a[i] + b[i];
}
__global__ void calc_v(const float* __restrict__ out_b, const float* __restrict__ emb_W,
                       float* __restrict__ v) {
    int j = blockIdx.x;
    const float* row = emb_W + (size_t)j * EMB_LD;
    float acc = 0.f;
    for (int e = threadIdx.x; e < E; e += 256) acc += out_b[e] * row[e];
    __shared__ float s[256];
    s[threadIdx.x] = acc;
    __syncthreads();
    for (int off = 128; off; off >>= 1) {
        if (threadIdx.x < off) s[threadIdx.x] += s[threadIdx.x + off];
        __syncthreads();
    }
    if (threadIdx.x == 0) v[j] = s[0];
}
__global__ void make_WA(const float* __restrict__ A1M, const float* __restrict__ attn_W,
                        float* __restrict__ WA) {
    int i = blockIdx.x * 256 + threadIdx.x;
    if (i >= T * H) return;
    int t = i / H, k = i - t * H;
    WA[i] = A1M[i] + attn_W[t * ATTN_LD + H + k];
}
__global__ void make_n1x(const float* __restrict__ n1p, const float* __restrict__ emb0,
                         const float* __restrict__ v, float* __restrict__ n1x) {
    int i = blockIdx.x * 256 + threadIdx.x;
    if (i >= S * B * H) return;
    int row = i / H, k = i - row * H;
    n1x[i] = n1p[i] + (row < 8 ? emb0[i] : v[k]);
}

// ---------------- host orchestration ----------------
template <typename Tp>
static Tp* sym(const void* symbol) {
    void* p;
    cudaGetSymbolAddress(&p, symbol);
    return (Tp*)p;
}

extern "C" void kernel_launch(void* const* d_in, const int* in_sizes, int n_in,
                              void* d_out, int out_size) {
    const float* in_input  = (const float*)d_in[0];
    const float* noise1    = (const float*)d_in[2];
    const float* noise2    = (const float*)d_in[3];
    const float* init_dec  = (const float*)d_in[4];
    const float* enc_Wih   = (const float*)d_in[5];
    const float* enc_Whh   = (const float*)d_in[6];
    const float* enc_bih   = (const float*)d_in[7];
    const float* enc_bhh   = (const float*)d_in[8];
    const float* dec_Wih   = (const float*)d_in[9];
    const float* dec_Whh   = (const float*)d_in[10];
    const float* dec_bih   = (const float*)d_in[11];
    const float* dec_bhh   = (const float*)d_in[12];
    const float* emb_W     = (const float*)d_in[13];
    const float* emb_b     = (const float*)d_in[14];
    const float* attn_W    = (const float*)d_in[15];
    const float* attn_b    = (const float*)d_in[16];
    const float* comb_W    = (const float*)d_in[17];
    const float* comb_b    = (const float*)d_in[18];
    const float* out_W     = (const float*)d_in[19];
    const float* out_b     = (const float*)d_in[20];
    float* out = (float*)d_out;

    float *pre = sym<float>(g_pre_enc), *Mm = sym<float>(g_Mmat),
          *n1p = sym<float>(g_n1pre), *n2p = sym<float>(g_n2pre),
          *Hs = sym<float>(g_Hs), *hb = sym<float>(g_hbuf), *c = sym<float>(g_c),
          *encb = sym<float>(g_encbias), *decb = sym<float>(g_decbias),
          *v = sym<float>(g_v), *kpart = sym<float>(g_kpart),
          *WA = sym<float>(g_WA), *A1M = sym<float>(g_A1M), *C1M = sym<float>(g_C1M),
          *pre_a = sym<float>(g_pre_a), *pre_c = sym<float>(g_pre_c),
          *n1x = sym<float>(g_n1x), *emb0 = sym<float>(g_emb0),
          *enc2T = sym<float>(g_enc2T), *enc_out = sym<float>(g_enc_out);
    __half *AinH = sym<__half>(g_Ain_h), *AinL = sym<__half>(g_Ain_l);
    __half *WihH = sym<__half>(g_Wih_h), *WihL = sym<__half>(g_Wih_l);
    __half *eWEH = sym<__half>(g_eWE_h), *eWEL = sym<__half>(g_eWE_l);
    __half *oWtH = sym<__half>(g_oWt_h), *oWtL = sym<__half>(g_oWt_l);
    __half *n1AH = sym<__half>(g_n1A_h), *n1AL = sym<__half>(g_n1A_l);
    __half *eWNH = sym<__half>(g_eWN_h), *eWNL = sym<__half>(g_eWN_l);
    __half *n2AH = sym<__half>(g_n2A_h), *n2AL = sym<__half>(g_n2A_l);
    __half *aW2H = sym<__half>(g_aW2_h), *aW2L = sym<__half>(g_aW2_l);
    __half *oWH = sym<__half>(g_oW_h), *oWL = sym<__half>(g_oW_l);
    __half *HsAH = sym<__half>(g_HsA_h), *HsAL = sym<__half>(g_HsA_l);
    __half *Wa1H = sym<__half>(g_Wa1_h), *Wa1L = sym<__half>(g_Wa1_l);
    __half *Wc1H = sym<__half>(g_Wc1_h), *Wc1L = sym<__half>(g_Wc1_l);
    __half *Wc2H = sym<__half>(g_Wc2_h), *Wc2L = sym<__half>(g_Wc2_l);
    __half *MtH = sym<__half>(g_Mt_h), *MtL = sym<__half>(g_Mt_l);
    __half *idH = sym<__half>(g_id_h), *idL = sym<__half>(g_id_l);
    __half *n1xH = sym<__half>(g_n1x_h), *n1xL = sym<__half>(g_n1x_l);
    __half *eoH = sym<__half>(g_eo_h), *eoL = sym<__half>(g_eo_l);

    cudaFuncSetAttribute(gemm_tc<1>, cudaFuncAttributeMaxDynamicSharedMemorySize, GEMM_SMEM);
    cudaFuncSetAttribute(gemm_tc<2>, cudaFuncAttributeMaxDynamicSharedMemorySize, GEMM_SMEM);
    cudaFuncSetAttribute(gemm_tc<3>, cudaFuncAttributeMaxDynamicSharedMemorySize, GEMM_SMEM);
    cudaFuncSetAttribute(dec_kernel, cudaFuncAttributeMaxDynamicSharedMemorySize, DEC_SMEM);

    const int GYE = (KP_E + 2047) / 2048, GYH = 1, GYNZ = (KP_NZ + 2047) / 2048;
    constexpr int NCH_E = KP_E / 32, NCH_NZ = KP_NZ / 32, NCH_H = KP_H / 32;

    // ---- launches 1-5 ----
    conv8<true, false><<<dim3(1024, GYE), 256>>>(in_input, E, T, AinH, AinL, 1024, E, KP_E);
    conv8<false, false><<<dim3(4096, GYE), 256>>>(enc_Wih, E, 0, WihH, WihL, G4, E, KP_E);
    bias_sum<<<(G4 + 255) / 256, 256>>>(enc_bih, enc_bhh, encb, G4);
    bias_sum<<<(G4 + 255) / 256, 256>>>(dec_bih, dec_bhh, decb, G4);
    calc_v<<<H, 256>>>(out_b, emb_W, v);

    // ---- launch 6: pre_enc GEMM (1-term fp16, split-K SL=8) ----
    {
        constexpr int SL = 8, CPS = (NCH_E + SL - 1) / SL;
        gemm_tc<1><<<dim3(16, 8, SL), 256, GEMM_SMEM>>>(AinH, AinL, WihH, WihL, KP_E,
                                                        nullptr, kpart, G4, T * B, G4, CPS, 1);
        reduce_k<<<(int)(((size_t)T * B * G4 + 255) / 256), 256>>>(
            kpart, encb, nullptr, pre, T * B, G4, G4, SL, 0);
    }

    // ---- init + remaining conversions ----
    cudaMemsetAsync(hb, 0, B * H * sizeof(float));
    cudaMemsetAsync(c, 0, B * H * sizeof(float));
    conv8<false, true><<<dim3(1024, GYE), 256>>>(emb_W, EMB_LD, 0, eWEH, eWEL, H, E, KP_E);
    conv_trans<<<dim3((KP_E + 31) / 32, 32), dim3(32, 8)>>>(out_W, H, oWtH, oWtL, E, H, KP_E, 1024);
    conv8<false, true><<<dim3(512, GYNZ), 256>>>(noise1, NZ, 0, n1AH, n1AL, 512, NZ, KP_NZ);
    conv8<false, true><<<dim3(1024, GYNZ), 256>>>(emb_W + E, EMB_LD, 0, eWNH, eWNL, H, NZ, KP_NZ);
    conv8<false, true><<<dim3(512, GYH), 256>>>(noise2, H, 0, n2AH, n2AL, 512, H, KP_H);
    conv8<false, true><<<dim3(256, GYH), 256>>>(attn_W + 2 * H, ATTN_LD, 0, aW2H, aW2L, T, H, KP_H);
    conv8<false, false><<<dim3(30720, GYH), 256>>>(out_W, H, 0, oWH, oWL, E, H, KP_H);
    conv8<false, true><<<dim3(256, GYH), 256>>>(attn_W, ATTN_LD, 0, Wa1H, Wa1L, T, H, KP_H);
    conv8<false, true><<<dim3(1024, GYH), 256>>>(comb_W, COMB_LD, 0, Wc1H, Wc1L, H, H, KP_H);
    conv8<false, true><<<dim3(1024, GYH), 256>>>(comb_W + H, COMB_LD, 0, Wc2H, Wc2L, H, H, KP_H);
    conv8<false, true><<<dim3(128, GYE), 256>>>(init_dec, E, 0, idH, idL, 8, E, KP_E);

    // ---- precompute GEMMs ----
    {   // Mmat = emb_W_E @ out_W   (2-term fp16)
        constexpr int SL = 4, CPS = (NCH_E + SL - 1) / SL;
        gemm_tc<2><<<dim3(4, 8, SL), 256, GEMM_SMEM>>>(eWEH, eWEL, oWtH, oWtL, KP_E,
                                                       nullptr, kpart, H, H, H, CPS, 1);
        reduce_k<<<(H * H + 255) / 256, 256>>>(kpart, nullptr, nullptr, Mm, H, H, H, SL, 0);
    }
    conv_trans<<<dim3((KP_H + 31) / 32, 32), dim3(32, 8)>>>(Mm, H, MtH, MtL, H, H, KP_H, 1024);
    {   // A1M = Wa1 @ M  (3-term)
        constexpr int SL = 8, CPS = (NCH_H + SL - 1) / SL;
        gemm_tc<3><<<dim3(4, 1, SL), 256, GEMM_SMEM>>>(Wa1H, Wa1L, MtH, MtL, KP_H,
                                                       nullptr, kpart, H, T, H, CPS, 1);
        reduce_k<<<(T * H + 255) / 256, 256>>>(kpart, nullptr, nullptr, A1M, T, H, H, SL, 0);
        make_WA<<<(T * H + 255) / 256, 256>>>(A1M, attn_W, WA);
    }
    {   // C1M = Wc1 @ M  (3-term)
        constexpr int SL = 4, CPS = (NCH_H + SL - 1) / SL;
        gemm_tc<3><<<dim3(4, 8, SL), 256, GEMM_SMEM>>>(Wc1H, Wc1L, MtH, MtL, KP_H,
                                                       nullptr, kpart, H, H, H, CPS, 1);
        reduce_k<<<(H * H + 255) / 256, 256>>>(kpart, nullptr, nullptr, C1M, H, H, H, SL, 0);
    }
    {   // n1pre = noise1 @ emb_W_N^T + emb_b  (3-term)
        constexpr int SL = 8, CPS = (NCH_NZ + SL - 1) / SL;
        gemm_tc<3><<<dim3(4, 4, SL), 256, GEMM_SMEM>>>(n1AH, n1AL, eWNH, eWNL, KP_NZ,
                                                       nullptr, kpart, H, S * B, H, CPS, 1);
        reduce_k<<<(S * B * H + 255) / 256, 256>>>(kpart, emb_b, nullptr, n1p, S * B, H, H, SL, 0);
    }
    {   // emb0 = init_dec @ emb_W_E^T  (3-term)
        constexpr int SL = 8, CPS = (NCH_E + SL - 1) / SL;
        gemm_tc<3><<<dim3(4, 1, SL), 256, GEMM_SMEM>>>(idH, idL, eWEH, eWEL, KP_E,
                                                       nullptr, kpart, H, 8, H, CPS, 1);
        reduce_k<<<(8 * H + 255) / 256, 256>>>(kpart, nullptr, nullptr, emb0, 8, H, H, SL, 0);
    }
    make_n1x<<<(S * B * H + 255) / 256, 256>>>(n1p, emb0, v, n1x);
    conv8<false, true><<<dim3(512, GYH), 256>>>(n1x, H, 0, n1xH, n1xL, S * B, H, KP_H);
    {   // n2pre = noise2 @ Wa3^T + attn_b  (3-term)
        constexpr int SL = 8, CPS = (NCH_H + SL - 1) / SL;
        gemm_tc<3><<<dim3(1, 4, SL), 256, GEMM_SMEM>>>(n2AH, n2AL, aW2H, aW2L, KP_H,
                                                       nullptr, kpart, T, S * B, T, CPS, 1);
        reduce_k<<<(S * B * T + 255) / 256, 256>>>(kpart, attn_b, nullptr, n2p, S * B, T, T, SL, 0);
    }
    {   // pre_a = n1x @ Wa1^T + n2pre  (3-term)
        constexpr int SL = 8, CPS = (NCH_H + SL - 1) / SL;
        gemm_tc<3><<<dim3(1, 4, SL), 256, GEMM_SMEM>>>(n1xH, n1xL, Wa1H, Wa1L, KP_H,
                                                       nullptr, kpart, T, S * B, T, CPS, 1);
        reduce_k<<<(S * B * T + 255) / 256, 256>>>(kpart, nullptr, n2p, pre_a, S * B, T, T, SL, 0);
    }
    {   // pre_c = n1x @ Wc1^T + comb_b  (3-term)
        constexpr int SL = 8, CPS = (NCH_H + SL - 1) / SL;
        gemm_tc<3><<<dim3(4, 4, SL), 256, GEMM_SMEM>>>(n1xH, n1xL, Wc1H, Wc1L, KP_H,
                                                       nullptr, kpart, H, S * B, H, CPS, 1);
        reduce_k<<<(S * B * H + 255) / 256, 256>>>(kpart, comb_b, nullptr, pre_c, S * B, H, H, SL, 0);
    }

    // ---- encoder ----
    enc_kernel<<<NCTA, 256>>>(enc_Whh);

    // ---- enc2T = (enc_out @ Wc2^T) in [b][j][t] layout  (3-term) ----
    conv8<false, true><<<dim3(1024, GYH), 256>>>(enc_out, H, 0, eoH, eoL, T * B, H, KP_H);
    {
        constexpr int SL = 4, CPS = (NCH_H + SL - 1) / SL;
        gemm_tc<3><<<dim3(4, 8, SL), 256, GEMM_SMEM>>>(eoH, eoL, Wc2H, Wc2L, KP_H,
                                                       nullptr, kpart, H, T * B, H, CPS, 1);
        reduce_k<<<(T * B * H + 255) / 256, 256>>>(kpart, nullptr, nullptr, enc2T,
                                                   T * B, H, H, SL, 1);
    }

    // ---- decoder ----
    dec_kernel<<<NCTA, 256, DEC_SMEM>>>(dec_Wih, dec_Whh, attn_W);

    // ---- final: out = Hs @ out_W^T + out_b (2-term fp16, split-K SL=2) ----
    conv8<false, true><<<dim3(512, GYH), 256>>>(Hs, H, 0, HsAH, HsAL, S * B, H, KP_H);
    {
        constexpr int SL = 2, CPS = (NCH_H + SL - 1) / SL;
        gemm_tc<2><<<dim3(120, 4, SL), 256, GEMM_SMEM>>>(HsAH, HsAL, oWH, oWL, KP_H,
                                                         nullptr, kpart, E, S * B, E, CPS, 1);
        reduce_k<<<(int)(((size_t)S * B * E + 255) / 256), 256>>>(
            kpart, out_b, nullptr, out, S * B, E, E, SL, 0);
    }
}

// round 16
// speedup vs baseline: 6.1713x; 1.0529x over previous
#include <cuda_runtime.h>
#include <cuda_bf16.h>
#include <cuda_fp16.h>
#include <math.h>

// Problem dims (fixed by setup_inputs)
constexpr int B = 8;
constexpr int T = 128;
constexpr int E = 30522;
constexpr int H = 1000;
constexpr int S = 64;
constexpr int NZ = 10000;
constexpr int G4 = 4 * H;          // 4000
constexpr int EMB_LD = E + NZ;     // 40522
constexpr int ATTN_LD = 3 * H;     // 3000
constexpr int COMB_LD = 2 * H;     // 2000
constexpr int NCTA = 148;

constexpr int KP_E  = 30528;       // E padded to 64
constexpr int KP_NZ = 10048;       // NZ padded to 64
constexpr int KP_H  = 1024;        // H padded to 64

// ---------------- fp32 scratch ----------------
__device__ float g_pre_enc[T * B * G4];
__device__ float g_enc_out[T * B * H];
__device__ float g_Mmat[H * H];
__device__ float g_n1pre[S * B * H];
__device__ float g_n2pre[S * B * T];
__device__ float g_Hs[S * B * H];
__device__ float g_hbuf[2][B * H];
__device__ float g_c[B * H];
__device__ float g_attn[B * T];
__device__ float g_comb[B * H];
__device__ float g_encbias[G4];
__device__ float g_decbias[G4];
__device__ float g_v[H];
__device__ float g_kpart[33000000];         // split-K partials (131 MB)
__device__ float g_WA[T * H];               // Wa1@M + Wa2
__device__ float g_A1M[T * H];
__device__ float g_C1M[H * H];
__device__ float g_pre_a[S * B * T];
__device__ float g_pre_c[S * B * H];
__device__ float g_n1x[S * B * H];
__device__ float g_emb0[B * H];
__device__ float g_enc2T[B * H * T];        // [b][j][t]
__device__ unsigned g_bar_arrive;
__device__ unsigned g_bar_gen;

// ---------------- fp16 hi/lo operand buffers (padded) ----------------
__device__ __half g_Ain_h[1024 * KP_E],  g_Ain_l[1024 * KP_E];
__device__ __half g_Wih_h[4096 * KP_E],  g_Wih_l[4096 * KP_E];
__device__ __half g_eWE_h[1024 * KP_E],  g_eWE_l[1024 * KP_E];
__device__ __half g_oWt_h[1024 * KP_E],  g_oWt_l[1024 * KP_E];
__device__ __half g_n1A_h[512 * KP_NZ],  g_n1A_l[512 * KP_NZ];
__device__ __half g_eWN_h[1024 * KP_NZ], g_eWN_l[1024 * KP_NZ];
__device__ __half g_n2A_h[512 * KP_H],   g_n2A_l[512 * KP_H];
__device__ __half g_aW2_h[256 * KP_H],   g_aW2_l[256 * KP_H];
__device__ __half g_oW_h[30720 * KP_H],  g_oW_l[30720 * KP_H];
__device__ __half g_HsA_h[512 * KP_H],   g_HsA_l[512 * KP_H];
__device__ __half g_Wa1_h[256 * KP_H],   g_Wa1_l[256 * KP_H];
__device__ __half g_Wc1_h[1024 * KP_H],  g_Wc1_l[1024 * KP_H];
__device__ __half g_Wc2_h[1024 * KP_H],  g_Wc2_l[1024 * KP_H];
__device__ __half g_Mt_h[1024 * KP_H],   g_Mt_l[1024 * KP_H];
__device__ __half g_id_h[128 * KP_E],    g_id_l[128 * KP_E];
__device__ __half g_n1x_h[512 * KP_H],   g_n1x_l[512 * KP_H];
__device__ __half g_eo_h[1024 * KP_H],   g_eo_l[1024 * KP_H];

// ---------------- helpers ----------------
__device__ __forceinline__ unsigned s2u(const void* p) {
    unsigned a;
    asm("{ .reg .u64 t; cvta.to.shared.u64 t, %1; cvt.u32.u64 %0, t; }"
        : "=r"(a) : "l"(p));
    return a;
}
__device__ __forceinline__ void cp16(unsigned dst, const void* src) {
    asm volatile("cp.async.cg.shared.global [%0], [%1], 16;" :: "r"(dst), "l"(src)
                 : "memory");
}
__device__ __forceinline__ void cp_commit() {
    asm volatile("cp.async.commit_group;" ::: "memory");
}
template <int N>
__device__ __forceinline__ void cp_wait() {
    asm volatile("cp.async.wait_group %0;" :: "n"(N) : "memory");
}
__device__ __forceinline__ void mma_f16(float* c, const unsigned* a, const unsigned* b) {
    asm volatile(
        "mma.sync.aligned.m16n8k16.row.col.f32.f16.f16.f32 "
        "{%0,%1,%2,%3}, {%4,%5,%6,%7}, {%8,%9}, {%0,%1,%2,%3};"
        : "+f"(c[0]), "+f"(c[1]), "+f"(c[2]), "+f"(c[3])
        : "r"(a[0]), "r"(a[1]), "r"(a[2]), "r"(a[3]), "r"(b[0]), "r"(b[1]));
}

// ---------------- vectorized converter: 8 cols/thread, fp16 hi/lo ----------
template <bool SWIZ, bool WLO>
__global__ void conv8(const float* __restrict__ src, int ldS, int swizT,
                      __half* __restrict__ dh,
                      __half* __restrict__ dl,
                      int Mr, int Kr, int Kpad) {
    int row = blockIdx.x;
    int c0 = (blockIdx.y * 256 + threadIdx.x) * 8;
    if (c0 >= Kpad) return;
    const float* sp = nullptr;
    if (row < Mr) {
        int r = SWIZ ? ((row & 7) * swizT + (row >> 3)) : row;
        sp = src + (size_t)r * ldS;
    }
    float x[8];
#pragma unroll
    for (int i = 0; i < 8; i++) {
        int col = c0 + i;
        x[i] = (sp && col < Kr) ? sp[col] : 0.f;
    }
    unsigned hw[4], lw[4];
#pragma unroll
    for (int p = 0; p < 4; p++) {
        __half h0 = __float2half_rn(x[2 * p]);
        __half h1 = __float2half_rn(x[2 * p + 1]);
        hw[p] = (unsigned)__half_as_ushort(h0) | ((unsigned)__half_as_ushort(h1) << 16);
        if (WLO) {
            __half l0 = __float2half_rn(x[2 * p] - __half2float(h0));
            __half l1 = __float2half_rn(x[2 * p + 1] - __half2float(h1));
            lw[p] = (unsigned)__half_as_ushort(l0) | ((unsigned)__half_as_ushort(l1) << 16);
        }
    }
    *(uint4*)(dh + (size_t)row * Kpad + c0) = make_uint4(hw[0], hw[1], hw[2], hw[3]);
    if (WLO)
        *(uint4*)(dl + (size_t)row * Kpad + c0) = make_uint4(lw[0], lw[1], lw[2], lw[3]);
}

// dst[n][k] = src[k][n]
template <bool WLO>
__global__ void conv_trans(const float* __restrict__ src, int ldS,
                           __half* __restrict__ dh,
                           __half* __restrict__ dl,
                           int Kr, int Nr, int Kpad, int Npad) {
    __shared__ float tile[32][33];
    int kb = blockIdx.x * 32, nb = blockIdx.y * 32;
    int tx = threadIdx.x, ty = threadIdx.y;   // 32 x 8
    for (int i = ty; i < 32; i += 8) {
        int k = kb + i, n = nb + tx;
        tile[i][tx] = (k < Kr && n < Nr) ? src[(size_t)k * ldS + n] : 0.f;
    }
    __syncthreads();
    for (int i = ty; i < 32; i += 8) {
        int n = nb + i, k = kb + tx;
        if (n < Npad && k < Kpad) {
            float x = tile[tx][i];
            __half h = __float2half_rn(x);
            dh[(size_t)n * Kpad + k] = h;
            if (WLO)
                dl[(size_t)n * Kpad + k] = __float2half_rn(x - __half2float(h));
        }
    }
}

// ---------------- mma.sync GEMM, fp16 hi/lo, 3-stage cp.async, split-K ------
// NTERMS==3: C = Ah·Bh + Al·Bh + Ah·Bl   (error ~2^-24)
// NTERMS==2: C = Ah·Bh + Al·Bh           (B truncation, ~1.4e-4 RMS)
// NTERMS==1: C = Ah·Bh                   (A+B truncation, ~2e-4 RMS)
constexpr int ST_W = 20 * (128 + 128 + 256 + 256);   // 15360 words
constexpr int ST_BYTES = ST_W * 4;
constexpr int GEMM_SMEM = 3 * ST_BYTES;

template <int NTERMS>
__global__ void __launch_bounds__(256, 1)
gemm_tc(const __half* __restrict__ Ah, const __half* __restrict__ Al,
        const __half* __restrict__ Bh, const __half* __restrict__ Bl,
        int Kpad, const float* __restrict__ bias,
        float* __restrict__ C, int ldC, int M, int N, int cps, int partial) {
    extern __shared__ unsigned sm[];
    const unsigned sbase = s2u(sm);
    const int tid = threadIdx.x;
    const int wid = tid >> 5, lane = tid & 31;
    const int g = lane >> 2, tq = lane & 3;
    const int wm = wid & 1, wn = wid >> 1;
    const int m0 = blockIdx.y * 128, n0 = blockIdx.x * 256;
    const int nch = Kpad / 32;
    const int z = blockIdx.z;
    const int c0 = z * cps;
    const int c1 = min(nch, c0 + cps);

    float acc[4][8][4];
#pragma unroll
    for (int i = 0; i < 4; i++)
#pragma unroll
        for (int j = 0; j < 8; j++)
#pragma unroll
            for (int q = 0; q < 4; q++) acc[i][j][q] = 0.f;

    auto load_stage = [&](int st, int ci) {
        unsigned sb = sbase + st * ST_BYTES;
        int k0 = ci * 32;
        constexpr int NQ = (NTERMS == 3) ? 12 : (NTERMS == 2 ? 8 : 6);
#pragma unroll
        for (int q = 0; q < NQ; q++) {
            int it = tid + q * 256;
            const __half* gp;
            unsigned dw;
            if (NTERMS == 1) {
                if (it < 512) {
                    int r = it >> 2, c = it & 3;
                    gp = Ah + (size_t)(m0 + r) * Kpad + k0 + c * 8;
                    dw = r * 20 + c * 4;
                } else {
                    int idx = it - 512, r = idx >> 2, c = idx & 3;
                    gp = Bh + (size_t)(n0 + r) * Kpad + k0 + c * 8;
                    dw = 5120u + r * 20 + c * 4;
                }
            } else {
                if (it < 1024) {
                    int idx = it & 511, r = idx >> 2, c = idx & 3;
                    gp = (it < 512 ? Ah : Al) + (size_t)(m0 + r) * Kpad + k0 + c * 8;
                    dw = (it < 512 ? 0u : 2560u) + r * 20 + c * 4;
                } else {
                    int idx = (it - 1024) & 1023, r = idx >> 2, c = idx & 3;
                    gp = (it < 2048 ? Bh : Bl) + (size_t)(n0 + r) * Kpad + k0 + c * 8;
                    dw = (it < 2048 ? 5120u : 10240u) + r * 20 + c * 4;
                }
            }
            cp16(sb + dw * 4, gp);
        }
        cp_commit();
    };

    if (c0 < c1)     load_stage(0, c0);
    if (c0 + 1 < c1) load_stage(1, c0 + 1);

    for (int ci = c0; ci < c1; ci++) {
        int st = (ci - c0) % 3;
        if (ci == c1 - 1) cp_wait<0>(); else cp_wait<1>();
        __syncthreads();
        if (ci + 2 < c1) load_stage((ci - c0 + 2) % 3, ci + 2);

        const unsigned b0 = st * ST_W;
#pragma unroll
        for (int ks = 0; ks < 2; ks++) {
            int ws = ks * 8 + tq;
            unsigned ahf[4][4], alf[4][4];
#pragma unroll
            for (int i = 0; i < 4; i++) {
                int am = wm * 64 + i * 16 + g;
                ahf[i][0] = sm[b0 + am * 20 + ws];
                ahf[i][1] = sm[b0 + (am + 8) * 20 + ws];
                ahf[i][2] = sm[b0 + am * 20 + ws + 4];
                ahf[i][3] = sm[b0 + (am + 8) * 20 + ws + 4];
                if (NTERMS >= 2) {
                    alf[i][0] = sm[b0 + 2560 + am * 20 + ws];
                    alf[i][1] = sm[b0 + 2560 + (am + 8) * 20 + ws];
                    alf[i][2] = sm[b0 + 2560 + am * 20 + ws + 4];
                    alf[i][3] = sm[b0 + 2560 + (am + 8) * 20 + ws + 4];
                }
            }
#pragma unroll
            for (int jh = 0; jh < 2; jh++) {
                unsigned bhf[4][2], blf[4][2];
#pragma unroll
                for (int j = 0; j < 4; j++) {
                    int bn = wn * 64 + jh * 32 + j * 8 + g;
                    bhf[j][0] = sm[b0 + 5120 + bn * 20 + ws];
                    bhf[j][1] = sm[b0 + 5120 + bn * 20 + ws + 4];
                    if (NTERMS == 3) {
                        blf[j][0] = sm[b0 + 10240 + bn * 20 + ws];
                        blf[j][1] = sm[b0 + 10240 + bn * 20 + ws + 4];
                    }
                }
#pragma unroll
                for (int i = 0; i < 4; i++)
#pragma unroll
                    for (int j = 0; j < 4; j++)
                        mma_f16(acc[i][jh * 4 + j], ahf[i], bhf[j]);
                if (NTERMS >= 2) {
#pragma unroll
                    for (int i = 0; i < 4; i++)
#pragma unroll
                        for (int j = 0; j < 4; j++)
                            mma_f16(acc[i][jh * 4 + j], alf[i], bhf[j]);
                }
                if (NTERMS == 3) {
#pragma unroll
                    for (int i = 0; i < 4; i++)
#pragma unroll
                        for (int j = 0; j < 4; j++)
                            mma_f16(acc[i][jh * 4 + j], ahf[i], blf[j]);
                }
            }
        }
        __syncthreads();
    }

    float* Cb = partial ? (C + (size_t)z * M * N) : C;
    const int ld = partial ? N : ldC;
#pragma unroll
    for (int i = 0; i < 4; i++) {
        int rr0 = m0 + wm * 64 + i * 16 + g;
#pragma unroll
        for (int j = 0; j < 8; j++) {
            int cc = n0 + wn * 64 + j * 8 + tq * 2;
#pragma unroll
            for (int q = 0; q < 4; q++) {
                int rr = rr0 + (q >> 1) * 8;
                int cn = cc + (q & 1);
                if (rr < M && cn < N) {
                    float v = acc[i][j][q];
                    if (!partial && bias) v += bias[cn];
                    Cb[(size_t)rr * ld + cn] = v;
                }
            }
        }
    }
}

// deterministic split-K reduce. emode 0: out[m*ldC+n]; 1: enc2T layout.
__global__ void reduce_k(const float* __restrict__ part,
                         const float* __restrict__ bias,
                         const float* __restrict__ add,
                         float* __restrict__ out,
                         int M, int N, int ldC, int slices, int emode) {
    size_t idx = (size_t)blockIdx.x * 256 + threadIdx.x;
    if (idx >= (size_t)M * N) return;
    int m = (int)(idx / N), n = (int)(idx - (size_t)m * N);
    float v = bias ? bias[n] : 0.f;
    if (add) v += add[idx];
    for (int z = 0; z < slices; z++) v += part[(size_t)z * M * N + idx];
    if (emode == 1) out[((size_t)(m & 7) * H + n) * T + (m >> 3)] = v;
    else out[(size_t)m * ldC + n] = v;
}

// ---------------- persistent kernels ----------------
__device__ __forceinline__ void grid_barrier() {
    __threadfence();
    __syncthreads();
    if (threadIdx.x == 0) {
        unsigned gen = atomicAdd(&g_bar_gen, 0u);
        if (atomicAdd(&g_bar_arrive, 1u) == gridDim.x - 1) {
            g_bar_arrive = 0;
            __threadfence();
            atomicAdd(&g_bar_gen, 1u);
        } else {
            volatile unsigned* vg = &g_bar_gen;
            while (*vg == gen) { }
        }
    }
    __syncthreads();
}
__device__ __forceinline__ float wsum(float v) {
#pragma unroll
    for (int off = 16; off; off >>= 1) v += __shfl_xor_sync(0xFFFFFFFFu, v, off);
    return v;
}
__device__ __forceinline__ float sigm(float x) { return 1.f / (1.f + expf(-x)); }
__device__ __forceinline__ void stage8k(float* xs, const float* src) {
    const float4* s4 = reinterpret_cast<const float4*>(src);
    float4* d4 = reinterpret_cast<float4*>(xs);
    for (int i = threadIdx.x; i < B * H / 4; i += 256) d4[i] = s4[i];
}
__device__ __forceinline__ float dot4(float4 a, float4 b) {
    return a.x * b.x + a.y * b.y + a.z * b.z + a.w * b.w;
}

__global__ void __launch_bounds__(256, 1)
enc_kernel(const float* __restrict__ enc_Whh) {
    __shared__ __align__(16) float xs[B][H];
    const int ct = blockIdx.x, tid = threadIdx.x;
    const int w = tid >> 5, lane = tid & 31;
    const int j = ct + NCTA * w;
    const bool own = (w < 7) && (j < H);

    for (int t = 0; t < T; t++) {
        stage8k(xs[0], g_hbuf[t & 1]);
        __syncthreads();
        float acc[4][8];
#pragma unroll
        for (int ga = 0; ga < 4; ga++)
#pragma unroll
            for (int b = 0; b < 8; b++) acc[ga][b] = 0.f;
        if (own) {
#pragma unroll
            for (int kb = 0; kb < 8; kb++) {
                int kk = kb * 128 + lane * 4;
                if (kk < H) {
                    float4 xv[8];
#pragma unroll
                    for (int b = 0; b < 8; b++)
                        xv[b] = *reinterpret_cast<const float4*>(&xs[b][kk]);
#pragma unroll
                    for (int ga = 0; ga < 4; ga++) {
                        float4 wv = *reinterpret_cast<const float4*>(
                            &enc_Whh[(size_t)(ga * H + j) * H + kk]);
#pragma unroll
                        for (int b = 0; b < 8; b++) acc[ga][b] += dot4(wv, xv[b]);
                    }
                }
            }
        }
#pragma unroll
        for (int ga = 0; ga < 4; ga++)
#pragma unroll
            for (int b = 0; b < 8; b++) acc[ga][b] = wsum(acc[ga][b]);
        if (own && lane < 8) {
            int b = lane;
            const float* pre = g_pre_enc + (t * 8 + b) * G4;
            float gi = sigm(acc[0][b] + pre[j]);
            float gf = sigm(acc[1][b] + pre[H + j]);
            float gg = tanhf(acc[2][b] + pre[2 * H + j]);
            float go = sigm(acc[3][b] + pre[3 * H + j]);
            float cn = gf * g_c[b * H + j] + gi * gg;
            g_c[b * H + j] = cn;
            float hn = go * tanhf(cn);
            g_hbuf[(t + 1) & 1][b * H + j] = hn;
            g_enc_out[t * (B * H) + b * H + j] = hn;
        }
        grid_barrier();
    }
}

// decoder: 3 phases/step. dynamic smem: xs(h) 8000f | cs(comb) 8000f | aw 1024f
constexpr int DEC_SMEM = (8000 + 8000 + 1024) * 4;

__global__ void __launch_bounds__(256, 1)
dec_kernel(const float* __restrict__ dec_Wih,
           const float* __restrict__ dec_Whh,
           const float* __restrict__ attn_W) {
    extern __shared__ __align__(16) float dsm[];
    float* xs = dsm;             // [8][1000] h
    float* cs = dsm + 8000;      // [8][1000] comb
    float* aw = dsm + 16000;     // [8][128]

    const int ct = blockIdx.x, tid = threadIdx.x;
    const int w = tid >> 5, lane = tid & 31;
    const int j = ct + NCTA * w;
    const bool own = (w < 7) && (j < H);

    for (int s = 0; s < S; s++) {
        stage8k(xs, g_hbuf[s & 1]);
        __syncthreads();

        // ---- phase A: rc = C1M@h partials; attn logits ----
        float rc[8];
#pragma unroll
        for (int b = 0; b < 8; b++) rc[b] = 0.f;
        if (s > 0 && own) {
#pragma unroll
            for (int kb = 0; kb < 8; kb++) {
                int kk = kb * 128 + lane * 4;
                if (kk < H) {
                    float4 cw = *reinterpret_cast<const float4*>(&g_C1M[(size_t)j * H + kk]);
#pragma unroll
                    for (int b = 0; b < 8; b++)
                        rc[b] += dot4(cw, *reinterpret_cast<const float4*>(&xs[b * H + kk]));
                }
            }
        }
        if (ct < T) {
            int tp = ct, b = w;
            float acc = 0.f;
            if (s == 0) {
#pragma unroll
                for (int kb = 0; kb < 8; kb++) {
                    int kk = kb * 128 + lane * 4;
                    if (kk < H) {
                        float4 wv = *reinterpret_cast<const float4*>(
                            &attn_W[(size_t)tp * ATTN_LD + H + kk]);
                        acc += dot4(wv, *reinterpret_cast<const float4*>(&xs[b * H + kk]));
                    }
                }
            } else {
#pragma unroll
                for (int kb = 0; kb < 8; kb++) {
                    int kk = kb * 128 + lane * 4;
                    if (kk < H) {
                        float4 wv = *reinterpret_cast<const float4*>(&g_WA[(size_t)tp * H + kk]);
                        acc += dot4(wv, *reinterpret_cast<const float4*>(&xs[b * H + kk]));
                    }
                }
            }
            acc = wsum(acc);
            if (lane == 0)
                g_attn[b * T + tp] = acc + g_pre_a[(s * 8 + b) * T + tp];
        }
        grid_barrier();

        // ---- phase B: local softmax + comb ----
        {
            int b = w;
            float vx[4];
#pragma unroll
            for (int q = 0; q < 4; q++) vx[q] = g_attn[b * T + lane + 32 * q];
            float m = fmaxf(fmaxf(vx[0], vx[1]), fmaxf(vx[2], vx[3]));
#pragma unroll
            for (int off = 16; off; off >>= 1)
                m = fmaxf(m, __shfl_xor_sync(0xFFFFFFFFu, m, off));
            float e[4], ssum = 0.f;
#pragma unroll
            for (int q = 0; q < 4; q++) { e[q] = expf(vx[q] - m); ssum += e[q]; }
            ssum = wsum(ssum);
            float inv = 1.f / ssum;
#pragma unroll
            for (int q = 0; q < 4; q++) aw[b * T + lane + 32 * q] = e[q] * inv;
        }
        __syncthreads();
        if (own) {
#pragma unroll
            for (int b = 0; b < 8; b++) {
                const float* e2 = g_enc2T + ((size_t)b * H + j) * T;
                float a = 0.f;
#pragma unroll
                for (int it = 0; it < 4; it++)
                    a += aw[b * T + lane + 32 * it] * e2[lane + 32 * it];
                rc[b] += a;
            }
#pragma unroll
            for (int b = 0; b < 8; b++) rc[b] = wsum(rc[b]);
            if (lane < 8) {
                int b = lane;
                g_comb[b * H + j] = fmaxf(rc[b] + g_pre_c[(s * 8 + b) * H + j], 0.f);
            }
        }
        grid_barrier();

        // ---- phase C: gates + LSTM ----
        stage8k(cs, g_comb);
        __syncthreads();
        float acc4[4][8];
#pragma unroll
        for (int ga = 0; ga < 4; ga++)
#pragma unroll
            for (int b = 0; b < 8; b++) acc4[ga][b] = 0.f;
        if (own) {
#pragma unroll
            for (int kb = 0; kb < 8; kb++) {
                int kk = kb * 128 + lane * 4;
                if (kk < H) {
                    float4 cv[8], hv[8];
#pragma unroll
                    for (int b = 0; b < 8; b++) {
                        cv[b] = *reinterpret_cast<const float4*>(&cs[b * H + kk]);
                        hv[b] = *reinterpret_cast<const float4*>(&xs[b * H + kk]);
                    }
#pragma unroll
                    for (int ga = 0; ga < 4; ga++) {
                        float4 wih = *reinterpret_cast<const float4*>(
                            &dec_Wih[(size_t)(ga * H + j) * H + kk]);
                        float4 whh = *reinterpret_cast<const float4*>(
                            &dec_Whh[(size_t)(ga * H + j) * H + kk]);
#pragma unroll
                        for (int b = 0; b < 8; b++)
                            acc4[ga][b] += dot4(wih, cv[b]) + dot4(whh, hv[b]);
                    }
                }
            }
        }
#pragma unroll
        for (int ga = 0; ga < 4; ga++)
#pragma unroll
            for (int b = 0; b < 8; b++) acc4[ga][b] = wsum(acc4[ga][b]);
        if (own && lane < 8) {
            int b = lane;
            float gi = sigm(acc4[0][b] + g_decbias[j]);
            float gf = sigm(acc4[1][b] + g_decbias[H + j]);
            float gg = tanhf(acc4[2][b] + g_decbias[2 * H + j]);
            float go = sigm(acc4[3][b] + g_decbias[3 * H + j]);
            float cn = gf * g_c[b * H + j] + gi * gg;
            g_c[b * H + j] = cn;
            float hn = go * tanhf(cn);
            g_hbuf[(s + 1) & 1][b * H + j] = hn;
            g_Hs[s * (B * H) + b * H + j] = hn;
        }
        grid_barrier();
    }
}

// ---------------- tiny kernels ----------------
__global__ void bias_sum(const float* __restrict__ a, const float* __restrict__ b,
                         float* __restrict__ o, int n) {
    int i = blockIdx.x * blockDim.x + threadIdx.x;
    if (i < n) o[i] = a[i] + b[i];
}
__global__ void calc_v(const float* __restrict__ out_b, const float* __restrict__ emb_W,
                       float* __restrict__ v) {
    int j = blockIdx.x;
    const float* row = emb_W + (size_t)j * EMB_LD;
    float acc = 0.f;
    for (int e = threadIdx.x; e < E; e += 256) acc += out_b[e] * row[e];
    __shared__ float s[256];
    s[threadIdx.x] = acc;
    __syncthreads();
    for (int off = 128; off; off >>= 1) {
        if (threadIdx.x < off) s[threadIdx.x] += s[threadIdx.x + off];
        __syncthreads();
    }
    if (threadIdx.x == 0) v[j] = s[0];
}
__global__ void make_WA(const float* __restrict__ A1M, const float* __restrict__ attn_W,
                        float* __restrict__ WA) {
    int i = blockIdx.x * 256 + threadIdx.x;
    if (i >= T * H) return;
    int t = i / H, k = i - t * H;
    WA[i] = A1M[i] + attn_W[t * ATTN_LD + H + k];
}
__global__ void make_n1x(const float* __restrict__ n1p, const float* __restrict__ emb0,
                         const float* __restrict__ v, float* __restrict__ n1x) {
    int i = blockIdx.x * 256 + threadIdx.x;
    if (i >= S * B * H) return;
    int row = i / H, k = i - row * H;
    n1x[i] = n1p[i] + (row < 8 ? emb0[i] : v[k]);
}

// ---------------- host orchestration ----------------
template <typename Tp>
static Tp* sym(const void* symbol) {
    void* p;
    cudaGetSymbolAddress(&p, symbol);
    return (Tp*)p;
}

extern "C" void kernel_launch(void* const* d_in, const int* in_sizes, int n_in,
                              void* d_out, int out_size) {
    const float* in_input  = (const float*)d_in[0];
    const float* noise1    = (const float*)d_in[2];
    const float* noise2    = (const float*)d_in[3];
    const float* init_dec  = (const float*)d_in[4];
    const float* enc_Wih   = (const float*)d_in[5];
    const float* enc_Whh   = (const float*)d_in[6];
    const float* enc_bih   = (const float*)d_in[7];
    const float* enc_bhh   = (const float*)d_in[8];
    const float* dec_Wih   = (const float*)d_in[9];
    const float* dec_Whh   = (const float*)d_in[10];
    const float* dec_bih   = (const float*)d_in[11];
    const float* dec_bhh   = (const float*)d_in[12];
    const float* emb_W     = (const float*)d_in[13];
    const float* emb_b     = (const float*)d_in[14];
    const float* attn_W    = (const float*)d_in[15];
    const float* attn_b    = (const float*)d_in[16];
    const float* comb_W    = (const float*)d_in[17];
    const float* comb_b    = (const float*)d_in[18];
    const float* out_W     = (const float*)d_in[19];
    const float* out_b     = (const float*)d_in[20];
    float* out = (float*)d_out;

    float *pre = sym<float>(g_pre_enc), *Mm = sym<float>(g_Mmat),
          *n1p = sym<float>(g_n1pre), *n2p = sym<float>(g_n2pre),
          *Hs = sym<float>(g_Hs), *hb = sym<float>(g_hbuf), *c = sym<float>(g_c),
          *encb = sym<float>(g_encbias), *decb = sym<float>(g_decbias),
          *v = sym<float>(g_v), *kpart = sym<float>(g_kpart),
          *WA = sym<float>(g_WA), *A1M = sym<float>(g_A1M), *C1M = sym<float>(g_C1M),
          *pre_a = sym<float>(g_pre_a), *pre_c = sym<float>(g_pre_c),
          *n1x = sym<float>(g_n1x), *emb0 = sym<float>(g_emb0),
          *enc2T = sym<float>(g_enc2T), *enc_out = sym<float>(g_enc_out);
    __half *AinH = sym<__half>(g_Ain_h), *AinL = sym<__half>(g_Ain_l);
    __half *WihH = sym<__half>(g_Wih_h), *WihL = sym<__half>(g_Wih_l);
    __half *eWEH = sym<__half>(g_eWE_h), *eWEL = sym<__half>(g_eWE_l);
    __half *oWtH = sym<__half>(g_oWt_h), *oWtL = sym<__half>(g_oWt_l);
    __half *n1AH = sym<__half>(g_n1A_h), *n1AL = sym<__half>(g_n1A_l);
    __half *eWNH = sym<__half>(g_eWN_h), *eWNL = sym<__half>(g_eWN_l);
    __half *n2AH = sym<__half>(g_n2A_h), *n2AL = sym<__half>(g_n2A_l);
    __half *aW2H = sym<__half>(g_aW2_h), *aW2L = sym<__half>(g_aW2_l);
    __half *oWH = sym<__half>(g_oW_h), *oWL = sym<__half>(g_oW_l);
    __half *HsAH = sym<__half>(g_HsA_h), *HsAL = sym<__half>(g_HsA_l);
    __half *Wa1H = sym<__half>(g_Wa1_h), *Wa1L = sym<__half>(g_Wa1_l);
    __half *Wc1H = sym<__half>(g_Wc1_h), *Wc1L = sym<__half>(g_Wc1_l);
    __half *Wc2H = sym<__half>(g_Wc2_h), *Wc2L = sym<__half>(g_Wc2_l);
    __half *MtH = sym<__half>(g_Mt_h), *MtL = sym<__half>(g_Mt_l);
    __half *idH = sym<__half>(g_id_h), *idL = sym<__half>(g_id_l);
    __half *n1xH = sym<__half>(g_n1x_h), *n1xL = sym<__half>(g_n1x_l);
    __half *eoH = sym<__half>(g_eo_h), *eoL = sym<__half>(g_eo_l);

    cudaFuncSetAttribute(gemm_tc<1>, cudaFuncAttributeMaxDynamicSharedMemorySize, GEMM_SMEM);
    cudaFuncSetAttribute(gemm_tc<2>, cudaFuncAttributeMaxDynamicSharedMemorySize, GEMM_SMEM);
    cudaFuncSetAttribute(gemm_tc<3>, cudaFuncAttributeMaxDynamicSharedMemorySize, GEMM_SMEM);
    cudaFuncSetAttribute(dec_kernel, cudaFuncAttributeMaxDynamicSharedMemorySize, DEC_SMEM);

    const int GYE = (KP_E + 2047) / 2048, GYH = 1, GYNZ = (KP_NZ + 2047) / 2048;
    constexpr int NCH_E = KP_E / 32, NCH_NZ = KP_NZ / 32, NCH_H = KP_H / 32;

    // ---- launches 1-5 ----
    conv8<true, false><<<dim3(1024, GYE), 256>>>(in_input, E, T, AinH, AinL, 1024, E, KP_E);
    conv8<false, false><<<dim3(4096, GYE), 256>>>(enc_Wih, E, 0, WihH, WihL, G4, E, KP_E);
    bias_sum<<<(G4 + 255) / 256, 256>>>(enc_bih, enc_bhh, encb, G4);
    bias_sum<<<(G4 + 255) / 256, 256>>>(dec_bih, dec_bhh, decb, G4);
    calc_v<<<H, 256>>>(out_b, emb_W, v);

    // ---- launch 6: pre_enc GEMM (1-term fp16, split-K SL=8) ----
    {
        constexpr int SL = 8, CPS = (NCH_E + SL - 1) / SL;
        gemm_tc<1><<<dim3(16, 8, SL), 256, GEMM_SMEM>>>(AinH, AinL, WihH, WihL, KP_E,
                                                        nullptr, kpart, G4, T * B, G4, CPS, 1);
        reduce_k<<<(int)(((size_t)T * B * G4 + 255) / 256), 256>>>(
            kpart, encb, nullptr, pre, T * B, G4, G4, SL, 0);
    }

    // ---- init + remaining conversions ----
    cudaMemsetAsync(hb, 0, B * H * sizeof(float));
    cudaMemsetAsync(c, 0, B * H * sizeof(float));
    conv8<false, true><<<dim3(1024, GYE), 256>>>(emb_W, EMB_LD, 0, eWEH, eWEL, H, E, KP_E);
    conv_trans<false><<<dim3((KP_E + 31) / 32, 32), dim3(32, 8)>>>(out_W, H, oWtH, oWtL, E, H, KP_E, 1024);
    conv8<false, true><<<dim3(512, GYNZ), 256>>>(noise1, NZ, 0, n1AH, n1AL, 512, NZ, KP_NZ);
    conv8<false, true><<<dim3(1024, GYNZ), 256>>>(emb_W + E, EMB_LD, 0, eWNH, eWNL, H, NZ, KP_NZ);
    conv8<false, true><<<dim3(512, GYH), 256>>>(noise2, H, 0, n2AH, n2AL, 512, H, KP_H);
    conv8<false, true><<<dim3(256, GYH), 256>>>(attn_W + 2 * H, ATTN_LD, 0, aW2H, aW2L, T, H, KP_H);
    conv8<false, false><<<dim3(30720, GYH), 256>>>(out_W, H, 0, oWH, oWL, E, H, KP_H);
    conv8<false, true><<<dim3(256, GYH), 256>>>(attn_W, ATTN_LD, 0, Wa1H, Wa1L, T, H, KP_H);
    conv8<false, true><<<dim3(1024, GYH), 256>>>(comb_W, COMB_LD, 0, Wc1H, Wc1L, H, H, KP_H);
    conv8<false, true><<<dim3(1024, GYH), 256>>>(comb_W + H, COMB_LD, 0, Wc2H, Wc2L, H, H, KP_H);
    conv8<false, true><<<dim3(128, GYE), 256>>>(init_dec, E, 0, idH, idL, 8, E, KP_E);

    // ---- precompute GEMMs ----
    {   // Mmat = emb_W_E @ out_W   (1-term fp16; error attenuated through decoder)
        constexpr int SL = 4, CPS = (NCH_E + SL - 1) / SL;
        gemm_tc<1><<<dim3(4, 8, SL), 256, GEMM_SMEM>>>(eWEH, eWEL, oWtH, oWtL, KP_E,
                                                       nullptr, kpart, H, H, H, CPS, 1);
        reduce_k<<<(H * H + 255) / 256, 256>>>(kpart, nullptr, nullptr, Mm, H, H, H, SL, 0);
    }
    conv_trans<true><<<dim3((KP_H + 31) / 32, 32), dim3(32, 8)>>>(Mm, H, MtH, MtL, H, H, KP_H, 1024);
    {   // A1M = Wa1 @ M  (3-term)
        constexpr int SL = 8, CPS = (NCH_H + SL - 1) / SL;
        gemm_tc<3><<<dim3(4, 1, SL), 256, GEMM_SMEM>>>(Wa1H, Wa1L, MtH, MtL, KP_H,
                                                       nullptr, kpart, H, T, H, CPS, 1);
        reduce_k<<<(T * H + 255) / 256, 256>>>(kpart, nullptr, nullptr, A1M, T, H, H, SL, 0);
        make_WA<<<(T * H + 255) / 256, 256>>>(A1M, attn_W, WA);
    }
    {   // C1M = Wc1 @ M  (3-term)
        constexpr int SL = 4, CPS = (NCH_H + SL - 1) / SL;
        gemm_tc<3><<<dim3(4, 8, SL), 256, GEMM_SMEM>>>(Wc1H, Wc1L, MtH, MtL, KP_H,
                                                       nullptr, kpart, H, H, H, CPS, 1);
        reduce_k<<<(H * H + 255) / 256, 256>>>(kpart, nullptr, nullptr, C1M, H, H, H, SL, 0);
    }
    {   // n1pre = noise1 @ emb_W_N^T + emb_b  (3-term)
        constexpr int SL = 8, CPS = (NCH_NZ + SL - 1) / SL;
        gemm_tc<3><<<dim3(4, 4, SL), 256, GEMM_SMEM>>>(n1AH, n1AL, eWNH, eWNL, KP_NZ,
                                                       nullptr, kpart, H, S * B, H, CPS, 1);
        reduce_k<<<(S * B * H + 255) / 256, 256>>>(kpart, emb_b, nullptr, n1p, S * B, H, H, SL, 0);
    }
    {   // emb0 = init_dec @ emb_W_E^T  (3-term)
        constexpr int SL = 8, CPS = (NCH_E + SL - 1) / SL;
        gemm_tc<3><<<dim3(4, 1, SL), 256, GEMM_SMEM>>>(idH, idL, eWEH, eWEL, KP_E,
                                                       nullptr, kpart, H, 8, H, CPS, 1);
        reduce_k<<<(8 * H + 255) / 256, 256>>>(kpart, nullptr, nullptr, emb0, 8, H, H, SL, 0);
    }
    make_n1x<<<(S * B * H + 255) / 256, 256>>>(n1p, emb0, v, n1x);
    conv8<false, true><<<dim3(512, GYH), 256>>>(n1x, H, 0, n1xH, n1xL, S * B, H, KP_H);
    {   // n2pre = noise2 @ Wa3^T + attn_b  (3-term)
        constexpr int SL = 8, CPS = (NCH_H + SL - 1) / SL;
        gemm_tc<3><<<dim3(1, 4, SL), 256, GEMM_SMEM>>>(n2AH, n2AL, aW2H, aW2L, KP_H,
                                                       nullptr, kpart, T, S * B, T, CPS, 1);
        reduce_k<<<(S * B * T + 255) / 256, 256>>>(kpart, attn_b, nullptr, n2p, S * B, T, T, SL, 0);
    }
    {   // pre_a = n1x @ Wa1^T + n2pre  (3-term)
        constexpr int SL = 8, CPS = (NCH_H + SL - 1) / SL;
        gemm_tc<3><<<dim3(1, 4, SL), 256, GEMM_SMEM>>>(n1xH, n1xL, Wa1H, Wa1L, KP_H,
                                                       nullptr, kpart, T, S * B, T, CPS, 1);
        reduce_k<<<(S * B * T + 255) / 256, 256>>>(kpart, nullptr, n2p, pre_a, S * B, T, T, SL, 0);
    }
    {   // pre_c = n1x @ Wc1^T + comb_b  (3-term)
        constexpr int SL = 8, CPS = (NCH_H + SL - 1) / SL;
        gemm_tc<3><<<dim3(4, 4, SL), 256, GEMM_SMEM>>>(n1xH, n1xL, Wc1H, Wc1L, KP_H,
                                                       nullptr, kpart, H, S * B, H, CPS, 1);
        reduce_k<<<(S * B * H + 255) / 256, 256>>>(kpart, comb_b, nullptr, pre_c, S * B, H, H, SL, 0);
    }

    // ---- encoder ----
    enc_kernel<<<NCTA, 256>>>(enc_Whh);

    // ---- enc2T = (enc_out @ Wc2^T) in [b][j][t] layout  (3-term) ----
    conv8<false, true><<<dim3(1024, GYH), 256>>>(enc_out, H, 0, eoH, eoL, T * B, H, KP_H);
    {
        constexpr int SL = 4, CPS = (NCH_H + SL - 1) / SL;
        gemm_tc<3><<<dim3(4, 8, SL), 256, GEMM_SMEM>>>(eoH, eoL, Wc2H, Wc2L, KP_H,
                                                       nullptr, kpart, H, T * B, H, CPS, 1);
        reduce_k<<<(T * B * H + 255) / 256, 256>>>(kpart, nullptr, nullptr, enc2T,
                                                   T * B, H, H, SL, 1);
    }

    // ---- decoder ----
    dec_kernel<<<NCTA, 256, DEC_SMEM>>>(dec_Wih, dec_Whh, attn_W);

    // ---- final: out = Hs @ out_W^T + out_b (1-term fp16, split-K SL=2) ----
    conv8<false, false><<<dim3(512, GYH), 256>>>(Hs, H, 0, HsAH, HsAL, S * B, H, KP_H);
    {
        constexpr int SL = 2, CPS = (NCH_H + SL - 1) / SL;
        gemm_tc<1><<<dim3(120, 4, SL), 256, GEMM_SMEM>>>(HsAH, HsAL, oWH, oWL, KP_H,
                                                         nullptr, kpart, E, S * B, E, CPS, 1);
        reduce_k<<<(int)(((size_t)S * B * E + 255) / 256), 256>>>(
            kpart, out_b, nullptr, out, S * B, E, E, SL, 0);
    }
}